// round 2
// baseline (speedup 1.0000x reference)
#include <cuda_runtime.h>

#define HOPS 8
#define FDIM 128
#define HID  256
#define NCLS 64

#define NMAX 100096

typedef unsigned long long ull;

// Scratch (allowed: __device__ globals, zero-init, no runtime alloc)
__device__ float g_h [(size_t)NMAX * HID];    // prelu(concat@W1+b1)
__device__ float g_sx[(size_t)NMAX * HOPS];   // per-hop attention x-part
__device__ float g_w [(size_t)NMAX * HOPS];   // softmax hop weights

__device__ __forceinline__ void ffma2(ull &d, ull a, ull b) {
    asm("fma.rn.f32x2 %0, %1, %2, %0;" : "+l"(d) : "l"(a), "l"(b));
}
__device__ __forceinline__ ull pack2(float x, float y) {
    ull r; asm("mov.b64 %0, {%1, %2};" : "=l"(r) : "f"(x), "f"(y)); return r;
}
__device__ __forceinline__ void unpack2(ull v, float &x, float &y) {
    asm("mov.b64 {%0, %1}, %2;" : "=f"(x), "=f"(y) : "l"(v));
}
__device__ __forceinline__ float prelu_f(float v, float a) { return v >= 0.f ? v : a * v; }

// ---------------------------------------------------------------------------
// K1: h[N,256] = prelu(concat[N,1024] @ W1 + b1, a_jk), fused s_x[N,8]
// BM=64, BN=256 (full), BK=16. 256 threads; per thread 8 rows x 8 cols,
// accumulated as 4 row-pairs x 8 cols in f32x2.
// ---------------------------------------------------------------------------
__global__ __launch_bounds__(256, 1) void k1_gemm(
    const float* __restrict__ feats, const float* __restrict__ W1,
    const float* __restrict__ b1, const float* __restrict__ a_jk_p,
    const float* __restrict__ w_att_x, int N)
{
    __shared__ float As[16][68];    // transposed A tile [k][row], padded
    __shared__ float Bs[16][256];
    __shared__ float sWx[FDIM];

    const int tid = threadIdx.x;
    const int n0  = blockIdx.x * 64;
    if (tid < FDIM) sWx[tid] = w_att_x[tid];

    const int trow = tid >> 5;   // warp id: rows trow*8 .. trow*8+7
    const int tcol = tid & 31;   // cols tcol*8 .. tcol*8+7

    ull acc[4][8];
    #pragma unroll
    for (int p = 0; p < 4; ++p)
        #pragma unroll
        for (int j = 0; j < 8; ++j) acc[p][j] = 0ull;

    const int lr = tid >> 2;            // A-load row 0..63
    const int lk = (tid & 3) << 2;      // A-load k offset 0,4,8,12
    int nrow = n0 + lr; if (nrow > N - 1) nrow = N - 1;

    const int bk = tid >> 4;            // B-load row 0..15
    const int bc = (tid & 15) << 4;     // B-load col base

    float sxreg = 0.f;

    for (int kt = 0; kt < 64; ++kt) {
        const int hop = kt >> 3;
        const int f0  = (kt & 7) << 4;

        float4 av = *(const float4*)(feats + (size_t)hop * N * FDIM
                                           + (size_t)nrow * FDIM + f0 + lk);
        As[lk + 0][lr] = av.x; As[lk + 1][lr] = av.y;
        As[lk + 2][lr] = av.z; As[lk + 3][lr] = av.w;

        const float4* bp = (const float4*)(W1 + (size_t)(kt * 16 + bk) * HID + bc);
        *(float4*)&Bs[bk][bc +  0] = bp[0];
        *(float4*)&Bs[bk][bc +  4] = bp[1];
        *(float4*)&Bs[bk][bc +  8] = bp[2];
        *(float4*)&Bs[bk][bc + 12] = bp[3];
        __syncthreads();

        if (tid < 64) {   // fused s_x partial for row tid
            #pragma unroll
            for (int kk = 0; kk < 16; ++kk) sxreg += As[kk][tid] * sWx[f0 + kk];
        }

        #pragma unroll
        for (int k = 0; k < 16; ++k) {
            ull ap[4];
            #pragma unroll
            for (int p = 0; p < 4; ++p)
                ap[p] = *(const ull*)&As[k][trow * 8 + p * 2];
            float4 bv0 = *(const float4*)&Bs[k][tcol * 8];
            float4 bv1 = *(const float4*)&Bs[k][tcol * 8 + 4];
            ull bd[8];
            bd[0] = pack2(bv0.x, bv0.x); bd[1] = pack2(bv0.y, bv0.y);
            bd[2] = pack2(bv0.z, bv0.z); bd[3] = pack2(bv0.w, bv0.w);
            bd[4] = pack2(bv1.x, bv1.x); bd[5] = pack2(bv1.y, bv1.y);
            bd[6] = pack2(bv1.z, bv1.z); bd[7] = pack2(bv1.w, bv1.w);
            #pragma unroll
            for (int p = 0; p < 4; ++p)
                #pragma unroll
                for (int j = 0; j < 8; ++j) ffma2(acc[p][j], ap[p], bd[j]);
        }
        __syncthreads();

        if ((kt & 7) == 7 && tid < 64) {
            if (n0 + tid < N) g_sx[(size_t)(n0 + tid) * HOPS + hop] = sxreg;
            sxreg = 0.f;
        }
    }

    const float a_jk = *a_jk_p;
    #pragma unroll
    for (int p = 0; p < 4; ++p) {
        const int r0 = trow * 8 + p * 2;
        float lo[8], hi[8];
        #pragma unroll
        for (int j = 0; j < 8; ++j) unpack2(acc[p][j], lo[j], hi[j]);
        #pragma unroll
        for (int j = 0; j < 8; ++j) {
            const float bb = b1[tcol * 8 + j];
            lo[j] = prelu_f(lo[j] + bb, a_jk);
            hi[j] = prelu_f(hi[j] + bb, a_jk);
        }
        if (n0 + r0 < N) {
            float* dst = g_h + (size_t)(n0 + r0) * HID + tcol * 8;
            *(float4*)(dst + 0) = make_float4(lo[0], lo[1], lo[2], lo[3]);
            *(float4*)(dst + 4) = make_float4(lo[4], lo[5], lo[6], lo[7]);
        }
        if (n0 + r0 + 1 < N) {
            float* dst = g_h + (size_t)(n0 + r0 + 1) * HID + tcol * 8;
            *(float4*)(dst + 0) = make_float4(hi[0], hi[1], hi[2], hi[3]);
            *(float4*)(dst + 4) = make_float4(hi[4], hi[5], hi[6], hi[7]);
        }
    }
}

// ---------------------------------------------------------------------------
// K2: jk = prelu(h@W2+b2, a_main); s_ref = jk . w_att_ref;
//     Wsm = softmax(sigmoid(s_x + s_ref + b_att)).  Writes only g_w[N,8].
// ---------------------------------------------------------------------------
__global__ __launch_bounds__(256, 1) void k2_att(
    const float* __restrict__ W2, const float* __restrict__ b2,
    const float* __restrict__ a_main_p, const float* __restrict__ w_ref,
    const float* __restrict__ b_att_p, int N)
{
    __shared__ float As[16][68];
    __shared__ float Bs[16][256];
    __shared__ float sred[64];

    const int tid = threadIdx.x;
    const int n0  = blockIdx.x * 64;
    const int trow = tid >> 5, tcol = tid & 31;

    ull acc[4][8];
    #pragma unroll
    for (int p = 0; p < 4; ++p)
        #pragma unroll
        for (int j = 0; j < 8; ++j) acc[p][j] = 0ull;

    const int lr = tid >> 2, lk = (tid & 3) << 2;
    int nrow = n0 + lr; if (nrow > N - 1) nrow = N - 1;
    const int bk = tid >> 4, bc = (tid & 15) << 4;

    for (int kt = 0; kt < 16; ++kt) {
        float4 av = *(const float4*)(g_h + (size_t)nrow * HID + kt * 16 + lk);
        As[lk + 0][lr] = av.x; As[lk + 1][lr] = av.y;
        As[lk + 2][lr] = av.z; As[lk + 3][lr] = av.w;

        const float4* bp = (const float4*)(W2 + (size_t)(kt * 16 + bk) * HID + bc);
        *(float4*)&Bs[bk][bc +  0] = bp[0];
        *(float4*)&Bs[bk][bc +  4] = bp[1];
        *(float4*)&Bs[bk][bc +  8] = bp[2];
        *(float4*)&Bs[bk][bc + 12] = bp[3];
        __syncthreads();

        #pragma unroll
        for (int k = 0; k < 16; ++k) {
            ull ap[4];
            #pragma unroll
            for (int p = 0; p < 4; ++p)
                ap[p] = *(const ull*)&As[k][trow * 8 + p * 2];
            float4 bv0 = *(const float4*)&Bs[k][tcol * 8];
            float4 bv1 = *(const float4*)&Bs[k][tcol * 8 + 4];
            ull bd[8];
            bd[0] = pack2(bv0.x, bv0.x); bd[1] = pack2(bv0.y, bv0.y);
            bd[2] = pack2(bv0.z, bv0.z); bd[3] = pack2(bv0.w, bv0.w);
            bd[4] = pack2(bv1.x, bv1.x); bd[5] = pack2(bv1.y, bv1.y);
            bd[6] = pack2(bv1.z, bv1.z); bd[7] = pack2(bv1.w, bv1.w);
            #pragma unroll
            for (int p = 0; p < 4; ++p)
                #pragma unroll
                for (int j = 0; j < 8; ++j) ffma2(acc[p][j], ap[p], bd[j]);
        }
        __syncthreads();
    }

    const float a_main = *a_main_p;
    float part[8];
    #pragma unroll
    for (int i = 0; i < 8; ++i) part[i] = 0.f;
    #pragma unroll
    for (int p = 0; p < 4; ++p) {
        #pragma unroll
        for (int j = 0; j < 8; ++j) {
            const int c = tcol * 8 + j;
            const float wr = w_ref[c], bb = b2[c];
            float x, y; unpack2(acc[p][j], x, y);
            part[2 * p]     += prelu_f(x + bb, a_main) * wr;
            part[2 * p + 1] += prelu_f(y + bb, a_main) * wr;
        }
    }
    #pragma unroll
    for (int i = 0; i < 8; ++i) {
        #pragma unroll
        for (int off = 16; off > 0; off >>= 1)
            part[i] += __shfl_xor_sync(0xffffffffu, part[i], off);
    }
    if (tcol == 0) {
        #pragma unroll
        for (int i = 0; i < 8; ++i) sred[trow * 8 + i] = part[i];
    }
    __syncthreads();

    if (tid < 64 && n0 + tid < N) {
        const float base = sred[tid] + *b_att_p;
        const size_t off = (size_t)(n0 + tid) * HOPS;
        float s[HOPS];
        float m = -1e30f;
        #pragma unroll
        for (int h = 0; h < HOPS; ++h) {
            float z = g_sx[off + h] + base;
            s[h] = 1.f / (1.f + expf(-z));        // sigmoid
            m = fmaxf(m, s[h]);
        }
        float sum = 0.f;
        #pragma unroll
        for (int h = 0; h < HOPS; ++h) { s[h] = expf(s[h] - m); sum += s[h]; }
        const float inv = 1.f / sum;
        #pragma unroll
        for (int h = 0; h < HOPS; ++h) g_w[off + h] = s[h] * inv;
    }
}

// ---------------------------------------------------------------------------
// K3: agg = sum_h Wsm[:,h]*feats[h]; t = prelu(agg@Wo1+bo1, a_out);
//     out = t@Wo2 + bo2.  Fully fused per 64-node tile, 115KB dynamic smem.
// ---------------------------------------------------------------------------
__global__ __launch_bounds__(256, 1) void k3_out(
    const float* __restrict__ feats, const float* __restrict__ Wo1,
    const float* __restrict__ bo1, const float* __restrict__ a_out_p,
    const float* __restrict__ Wo2, const float* __restrict__ bo2,
    float* __restrict__ out, int N)
{
    extern __shared__ float sm[];
    float* sAgg = sm;                        // 64*128
    float* sB   = sm + 64 * FDIM;            // 16*256 (reused for Wo2 tiles)
    float* sT   = sB + 16 * HID;             // 64*256

    const int tid = threadIdx.x;
    const int n0  = blockIdx.x * 64;

    // ---- Phase A: weighted hop aggregation into sAgg ----
    float4 aacc[8];
    #pragma unroll
    for (int c = 0; c < 8; ++c) aacc[c] = make_float4(0.f, 0.f, 0.f, 0.f);
    for (int hop = 0; hop < HOPS; ++hop) {
        const float* fb = feats + (size_t)hop * N * FDIM;
        #pragma unroll
        for (int c = 0; c < 8; ++c) {
            const int flat = c * 1024 + tid * 4;     // r*128 + f
            const int r = flat >> 7;
            int n = n0 + r; int nc = (n < N) ? n : (N - 1);
            const float w = g_w[(size_t)nc * HOPS + hop];
            const float4 v = *(const float4*)(fb + (size_t)nc * FDIM + (flat & 127));
            aacc[c].x += w * v.x; aacc[c].y += w * v.y;
            aacc[c].z += w * v.z; aacc[c].w += w * v.w;
        }
    }
    #pragma unroll
    for (int c = 0; c < 8; ++c)
        *(float4*)&sAgg[c * 1024 + tid * 4] = aacc[c];

    // ---- Phase B: t = prelu(agg @ Wo1 + bo1), K=128 ----
    const int trow = tid >> 5, tcol = tid & 31;
    ull accB[8][4];
    #pragma unroll
    for (int i = 0; i < 8; ++i)
        #pragma unroll
        for (int j = 0; j < 4; ++j) accB[i][j] = 0ull;
    const int bk = tid >> 4, bc = (tid & 15) << 4;

    for (int kt = 0; kt < 8; ++kt) {
        const float4* bp = (const float4*)(Wo1 + (size_t)(kt * 16 + bk) * HID + bc);
        float4 t0 = bp[0], t1 = bp[1], t2 = bp[2], t3 = bp[3];
        __syncthreads();   // also covers sAgg writes (first iter) / prior reads
        *(float4*)&sB[bk * HID + bc +  0] = t0;
        *(float4*)&sB[bk * HID + bc +  4] = t1;
        *(float4*)&sB[bk * HID + bc +  8] = t2;
        *(float4*)&sB[bk * HID + bc + 12] = t3;
        __syncthreads();
        #pragma unroll
        for (int k = 0; k < 16; ++k) {
            const int kk = kt * 16 + k;
            float a[8];
            #pragma unroll
            for (int i = 0; i < 8; ++i) a[i] = sAgg[(trow * 8 + i) * FDIM + kk];
            ull ad[8];
            #pragma unroll
            for (int i = 0; i < 8; ++i) ad[i] = pack2(a[i], a[i]);
            const ull* bp2 = (const ull*)&sB[k * HID + tcol * 8];
            ull bv[4]; bv[0] = bp2[0]; bv[1] = bp2[1]; bv[2] = bp2[2]; bv[3] = bp2[3];
            #pragma unroll
            for (int i = 0; i < 8; ++i)
                #pragma unroll
                for (int j = 0; j < 4; ++j) ffma2(accB[i][j], ad[i], bv[j]);
        }
    }
    __syncthreads();

    const float a_out = *a_out_p;
    #pragma unroll
    for (int i = 0; i < 8; ++i) {
        const int row = trow * 8 + i;
        float t[8];
        #pragma unroll
        for (int j = 0; j < 4; ++j) unpack2(accB[i][j], t[2 * j], t[2 * j + 1]);
        #pragma unroll
        for (int jj = 0; jj < 8; ++jj)
            t[jj] = prelu_f(t[jj] + bo1[tcol * 8 + jj], a_out);
        float* dst = sT + row * HID + tcol * 8;
        *(float4*)(dst + 0) = make_float4(t[0], t[1], t[2], t[3]);
        *(float4*)(dst + 4) = make_float4(t[4], t[5], t[6], t[7]);
    }
    __syncthreads();

    // ---- Phase C: out = t @ Wo2 + bo2, K=256, cols=64 ----
    float accC[8][2];
    #pragma unroll
    for (int i = 0; i < 8; ++i) { accC[i][0] = 0.f; accC[i][1] = 0.f; }
    const int col2 = tcol * 2;
    const int bk2 = tid >> 4;            // 0..15
    const int bc2 = (tid & 15) << 2;     // 0..60

    for (int kt = 0; kt < 16; ++kt) {
        float4 bt = *(const float4*)(Wo2 + (size_t)(kt * 16 + bk2) * NCLS + bc2);
        __syncthreads();   // protect sB reuse between iterations
        *(float4*)&sB[bk2 * NCLS + bc2] = bt;
        __syncthreads();
        #pragma unroll
        for (int k = 0; k < 16; ++k) {
            const float2 bb = *(const float2*)&sB[k * NCLS + col2];
            #pragma unroll
            for (int i = 0; i < 8; ++i) {
                const float a = sT[(trow * 8 + i) * HID + kt * 16 + k];
                accC[i][0] += a * bb.x;
                accC[i][1] += a * bb.y;
            }
        }
    }

    #pragma unroll
    for (int i = 0; i < 8; ++i) {
        const int n = n0 + trow * 8 + i;
        if (n < N) {
            float2 o;
            o.x = accC[i][0] + bo2[col2];
            o.y = accC[i][1] + bo2[col2 + 1];
            *(float2*)&out[(size_t)n * NCLS + col2] = o;
        }
    }
}

// ---------------------------------------------------------------------------
extern "C" void kernel_launch(void* const* d_in, const int* in_sizes, int n_in,
                              void* d_out, int out_size)
{
    const float* feats  = (const float*)d_in[0];
    const float* W_jk1  = (const float*)d_in[1];
    const float* b_jk1  = (const float*)d_in[2];
    const float* W_jk2  = (const float*)d_in[3];
    const float* b_jk2  = (const float*)d_in[4];
    const float* a_jk   = (const float*)d_in[5];
    const float* a_main = (const float*)d_in[6];
    const float* a_out  = (const float*)d_in[7];
    const float* w_ref  = (const float*)d_in[8];
    const float* w_x    = (const float*)d_in[9];
    const float* b_att  = (const float*)d_in[10];
    const float* W_o1   = (const float*)d_in[11];
    const float* b_o1   = (const float*)d_in[12];
    const float* W_o2   = (const float*)d_in[13];
    const float* b_o2   = (const float*)d_in[14];
    float* out = (float*)d_out;

    const int N  = in_sizes[0] / (HOPS * FDIM);
    const int nb = (N + 63) / 64;

    const size_t smem3 = (size_t)(64 * FDIM + 16 * HID + 64 * HID) * sizeof(float);
    cudaFuncSetAttribute(k3_out, cudaFuncAttributeMaxDynamicSharedMemorySize, (int)smem3);

    k1_gemm<<<nb, 256>>>(feats, W_jk1, b_jk1, a_jk, w_x, N);
    k2_att <<<nb, 256>>>(W_jk2, b_jk2, a_main, w_ref, b_att, N);
    k3_out <<<nb, 256, smem3>>>(feats, W_o1, b_o1, a_out, W_o2, b_o2, out, N);
}

// round 5
// speedup vs baseline: 2.3740x; 2.3740x over previous
#include <cuda_runtime.h>
#include <cuda_bf16.h>
#include <cstdint>

#define HOPS 8
#define FDIM 128
#define HID  256
#define NCLS 64
#define NMAX 100096

typedef unsigned long long ull;

// ---------------- scratch (device globals; no runtime alloc) ----------------
__device__ __nv_bfloat16 g_h_hi[(size_t)NMAX * HID];
__device__ __nv_bfloat16 g_h_lo[(size_t)NMAX * HID];
__device__ float g_sx[(size_t)NMAX * HOPS];
__device__ float g_w [(size_t)NMAX * HOPS];
__device__ __nv_bfloat16 g_W1T_hi[(size_t)HID * 1024];   // [c][k]
__device__ __nv_bfloat16 g_W1T_lo[(size_t)HID * 1024];
__device__ __nv_bfloat16 g_W2T_hi[(size_t)HID * HID];
__device__ __nv_bfloat16 g_W2T_lo[(size_t)HID * HID];
__device__ __nv_bfloat16 g_Wo1T_hi[(size_t)HID * FDIM];  // [c=256][k=128]
__device__ __nv_bfloat16 g_Wo1T_lo[(size_t)HID * FDIM];
__device__ __nv_bfloat16 g_Wo2T_hi[(size_t)NCLS * HID];  // [c=64][k=256]
__device__ __nv_bfloat16 g_Wo2T_lo[(size_t)NCLS * HID];

// ---------------- helpers ----------------
__device__ __forceinline__ uint32_t smem_u32(const void* p) {
    uint32_t a;
    asm("{ .reg .u64 t; cvta.to.shared.u64 t, %1; cvt.u32.u64 %0, t; }" : "=r"(a) : "l"(p));
    return a;
}
__device__ __forceinline__ void ldsm4(uint32_t* r, uint32_t addr) {
    asm volatile("ldmatrix.sync.aligned.m8n8.x4.shared.b16 {%0,%1,%2,%3}, [%4];"
        : "=r"(r[0]), "=r"(r[1]), "=r"(r[2]), "=r"(r[3]) : "r"(addr));
}
__device__ __forceinline__ void mma16816(float* c, const uint32_t* a, const uint32_t* b) {
    asm volatile("mma.sync.aligned.m16n8k16.row.col.f32.bf16.bf16.f32 "
        "{%0,%1,%2,%3}, {%4,%5,%6,%7}, {%8,%9}, {%0,%1,%2,%3};"
        : "+f"(c[0]), "+f"(c[1]), "+f"(c[2]), "+f"(c[3])
        : "r"(a[0]), "r"(a[1]), "r"(a[2]), "r"(a[3]), "r"(b[0]), "r"(b[1]));
}
__device__ __forceinline__ float prelu_f(float v, float a) { return v >= 0.f ? v : a * v; }

union BfPair { uint32_t u; __nv_bfloat16 e[2]; };
union Bf4    { ull u;      __nv_bfloat16 e[4]; };
union Bf8    { uint4 q;    __nv_bfloat16 e[8]; };

// store two adjacent columns (c, c+1) of value pair as split bf16 hi/lo
__device__ __forceinline__ void store_split2(__nv_bfloat16* hi, __nv_bfloat16* lo,
                                             size_t base, float x0, float x1) {
    BfPair ph, pl;
    ph.e[0] = __float2bfloat16(x0);
    ph.e[1] = __float2bfloat16(x1);
    pl.e[0] = __float2bfloat16(x0 - __bfloat162float(ph.e[0]));
    pl.e[1] = __float2bfloat16(x1 - __bfloat162float(ph.e[1]));
    *(uint32_t*)&hi[base] = ph.u;
    *(uint32_t*)&lo[base] = pl.u;
}

// ---------------------------------------------------------------------------
// k0: transpose + bf16-split all four weight matrices
// ---------------------------------------------------------------------------
__global__ void k0_convert(const float* __restrict__ W1, const float* __restrict__ W2,
                           const float* __restrict__ Wo1, const float* __restrict__ Wo2)
{
    int idx = blockIdx.x * 1024 + threadIdx.x;
    float v; size_t dst; __nv_bfloat16* ph; __nv_bfloat16* pl;
    if (idx < 262144) {                       // W1 [1024][256]
        int k = idx >> 8, c = idx & 255;
        v = W1[idx]; dst = (size_t)c * 1024 + k; ph = g_W1T_hi; pl = g_W1T_lo;
    } else if (idx < 327680) {                // W2 [256][256]
        int i = idx - 262144, k = i >> 8, c = i & 255;
        v = W2[i]; dst = (size_t)c * 256 + k; ph = g_W2T_hi; pl = g_W2T_lo;
    } else if (idx < 360448) {                // Wo1 [128][256]
        int i = idx - 327680, k = i >> 8, c = i & 255;
        v = Wo1[i]; dst = (size_t)c * 128 + k; ph = g_Wo1T_hi; pl = g_Wo1T_lo;
    } else if (idx < 376832) {                // Wo2 [256][64]
        int i = idx - 360448, k = i >> 6, c = i & 63;
        v = Wo2[i]; dst = (size_t)c * 256 + k; ph = g_Wo2T_hi; pl = g_Wo2T_lo;
    } else return;
    __nv_bfloat16 h = __float2bfloat16(v);
    ph[dst] = h;
    pl[dst] = __float2bfloat16(v - __bfloat162float(h));
}

// ---------------------------------------------------------------------------
// Shared smem layout for k1/k2: A[128][64] hi/lo (pitch 144B), B[256][64] hi/lo
// ---------------------------------------------------------------------------
#define OFF_AH 0
#define OFF_AL 18432
#define OFF_BH 36864
#define OFF_BL 73728
// k1 extras
#define K1_WX  110592
#define K1_B1  111104
#define K1_SMEM 112128
// k2 extras
#define K2_SRED 110592
#define K2_B2   112640
#define K2_WR   113664
#define K2_SMEM 114688

// ---------------------------------------------------------------------------
// k1: h = prelu(concat @ W1 + b1, a_jk) -> g_h hi/lo; fused s_x.
// 512 thr, BM=128, BN=256, K chunks of 64. Warps 4M x 4N, warp tile 32x64.
// ---------------------------------------------------------------------------
__global__ __launch_bounds__(512, 1) void k1_gemm(
    const float* __restrict__ feats, const float* __restrict__ wx,
    const float* __restrict__ b1, const float* __restrict__ a_jk_p, int N)
{
    extern __shared__ char smraw[];
    const uint32_t sb = smem_u32(smraw);
    const int tid = threadIdx.x, wid = tid >> 5, lane = tid & 31;
    const int n0 = blockIdx.x * 128;
    const int wm = wid & 3, wn = wid >> 2;          // 4 x 4 warps: 32 rows x 64 cols
    const int g = lane >> 2, tg = lane & 3;

    float* wxs = (float*)(smraw + K1_WX);
    float* sb1 = (float*)(smraw + K1_B1);
    if (tid < 128) wxs[tid] = wx[tid];
    else if (tid < 384) sb1[tid - 128] = b1[tid - 128];

    float acc[2][8][4];
    #pragma unroll
    for (int a = 0; a < 2; ++a)
        #pragma unroll
        for (int b = 0; b < 8; ++b)
            #pragma unroll
            for (int c = 0; c < 4; ++c) acc[a][b][c] = 0.f;

    const uint32_t aoffH = sb + OFF_AH + (uint32_t)(wm * 32 + (lane & 15)) * 144
                         + (uint32_t)((lane >> 4) * 8) * 2;
    const uint32_t aoffL = aoffH + (OFF_AL - OFF_AH);
    const int brow = (lane & 7) + ((lane >> 4) << 3);
    const int bko  = ((lane >> 3) & 1) * 8;
    const uint32_t boffH = sb + OFF_BH + (uint32_t)(wn * 64 + brow) * 144 + (uint32_t)bko * 2;
    const uint32_t boffL = boffH + (OFF_BL - OFF_BH);

    float sx = 0.f;

    for (int chunk = 0; chunk < 16; ++chunk) {
        const int hop = chunk >> 1, f0 = (chunk & 1) << 6, c0 = chunk << 6;
        const float* fb = feats + (size_t)hop * N * FDIM + f0;
        #pragma unroll
        for (int i = 0; i < 4; ++i) {
            int idx = i * 512 + tid;
            int r = idx >> 4, cq = (idx & 15) << 2;
            int n = n0 + r; if (n > N - 1) n = N - 1;
            float4 v = *(const float4*)(fb + (size_t)n * FDIM + cq);
            Bf4 uh, ulo;
            float f[4] = {v.x, v.y, v.z, v.w};
            #pragma unroll
            for (int j = 0; j < 4; ++j) {
                __nv_bfloat16 h = __float2bfloat16(f[j]);
                uh.e[j]  = h;
                ulo.e[j] = __float2bfloat16(f[j] - __bfloat162float(h));
            }
            *(ull*)(smraw + OFF_AH + r * 144 + cq * 2) = uh.u;
            *(ull*)(smraw + OFF_AL + r * 144 + cq * 2) = ulo.u;
        }
        // B tile: 256 rows x 64 cols (2048 uint4 stores -> i < 4)
        #pragma unroll
        for (int i = 0; i < 4; ++i) {
            int idx = i * 512 + tid;
            int r = idx >> 3, c8 = (idx & 7) << 3;
            *(uint4*)(smraw + OFF_BH + r * 144 + c8 * 2) =
                *(const uint4*)(g_W1T_hi + (size_t)r * 1024 + c0 + c8);
            *(uint4*)(smraw + OFF_BL + r * 144 + c8 * 2) =
                *(const uint4*)(g_W1T_lo + (size_t)r * 1024 + c0 + c8);
        }
        __syncthreads();

        if (tid < 128) {   // fused s_x for row tid
            const char* bh = smraw + OFF_AH + tid * 144;
            const char* bl = smraw + OFF_AL + tid * 144;
            #pragma unroll
            for (int i8 = 0; i8 < 8; ++i8) {
                Bf8 qh, ql;
                qh.q = *(const uint4*)(bh + i8 * 16);
                ql.q = *(const uint4*)(bl + i8 * 16);
                #pragma unroll
                for (int j = 0; j < 8; ++j)
                    sx += (__bfloat162float(qh.e[j]) + __bfloat162float(ql.e[j]))
                        * wxs[f0 + i8 * 8 + j];
            }
        }

        #pragma unroll
        for (int ks = 0; ks < 4; ++ks) {
            uint32_t ah[2][4], al[2][4];
            ldsm4(ah[0], aoffH + ks * 32);
            ldsm4(ah[1], aoffH + 16 * 144 + ks * 32);
            ldsm4(al[0], aoffL + ks * 32);
            ldsm4(al[1], aoffL + 16 * 144 + ks * 32);
            #pragma unroll
            for (int ntp = 0; ntp < 4; ++ntp) {
                uint32_t bh[4], bl[4];
                ldsm4(bh, boffH + ntp * 16 * 144 + ks * 32);
                ldsm4(bl, boffL + ntp * 16 * 144 + ks * 32);
                #pragma unroll
                for (int mt = 0; mt < 2; ++mt) {
                    mma16816(acc[mt][ntp * 2],     ah[mt], bh);
                    mma16816(acc[mt][ntp * 2],     ah[mt], bl);
                    mma16816(acc[mt][ntp * 2],     al[mt], bh);
                    mma16816(acc[mt][ntp * 2 + 1], ah[mt], bh + 2);
                    mma16816(acc[mt][ntp * 2 + 1], ah[mt], bl + 2);
                    mma16816(acc[mt][ntp * 2 + 1], al[mt], bh + 2);
                }
            }
        }
        __syncthreads();

        if ((chunk & 1) && tid < 128) {
            if (n0 + tid < N) g_sx[(size_t)(n0 + tid) * HOPS + hop] = sx;
            sx = 0.f;
        }
    }

    const float a_jk = *a_jk_p;
    #pragma unroll
    for (int mt = 0; mt < 2; ++mt) {
        const int r0 = n0 + wm * 32 + mt * 16 + g;
        #pragma unroll
        for (int nt = 0; nt < 8; ++nt) {
            const int c = wn * 64 + nt * 8 + tg * 2;
            const float b0v = sb1[c], b1v = sb1[c + 1];
            if (r0 < N) {
                float x0 = prelu_f(acc[mt][nt][0] + b0v, a_jk);
                float x1 = prelu_f(acc[mt][nt][1] + b1v, a_jk);
                store_split2(g_h_hi, g_h_lo, (size_t)r0 * HID + c, x0, x1);
            }
            if (r0 + 8 < N) {
                float x2 = prelu_f(acc[mt][nt][2] + b0v, a_jk);
                float x3 = prelu_f(acc[mt][nt][3] + b1v, a_jk);
                store_split2(g_h_hi, g_h_lo, (size_t)(r0 + 8) * HID + c, x2, x3);
            }
        }
    }
}

// ---------------------------------------------------------------------------
// k2: jk = prelu(h @ W2 + b2, a_main); s_ref = jk . w_ref;
//     g_w = softmax(sigmoid(s_x + s_ref + b_att))
// ---------------------------------------------------------------------------
__global__ __launch_bounds__(512, 1) void k2_att(
    const float* __restrict__ b2, const float* __restrict__ a_main_p,
    const float* __restrict__ w_ref, const float* __restrict__ b_att_p, int N)
{
    extern __shared__ char smraw[];
    const uint32_t sb = smem_u32(smraw);
    const int tid = threadIdx.x, wid = tid >> 5, lane = tid & 31;
    const int n0 = blockIdx.x * 128;
    const int wm = wid & 3, wn = wid >> 2;
    const int g = lane >> 2, tg = lane & 3;

    float* sred = (float*)(smraw + K2_SRED);   // [128][4]
    float* sb2  = (float*)(smraw + K2_B2);
    float* swr  = (float*)(smraw + K2_WR);
    if (tid < 256) sb2[tid] = b2[tid];
    else swr[tid - 256] = w_ref[tid - 256];

    float acc[2][8][4];
    #pragma unroll
    for (int a = 0; a < 2; ++a)
        #pragma unroll
        for (int b = 0; b < 8; ++b)
            #pragma unroll
            for (int c = 0; c < 4; ++c) acc[a][b][c] = 0.f;

    const uint32_t aoffH = sb + OFF_AH + (uint32_t)(wm * 32 + (lane & 15)) * 144
                         + (uint32_t)((lane >> 4) * 8) * 2;
    const uint32_t aoffL = aoffH + (OFF_AL - OFF_AH);
    const int brow = (lane & 7) + ((lane >> 4) << 3);
    const int bko  = ((lane >> 3) & 1) * 8;
    const uint32_t boffH = sb + OFF_BH + (uint32_t)(wn * 64 + brow) * 144 + (uint32_t)bko * 2;
    const uint32_t boffL = boffH + (OFF_BL - OFF_BH);

    for (int chunk = 0; chunk < 4; ++chunk) {
        const int c0 = chunk << 6;
        #pragma unroll
        for (int i = 0; i < 2; ++i) {
            int idx = i * 512 + tid;
            int r = idx >> 3, c8 = (idx & 7) << 3;
            int n = n0 + r; if (n > N - 1) n = N - 1;
            *(uint4*)(smraw + OFF_AH + r * 144 + c8 * 2) =
                *(const uint4*)(g_h_hi + (size_t)n * HID + c0 + c8);
            *(uint4*)(smraw + OFF_AL + r * 144 + c8 * 2) =
                *(const uint4*)(g_h_lo + (size_t)n * HID + c0 + c8);
        }
        // B tile: 256 rows (i < 4)
        #pragma unroll
        for (int i = 0; i < 4; ++i) {
            int idx = i * 512 + tid;
            int r = idx >> 3, c8 = (idx & 7) << 3;
            *(uint4*)(smraw + OFF_BH + r * 144 + c8 * 2) =
                *(const uint4*)(g_W2T_hi + (size_t)r * 256 + c0 + c8);
            *(uint4*)(smraw + OFF_BL + r * 144 + c8 * 2) =
                *(const uint4*)(g_W2T_lo + (size_t)r * 256 + c0 + c8);
        }
        __syncthreads();

        #pragma unroll
        for (int ks = 0; ks < 4; ++ks) {
            uint32_t ah[2][4], al[2][4];
            ldsm4(ah[0], aoffH + ks * 32);
            ldsm4(ah[1], aoffH + 16 * 144 + ks * 32);
            ldsm4(al[0], aoffL + ks * 32);
            ldsm4(al[1], aoffL + 16 * 144 + ks * 32);
            #pragma unroll
            for (int ntp = 0; ntp < 4; ++ntp) {
                uint32_t bh[4], bl[4];
                ldsm4(bh, boffH + ntp * 16 * 144 + ks * 32);
                ldsm4(bl, boffL + ntp * 16 * 144 + ks * 32);
                #pragma unroll
                for (int mt = 0; mt < 2; ++mt) {
                    mma16816(acc[mt][ntp * 2],     ah[mt], bh);
                    mma16816(acc[mt][ntp * 2],     ah[mt], bl);
                    mma16816(acc[mt][ntp * 2],     al[mt], bh);
                    mma16816(acc[mt][ntp * 2 + 1], ah[mt], bh + 2);
                    mma16816(acc[mt][ntp * 2 + 1], ah[mt], bl + 2);
                    mma16816(acc[mt][ntp * 2 + 1], al[mt], bh + 2);
                }
            }
        }
        __syncthreads();
    }

    // epilogue: prelu -> dot(w_ref) partial -> reduce over 4-lane groups
    const float a_main = *a_main_p;
    float part[2][2] = {{0.f, 0.f}, {0.f, 0.f}};
    #pragma unroll
    for (int mt = 0; mt < 2; ++mt) {
        #pragma unroll
        for (int nt = 0; nt < 8; ++nt) {
            const int c = wn * 64 + nt * 8 + tg * 2;
            const float w0 = swr[c], w1 = swr[c + 1];
            const float bb0 = sb2[c], bb1 = sb2[c + 1];
            part[mt][0] += prelu_f(acc[mt][nt][0] + bb0, a_main) * w0
                         + prelu_f(acc[mt][nt][1] + bb1, a_main) * w1;
            part[mt][1] += prelu_f(acc[mt][nt][2] + bb0, a_main) * w0
                         + prelu_f(acc[mt][nt][3] + bb1, a_main) * w1;
        }
    }
    #pragma unroll
    for (int mt = 0; mt < 2; ++mt)
        #pragma unroll
        for (int h = 0; h < 2; ++h) {
            part[mt][h] += __shfl_xor_sync(0xffffffffu, part[mt][h], 1);
            part[mt][h] += __shfl_xor_sync(0xffffffffu, part[mt][h], 2);
        }
    if (tg == 0) {
        #pragma unroll
        for (int mt = 0; mt < 2; ++mt) {
            const int r = wm * 32 + mt * 16 + g;
            sred[r * 4 + wn]       = part[mt][0];
            sred[(r + 8) * 4 + wn] = part[mt][1];
        }
    }
    __syncthreads();

    if (tid < 128) {
        const int n = n0 + tid;
        if (n < N) {
            const float sref = sred[tid * 4] + sred[tid * 4 + 1]
                             + sred[tid * 4 + 2] + sred[tid * 4 + 3] + *b_att_p;
            const float* sxp = g_sx + (size_t)n * HOPS;
            float s[HOPS];
            float m = -1e30f;
            #pragma unroll
            for (int h = 0; h < HOPS; ++h) {
                float z = sxp[h] + sref;
                s[h] = 1.f / (1.f + expf(-z));
                m = fmaxf(m, s[h]);
            }
            float sum = 0.f;
            #pragma unroll
            for (int h = 0; h < HOPS; ++h) { s[h] = expf(s[h] - m); sum += s[h]; }
            const float inv = 1.f / sum;
            float* d = g_w + (size_t)n * HOPS;
            *(float4*)(d + 0) = make_float4(s[0] * inv, s[1] * inv, s[2] * inv, s[3] * inv);
            *(float4*)(d + 4) = make_float4(s[4] * inv, s[5] * inv, s[6] * inv, s[7] * inv);
        }
    }
}

// ---------------------------------------------------------------------------
// k3: agg = sum_h Wsm*feats (scalar, DRAM-bound); FFN1+FFN2 via mma.sync.
// 256 thr, BM=64.
// ---------------------------------------------------------------------------
#define AGH 0
#define AGL 17408
#define BB  34816
#define TH  108544
#define TL  142336
#define K3_SMEM 176128

__global__ __launch_bounds__(256, 1) void k3_out(
    const float* __restrict__ feats, const float* __restrict__ bo1,
    const float* __restrict__ a_out_p, const float* __restrict__ bo2,
    float* __restrict__ out, int N)
{
    extern __shared__ char smraw[];
    const uint32_t sb = smem_u32(smraw);
    const int tid = threadIdx.x, wid = tid >> 5, lane = tid & 31;
    const int n0 = blockIdx.x * 64;
    const int g = lane >> 2, tg = lane & 3;

    // ---- Phase A: weighted hop aggregation -> split bf16 smem (pitch 272B) ----
    float4 aacc[8];
    #pragma unroll
    for (int c = 0; c < 8; ++c) aacc[c] = make_float4(0.f, 0.f, 0.f, 0.f);
    for (int hop = 0; hop < HOPS; ++hop) {
        const float* fb = feats + (size_t)hop * N * FDIM;
        #pragma unroll
        for (int c = 0; c < 8; ++c) {
            const int flat = c * 1024 + tid * 4;
            const int r = flat >> 7;
            int n = n0 + r; int nc = (n < N) ? n : (N - 1);
            const float w = g_w[(size_t)nc * HOPS + hop];
            const float4 v = *(const float4*)(fb + (size_t)nc * FDIM + (flat & 127));
            aacc[c].x += w * v.x; aacc[c].y += w * v.y;
            aacc[c].z += w * v.z; aacc[c].w += w * v.w;
        }
    }
    #pragma unroll
    for (int c = 0; c < 8; ++c) {
        const int flat = c * 1024 + tid * 4;
        const int r = flat >> 7, f = flat & 127;
        Bf4 uh, ulo;
        float fv[4] = {aacc[c].x, aacc[c].y, aacc[c].z, aacc[c].w};
        #pragma unroll
        for (int j = 0; j < 4; ++j) {
            __nv_bfloat16 h = __float2bfloat16(fv[j]);
            uh.e[j]  = h;
            ulo.e[j] = __float2bfloat16(fv[j] - __bfloat162float(h));
        }
        *(ull*)(smraw + AGH + r * 272 + f * 2) = uh.u;
        *(ull*)(smraw + AGL + r * 272 + f * 2) = ulo.u;
    }
    __syncthreads();

    const int brow = (lane & 7) + ((lane >> 4) << 3);
    const int bko  = ((lane >> 3) & 1) * 8;

    // ---- FFN1: t = prelu(agg[64x128] @ Wo1 + bo1) -> split smem (pitch 528B) ----
    {
        const int wm = wid & 1, wn = wid >> 1;   // 2M x 4N, warp 32x64
        float acc1[2][8][4];
        #pragma unroll
        for (int a = 0; a < 2; ++a)
            #pragma unroll
            for (int b = 0; b < 8; ++b)
                #pragma unroll
                for (int c = 0; c < 4; ++c) acc1[a][b][c] = 0.f;

        const uint32_t aoffH = sb + AGH + (uint32_t)(wm * 32 + (lane & 15)) * 272
                             + (uint32_t)((lane >> 4) * 8) * 2;
        const uint32_t aoffL = aoffH + (AGL - AGH);
        const uint32_t boffH = sb + BB + (uint32_t)(wn * 64 + brow) * 144 + (uint32_t)bko * 2;
        const uint32_t boffL = boffH + 36864;

        for (int cb = 0; cb < 2; ++cb) {
            #pragma unroll
            for (int i = 0; i < 8; ++i) {
                int idx = i * 256 + tid;
                int r = idx >> 3, c8 = (idx & 7) << 3;
                *(uint4*)(smraw + BB + r * 144 + c8 * 2) =
                    *(const uint4*)(g_Wo1T_hi + (size_t)r * 128 + cb * 64 + c8);
                *(uint4*)(smraw + BB + 36864 + r * 144 + c8 * 2) =
                    *(const uint4*)(g_Wo1T_lo + (size_t)r * 128 + cb * 64 + c8);
            }
            __syncthreads();
            #pragma unroll
            for (int ks = 0; ks < 4; ++ks) {
                const int kglob = cb * 64 + ks * 16;
                uint32_t ah[2][4], al[2][4];
                ldsm4(ah[0], aoffH + kglob * 2);
                ldsm4(ah[1], aoffH + 16 * 272 + kglob * 2);
                ldsm4(al[0], aoffL + kglob * 2);
                ldsm4(al[1], aoffL + 16 * 272 + kglob * 2);
                #pragma unroll
                for (int ntp = 0; ntp < 4; ++ntp) {
                    uint32_t bh[4], bl[4];
                    ldsm4(bh, boffH + ntp * 16 * 144 + ks * 32);
                    ldsm4(bl, boffL + ntp * 16 * 144 + ks * 32);
                    #pragma unroll
                    for (int mt = 0; mt < 2; ++mt) {
                        mma16816(acc1[mt][ntp * 2],     ah[mt], bh);
                        mma16816(acc1[mt][ntp * 2],     ah[mt], bl);
                        mma16816(acc1[mt][ntp * 2],     al[mt], bh);
                        mma16816(acc1[mt][ntp * 2 + 1], ah[mt], bh + 2);
                        mma16816(acc1[mt][ntp * 2 + 1], ah[mt], bl + 2);
                        mma16816(acc1[mt][ntp * 2 + 1], al[mt], bh + 2);
                    }
                }
            }
            __syncthreads();
        }

        const float a_out = *a_out_p;
        __nv_bfloat16* th = (__nv_bfloat16*)(smraw + TH);
        __nv_bfloat16* tl = (__nv_bfloat16*)(smraw + TL);
        #pragma unroll
        for (int mt = 0; mt < 2; ++mt) {
            const int r = wm * 32 + mt * 16 + g;
            #pragma unroll
            for (int nt = 0; nt < 8; ++nt) {
                const int c = wn * 64 + nt * 8 + tg * 2;
                const float b0v = __ldg(&bo1[c]), b1v = __ldg(&bo1[c + 1]);
                float x0 = prelu_f(acc1[mt][nt][0] + b0v, a_out);
                float x1 = prelu_f(acc1[mt][nt][1] + b1v, a_out);
                float x2 = prelu_f(acc1[mt][nt][2] + b0v, a_out);
                float x3 = prelu_f(acc1[mt][nt][3] + b1v, a_out);
                store_split2(th, tl, (size_t)r * 264 + c, x0, x1);
                store_split2(th, tl, (size_t)(r + 8) * 264 + c, x2, x3);
            }
        }
        __syncthreads();
    }

    // ---- FFN2: out = t[64x256] @ Wo2 + bo2 ----
    {
        const int wm2 = wid & 1, wn2 = wid >> 1;  // 2M x 4N, warp 32x16
        float acc2[2][2][4];
        #pragma unroll
        for (int a = 0; a < 2; ++a)
            #pragma unroll
            for (int b = 0; b < 2; ++b)
                #pragma unroll
                for (int c = 0; c < 4; ++c) acc2[a][b][c] = 0.f;

        const uint32_t aoffH = sb + TH + (uint32_t)(wm2 * 32 + (lane & 15)) * 528
                             + (uint32_t)((lane >> 4) * 8) * 2;
        const uint32_t aoffL = aoffH + (TL - TH);
        const uint32_t boffH = sb + BB + (uint32_t)(wn2 * 16 + brow) * 144 + (uint32_t)bko * 2;
        const uint32_t boffL = boffH + 36864;

        for (int ch = 0; ch < 4; ++ch) {
            #pragma unroll
            for (int i = 0; i < 2; ++i) {
                int idx = i * 256 + tid;
                int r = idx >> 3, c8 = (idx & 7) << 3;
                *(uint4*)(smraw + BB + r * 144 + c8 * 2) =
                    *(const uint4*)(g_Wo2T_hi + (size_t)r * 256 + ch * 64 + c8);
                *(uint4*)(smraw + BB + 36864 + r * 144 + c8 * 2) =
                    *(const uint4*)(g_Wo2T_lo + (size_t)r * 256 + ch * 64 + c8);
            }
            __syncthreads();
            #pragma unroll
            for (int ks = 0; ks < 4; ++ks) {
                const int kglob = ch * 64 + ks * 16;
                uint32_t ah[2][4], al[2][4], bh[4], bl[4];
                ldsm4(ah[0], aoffH + kglob * 2);
                ldsm4(ah[1], aoffH + 16 * 528 + kglob * 2);
                ldsm4(al[0], aoffL + kglob * 2);
                ldsm4(al[1], aoffL + 16 * 528 + kglob * 2);
                ldsm4(bh, boffH + ks * 32);
                ldsm4(bl, boffL + ks * 32);
                #pragma unroll
                for (int mt = 0; mt < 2; ++mt) {
                    mma16816(acc2[mt][0], ah[mt], bh);
                    mma16816(acc2[mt][0], ah[mt], bl);
                    mma16816(acc2[mt][0], al[mt], bh);
                    mma16816(acc2[mt][1], ah[mt], bh + 2);
                    mma16816(acc2[mt][1], ah[mt], bl + 2);
                    mma16816(acc2[mt][1], al[mt], bh + 2);
                }
            }
            __syncthreads();
        }

        #pragma unroll
        for (int mt = 0; mt < 2; ++mt) {
            const int n = n0 + wm2 * 32 + mt * 16 + g;
            #pragma unroll
            for (int nt = 0; nt < 2; ++nt) {
                const int c = wn2 * 16 + nt * 8 + tg * 2;
                const float b0v = __ldg(&bo2[c]), b1v = __ldg(&bo2[c + 1]);
                if (n < N) {
                    float2 o = make_float2(acc2[mt][nt][0] + b0v, acc2[mt][nt][1] + b1v);
                    *(float2*)&out[(size_t)n * NCLS + c] = o;
                }
                if (n + 8 < N) {
                    float2 o = make_float2(acc2[mt][nt][2] + b0v, acc2[mt][nt][3] + b1v);
                    *(float2*)&out[(size_t)(n + 8) * NCLS + c] = o;
                }
            }
        }
    }
}

// ---------------------------------------------------------------------------
extern "C" void kernel_launch(void* const* d_in, const int* in_sizes, int n_in,
                              void* d_out, int out_size)
{
    const float* feats  = (const float*)d_in[0];
    const float* W_jk1  = (const float*)d_in[1];
    const float* b_jk1  = (const float*)d_in[2];
    const float* W_jk2  = (const float*)d_in[3];
    const float* b_jk2  = (const float*)d_in[4];
    const float* a_jk   = (const float*)d_in[5];
    const float* a_main = (const float*)d_in[6];
    const float* a_out  = (const float*)d_in[7];
    const float* w_ref  = (const float*)d_in[8];
    const float* w_x    = (const float*)d_in[9];
    const float* b_att  = (const float*)d_in[10];
    const float* W_o1   = (const float*)d_in[11];
    const float* b_o1   = (const float*)d_in[12];
    const float* W_o2   = (const float*)d_in[13];
    const float* b_o2   = (const float*)d_in[14];
    float* out = (float*)d_out;

    const int N = in_sizes[0] / (HOPS * FDIM);
    const int nb128 = (N + 127) / 128;
    const int nb64  = (N + 63) / 64;

    cudaFuncSetAttribute(k1_gemm, cudaFuncAttributeMaxDynamicSharedMemorySize, K1_SMEM);
    cudaFuncSetAttribute(k2_att,  cudaFuncAttributeMaxDynamicSharedMemorySize, K2_SMEM);
    cudaFuncSetAttribute(k3_out,  cudaFuncAttributeMaxDynamicSharedMemorySize, K3_SMEM);

    k0_convert<<<368, 1024>>>(W_jk1, W_jk2, W_o1, W_o2);
    k1_gemm<<<nb128, 512, K1_SMEM>>>(feats, w_x, b_jk1, a_jk, N);
    k2_att <<<nb128, 512, K2_SMEM>>>(b_jk2, a_main, w_ref, b_att, N);
    k3_out <<<nb64, 256, K3_SMEM>>>(feats, b_o1, a_out, b_o2, out, N);
}

// round 6
// speedup vs baseline: 2.6652x; 1.1227x over previous
#include <cuda_runtime.h>
#include <cuda_bf16.h>
#include <cstdint>

#define HOPS 8
#define FDIM 128
#define HID  256
#define NCLS 64
#define NMAX 100096

typedef unsigned long long ull;

// ---------------- scratch (device globals; no runtime alloc) ----------------
__device__ float g_sx[(size_t)NMAX * HOPS];
__device__ float g_w [(size_t)NMAX * HOPS];
__device__ __nv_bfloat16 g_agg_hi[(size_t)NMAX * FDIM];
__device__ __nv_bfloat16 g_agg_lo[(size_t)NMAX * FDIM];
__device__ __nv_bfloat16 g_W1T_hi[(size_t)HID * 1024];   // [c][k]
__device__ __nv_bfloat16 g_W1T_lo[(size_t)HID * 1024];
__device__ __nv_bfloat16 g_W2T_hi[(size_t)HID * HID];
__device__ __nv_bfloat16 g_W2T_lo[(size_t)HID * HID];
__device__ __nv_bfloat16 g_Wo1T_hi[(size_t)HID * FDIM];  // [c=256][k=128]
__device__ __nv_bfloat16 g_Wo1T_lo[(size_t)HID * FDIM];
__device__ __nv_bfloat16 g_Wo2T_hi[(size_t)NCLS * HID];  // [c=64][k=256]
__device__ __nv_bfloat16 g_Wo2T_lo[(size_t)NCLS * HID];

// ---------------- helpers ----------------
__device__ __forceinline__ uint32_t smem_u32(const void* p) {
    uint32_t a;
    asm("{ .reg .u64 t; cvta.to.shared.u64 t, %1; cvt.u32.u64 %0, t; }" : "=r"(a) : "l"(p));
    return a;
}
__device__ __forceinline__ void ldsm4(uint32_t* r, uint32_t addr) {
    asm volatile("ldmatrix.sync.aligned.m8n8.x4.shared.b16 {%0,%1,%2,%3}, [%4];"
        : "=r"(r[0]), "=r"(r[1]), "=r"(r[2]), "=r"(r[3]) : "r"(addr));
}
__device__ __forceinline__ void mma16816(float* c, const uint32_t* a, const uint32_t* b) {
    asm volatile("mma.sync.aligned.m16n8k16.row.col.f32.bf16.bf16.f32 "
        "{%0,%1,%2,%3}, {%4,%5,%6,%7}, {%8,%9}, {%0,%1,%2,%3};"
        : "+f"(c[0]), "+f"(c[1]), "+f"(c[2]), "+f"(c[3])
        : "r"(a[0]), "r"(a[1]), "r"(a[2]), "r"(a[3]), "r"(b[0]), "r"(b[1]));
}
#define CP_ASYNC16(dst, src) \
    asm volatile("cp.async.cg.shared.global [%0], [%1], 16;" :: "r"(dst), "l"(src))
#define CP_COMMIT() asm volatile("cp.async.commit_group;" ::: "memory")
#define CP_WAIT0()  asm volatile("cp.async.wait_group 0;" ::: "memory")

__device__ __forceinline__ float prelu_f(float v, float a) { return v >= 0.f ? v : a * v; }

union BfPair { uint32_t u; __nv_bfloat16 e[2]; };
union Bf4    { ull u;      __nv_bfloat16 e[4]; };
union Bf8    { uint4 q;    __nv_bfloat16 e[8]; };

__device__ __forceinline__ void store_split2(__nv_bfloat16* hi, __nv_bfloat16* lo,
                                             size_t base, float x0, float x1) {
    BfPair ph, pl;
    ph.e[0] = __float2bfloat16(x0);
    ph.e[1] = __float2bfloat16(x1);
    pl.e[0] = __float2bfloat16(x0 - __bfloat162float(ph.e[0]));
    pl.e[1] = __float2bfloat16(x1 - __bfloat162float(ph.e[1]));
    *(uint32_t*)&hi[base] = ph.u;
    *(uint32_t*)&lo[base] = pl.u;
}

// ---------------------------------------------------------------------------
// k0: transpose + bf16-split all four weight matrices
// ---------------------------------------------------------------------------
__global__ void k0_convert(const float* __restrict__ W1, const float* __restrict__ W2,
                           const float* __restrict__ Wo1, const float* __restrict__ Wo2)
{
    int idx = blockIdx.x * 1024 + threadIdx.x;
    float v; size_t dst; __nv_bfloat16* ph; __nv_bfloat16* pl;
    if (idx < 262144) {                       // W1 [1024][256]
        int k = idx >> 8, c = idx & 255;
        v = W1[idx]; dst = (size_t)c * 1024 + k; ph = g_W1T_hi; pl = g_W1T_lo;
    } else if (idx < 327680) {                // W2 [256][256]
        int i = idx - 262144, k = i >> 8, c = i & 255;
        v = W2[i]; dst = (size_t)c * 256 + k; ph = g_W2T_hi; pl = g_W2T_lo;
    } else if (idx < 360448) {                // Wo1 [128][256]
        int i = idx - 327680, k = i >> 8, c = i & 255;
        v = Wo1[i]; dst = (size_t)c * 128 + k; ph = g_Wo1T_hi; pl = g_Wo1T_lo;
    } else if (idx < 376832) {                // Wo2 [256][64]
        int i = idx - 360448, k = i >> 6, c = i & 63;
        v = Wo2[i]; dst = (size_t)c * 256 + k; ph = g_Wo2T_hi; pl = g_Wo2T_lo;
    } else return;
    __nv_bfloat16 h = __float2bfloat16(v);
    ph[dst] = h;
    pl[dst] = __float2bfloat16(v - __bfloat162float(h));
}

// ---------------------------------------------------------------------------
// k12 smem layout. Phase 1: two 110592B stages (A 128x64 hi/lo pitch 144,
// B 256x64 hi/lo pitch 144). Phase 2: H tile [128][264] hi/lo pitch 528
// overlaying stage memory, W2 B-chunk region after it. Extras at tail.
// ---------------------------------------------------------------------------
#define STG    110592
#define S_AH   0
#define S_AL   18432
#define S_BH   36864
#define S_BL   73728
#define HREG_H 0
#define HREG_L 67584
#define B2H    135168
#define B2L    172032
#define EX_WX   221184
#define EX_B1   221696
#define EX_B2   222720
#define EX_WR   223744
#define EX_SRED 224768
#define K12_SMEM 226816

// ---------------------------------------------------------------------------
// k12: fused  h = prelu(concat@W1+b1, a_jk)  (kept in smem, split bf16)
//             jk = prelu(h@W2+b2, a_main);  s_ref = jk.w_ref
//             g_w = softmax(sigmoid(s_x + s_ref + b_att));   plus fused s_x.
// 512 thr, BM=128. Phase 1 double-buffered with cp.async B + reg-staged A.
// ---------------------------------------------------------------------------
__global__ __launch_bounds__(512, 1) void k12(
    const float* __restrict__ feats, const float* __restrict__ wx,
    const float* __restrict__ b1, const float* __restrict__ a_jk_p,
    const float* __restrict__ b2, const float* __restrict__ a_main_p,
    const float* __restrict__ w_ref, const float* __restrict__ b_att_p, int N)
{
    extern __shared__ char smraw[];
    const uint32_t sb = smem_u32(smraw);
    const int tid = threadIdx.x, wid = tid >> 5, lane = tid & 31;
    const int n0 = blockIdx.x * 128;
    const int wm = wid & 3, wn = wid >> 2;          // 4M x 4N warps, tile 32x64
    const int g = lane >> 2, tg = lane & 3;

    float* wxs  = (float*)(smraw + EX_WX);
    float* sb1  = (float*)(smraw + EX_B1);
    float* sb2  = (float*)(smraw + EX_B2);
    float* swr  = (float*)(smraw + EX_WR);
    float* sred = (float*)(smraw + EX_SRED);
    if (tid < 128) wxs[tid] = wx[tid];
    else if (tid < 384) sb1[tid - 128] = b1[tid - 128];
    {
        int t2 = tid;
        if (t2 < 256) sb2[t2] = b2[t2];
        else if (t2 < 512) swr[t2 - 256] = w_ref[t2 - 256];
    }

    float acc[2][8][4];
    #pragma unroll
    for (int a = 0; a < 2; ++a)
        #pragma unroll
        for (int b = 0; b < 8; ++b)
            #pragma unroll
            for (int c = 0; c < 4; ++c) acc[a][b][c] = 0.f;

    // fragment addressing (stage-relative constants)
    const uint32_t aoff_c = (uint32_t)(wm * 32 + (lane & 15)) * 144
                          + (uint32_t)((lane >> 4) * 8) * 2;
    const int brow = (lane & 7) + ((lane >> 4) << 3);
    const int bko  = ((lane >> 3) & 1) * 8;
    const uint32_t boff_c = (uint32_t)(wn * 64 + brow) * 144 + (uint32_t)bko * 2;

    // A-load thread mapping
    const int lr = (tid >> 4);           // wait: recompute below per i
    (void)lr;

    // ---------------- Phase 1: 16 K-chunks of 64, double-buffered ----------------
    float4 areg[4];
    // prologue: chunk 0
    {
        const float* fb = feats + 0;  // hop 0, f0 0
        #pragma unroll
        for (int i = 0; i < 4; ++i) {
            int idx = i * 512 + tid;
            int r = idx >> 4, cq = (idx & 15) << 2;
            int n = n0 + r; if (n > N - 1) n = N - 1;
            areg[i] = *(const float4*)(fb + (size_t)n * FDIM + cq);
        }
        #pragma unroll
        for (int i = 0; i < 4; ++i) {
            int idx = i * 512 + tid;
            int r = idx >> 3, c8 = (idx & 7) << 3;
            CP_ASYNC16(sb + S_BH + r * 144 + c8 * 2,
                       g_W1T_hi + (size_t)r * 1024 + c8);
            CP_ASYNC16(sb + S_BL + r * 144 + c8 * 2,
                       g_W1T_lo + (size_t)r * 1024 + c8);
        }
        CP_COMMIT();
        #pragma unroll
        for (int i = 0; i < 4; ++i) {
            int idx = i * 512 + tid;
            int r = idx >> 4, cq = (idx & 15) << 2;
            Bf4 uh, ulo;
            float f[4] = {areg[i].x, areg[i].y, areg[i].z, areg[i].w};
            #pragma unroll
            for (int j = 0; j < 4; ++j) {
                __nv_bfloat16 h = __float2bfloat16(f[j]);
                uh.e[j]  = h;
                ulo.e[j] = __float2bfloat16(f[j] - __bfloat162float(h));
            }
            *(ull*)(smraw + S_AH + r * 144 + cq * 2) = uh.u;
            *(ull*)(smraw + S_AL + r * 144 + cq * 2) = ulo.u;
        }
    }

    float sx = 0.f;

    for (int chunk = 0; chunk < 16; ++chunk) {
        const int cur = chunk & 1;
        const uint32_t sbase = (uint32_t)cur * STG;
        const int hop = chunk >> 1, f0 = (chunk & 1) << 6;

        CP_WAIT0();
        __syncthreads();

        if (chunk < 15) {
            const int cn = chunk + 1;
            const uint32_t nbase = (uint32_t)(cn & 1) * STG;
            const int c0n = cn << 6;
            // kick B(next) cp.async
            #pragma unroll
            for (int i = 0; i < 4; ++i) {
                int idx = i * 512 + tid;
                int r = idx >> 3, c8 = (idx & 7) << 3;
                CP_ASYNC16(sb + nbase + S_BH + r * 144 + c8 * 2,
                           g_W1T_hi + (size_t)r * 1024 + c0n + c8);
                CP_ASYNC16(sb + nbase + S_BL + r * 144 + c8 * 2,
                           g_W1T_lo + (size_t)r * 1024 + c0n + c8);
            }
            CP_COMMIT();
            // kick A(next) LDG into regs
            const int hop_n = cn >> 1, f0_n = (cn & 1) << 6;
            const float* fbn = feats + (size_t)hop_n * N * FDIM + f0_n;
            #pragma unroll
            for (int i = 0; i < 4; ++i) {
                int idx = i * 512 + tid;
                int r = idx >> 4, cq = (idx & 15) << 2;
                int n = n0 + r; if (n > N - 1) n = N - 1;
                areg[i] = *(const float4*)(fbn + (size_t)n * FDIM + cq);
            }
        }

        if (tid < 128) {   // fused s_x for row tid
            const char* bh = smraw + sbase + S_AH + tid * 144;
            const char* bl = smraw + sbase + S_AL + tid * 144;
            #pragma unroll
            for (int i8 = 0; i8 < 8; ++i8) {
                Bf8 qh, ql;
                qh.q = *(const uint4*)(bh + i8 * 16);
                ql.q = *(const uint4*)(bl + i8 * 16);
                #pragma unroll
                for (int j = 0; j < 8; ++j)
                    sx += (__bfloat162float(qh.e[j]) + __bfloat162float(ql.e[j]))
                        * wxs[f0 + i8 * 8 + j];
            }
        }

        const uint32_t aH = sb + sbase + S_AH + aoff_c;
        const uint32_t aL = sb + sbase + S_AL + aoff_c;
        const uint32_t bH = sb + sbase + S_BH + boff_c;
        const uint32_t bL = sb + sbase + S_BL + boff_c;
        #pragma unroll
        for (int ks = 0; ks < 4; ++ks) {
            uint32_t ah[2][4], al[2][4];
            ldsm4(ah[0], aH + ks * 32);
            ldsm4(ah[1], aH + 16 * 144 + ks * 32);
            ldsm4(al[0], aL + ks * 32);
            ldsm4(al[1], aL + 16 * 144 + ks * 32);
            #pragma unroll
            for (int ntp = 0; ntp < 4; ++ntp) {
                uint32_t bhf[4], blf[4];
                ldsm4(bhf, bH + ntp * 16 * 144 + ks * 32);
                ldsm4(blf, bL + ntp * 16 * 144 + ks * 32);
                #pragma unroll
                for (int mt = 0; mt < 2; ++mt) {
                    mma16816(acc[mt][ntp * 2],     ah[mt], bhf);
                    mma16816(acc[mt][ntp * 2],     ah[mt], blf);
                    mma16816(acc[mt][ntp * 2],     al[mt], bhf);
                    mma16816(acc[mt][ntp * 2 + 1], ah[mt], bhf + 2);
                    mma16816(acc[mt][ntp * 2 + 1], ah[mt], blf + 2);
                    mma16816(acc[mt][ntp * 2 + 1], al[mt], bhf + 2);
                }
            }
        }

        if (chunk < 15) {   // convert + store A(next) into next stage
            const uint32_t nbase = (uint32_t)((chunk + 1) & 1) * STG;
            #pragma unroll
            for (int i = 0; i < 4; ++i) {
                int idx = i * 512 + tid;
                int r = idx >> 4, cq = (idx & 15) << 2;
                Bf4 uh, ulo;
                float f[4] = {areg[i].x, areg[i].y, areg[i].z, areg[i].w};
                #pragma unroll
                for (int j = 0; j < 4; ++j) {
                    __nv_bfloat16 h = __float2bfloat16(f[j]);
                    uh.e[j]  = h;
                    ulo.e[j] = __float2bfloat16(f[j] - __bfloat162float(h));
                }
                *(ull*)(smraw + nbase + S_AH + r * 144 + cq * 2) = uh.u;
                *(ull*)(smraw + nbase + S_AL + r * 144 + cq * 2) = ulo.u;
            }
        }

        if ((chunk & 1) && tid < 128) {
            if (n0 + tid < N) g_sx[(size_t)(n0 + tid) * HOPS + hop] = sx;
            sx = 0.f;
        }
    }
    __syncthreads();

    // ---------------- epilogue 1: bias + prelu -> H split tile in smem ----------------
    {
        const float a_jk = *a_jk_p;
        __nv_bfloat16* hh = (__nv_bfloat16*)(smraw + HREG_H);
        __nv_bfloat16* hl = (__nv_bfloat16*)(smraw + HREG_L);
        #pragma unroll
        for (int mt = 0; mt < 2; ++mt) {
            const int r = wm * 32 + mt * 16 + g;
            #pragma unroll
            for (int nt = 0; nt < 8; ++nt) {
                const int c = wn * 64 + nt * 8 + tg * 2;
                const float b0v = sb1[c], b1v = sb1[c + 1];
                float x0 = prelu_f(acc[mt][nt][0] + b0v, a_jk);
                float x1 = prelu_f(acc[mt][nt][1] + b1v, a_jk);
                float x2 = prelu_f(acc[mt][nt][2] + b0v, a_jk);
                float x3 = prelu_f(acc[mt][nt][3] + b1v, a_jk);
                store_split2(hh, hl, (size_t)r * 264 + c, x0, x1);
                store_split2(hh, hl, (size_t)(r + 8) * 264 + c, x2, x3);
            }
        }
    }

    // zero accumulators for phase 2
    #pragma unroll
    for (int a = 0; a < 2; ++a)
        #pragma unroll
        for (int b = 0; b < 8; ++b)
            #pragma unroll
            for (int c = 0; c < 4; ++c) acc[a][b][c] = 0.f;

    // ---------------- Phase 2: jk = H @ W2, K=256 in 4 chunks ----------------
    const uint32_t a2H = sb + HREG_H + (uint32_t)(wm * 32 + (lane & 15)) * 528
                       + (uint32_t)((lane >> 4) * 8) * 2;
    const uint32_t a2L = a2H + (HREG_L - HREG_H);
    const uint32_t b2Hf = sb + B2H + boff_c;
    const uint32_t b2Lf = b2Hf + (B2L - B2H);

    for (int c2 = 0; c2 < 4; ++c2) {
        __syncthreads();   // H stores visible (c2=0) / prior MMA done before B2 overwrite
        const int c0 = c2 << 6;
        #pragma unroll
        for (int i = 0; i < 4; ++i) {
            int idx = i * 512 + tid;
            int r = idx >> 3, c8 = (idx & 7) << 3;
            CP_ASYNC16(sb + B2H + r * 144 + c8 * 2,
                       g_W2T_hi + (size_t)r * 256 + c0 + c8);
            CP_ASYNC16(sb + B2L + r * 144 + c8 * 2,
                       g_W2T_lo + (size_t)r * 256 + c0 + c8);
        }
        CP_COMMIT();
        CP_WAIT0();
        __syncthreads();

        #pragma unroll
        for (int ks = 0; ks < 4; ++ks) {
            const uint32_t ko = (uint32_t)(c0 + ks * 16) * 2;
            uint32_t ah[2][4], al[2][4];
            ldsm4(ah[0], a2H + ko);
            ldsm4(ah[1], a2H + 16 * 528 + ko);
            ldsm4(al[0], a2L + ko);
            ldsm4(al[1], a2L + 16 * 528 + ko);
            #pragma unroll
            for (int ntp = 0; ntp < 4; ++ntp) {
                uint32_t bhf[4], blf[4];
                ldsm4(bhf, b2Hf + ntp * 16 * 144 + ks * 32);
                ldsm4(blf, b2Lf + ntp * 16 * 144 + ks * 32);
                #pragma unroll
                for (int mt = 0; mt < 2; ++mt) {
                    mma16816(acc[mt][ntp * 2],     ah[mt], bhf);
                    mma16816(acc[mt][ntp * 2],     ah[mt], blf);
                    mma16816(acc[mt][ntp * 2],     al[mt], bhf);
                    mma16816(acc[mt][ntp * 2 + 1], ah[mt], bhf + 2);
                    mma16816(acc[mt][ntp * 2 + 1], ah[mt], blf + 2);
                    mma16816(acc[mt][ntp * 2 + 1], al[mt], bhf + 2);
                }
            }
        }
    }

    // ---------------- epilogue 2: prelu -> dot(w_ref) -> softmax(sigmoid) ----------------
    const float a_main = *a_main_p;
    float part[2][2] = {{0.f, 0.f}, {0.f, 0.f}};
    #pragma unroll
    for (int mt = 0; mt < 2; ++mt) {
        #pragma unroll
        for (int nt = 0; nt < 8; ++nt) {
            const int c = wn * 64 + nt * 8 + tg * 2;
            const float w0 = swr[c], w1 = swr[c + 1];
            const float bb0 = sb2[c], bb1 = sb2[c + 1];
            part[mt][0] += prelu_f(acc[mt][nt][0] + bb0, a_main) * w0
                         + prelu_f(acc[mt][nt][1] + bb1, a_main) * w1;
            part[mt][1] += prelu_f(acc[mt][nt][2] + bb0, a_main) * w0
                         + prelu_f(acc[mt][nt][3] + bb1, a_main) * w1;
        }
    }
    #pragma unroll
    for (int mt = 0; mt < 2; ++mt)
        #pragma unroll
        for (int h = 0; h < 2; ++h) {
            part[mt][h] += __shfl_xor_sync(0xffffffffu, part[mt][h], 1);
            part[mt][h] += __shfl_xor_sync(0xffffffffu, part[mt][h], 2);
        }
    __syncthreads();
    if (tg == 0) {
        #pragma unroll
        for (int mt = 0; mt < 2; ++mt) {
            const int r = wm * 32 + mt * 16 + g;
            sred[r * 4 + wn]       = part[mt][0];
            sred[(r + 8) * 4 + wn] = part[mt][1];
        }
    }
    __syncthreads();

    if (tid < 128) {
        const int n = n0 + tid;
        if (n < N) {
            const float sref = sred[tid * 4] + sred[tid * 4 + 1]
                             + sred[tid * 4 + 2] + sred[tid * 4 + 3] + *b_att_p;
            const float* sxp = g_sx + (size_t)n * HOPS;
            float s[HOPS];
            float m = -1e30f;
            #pragma unroll
            for (int h = 0; h < HOPS; ++h) {
                float z = sxp[h] + sref;
                s[h] = 1.f / (1.f + expf(-z));
                m = fmaxf(m, s[h]);
            }
            float sum = 0.f;
            #pragma unroll
            for (int h = 0; h < HOPS; ++h) { s[h] = expf(s[h] - m); sum += s[h]; }
            const float inv = 1.f / sum;
            float* d = g_w + (size_t)n * HOPS;
            *(float4*)(d + 0) = make_float4(s[0] * inv, s[1] * inv, s[2] * inv, s[3] * inv);
            *(float4*)(d + 4) = make_float4(s[4] * inv, s[5] * inv, s[6] * inv, s[7] * inv);
        }
    }
}

// ---------------------------------------------------------------------------
// k3a: agg[n][f] = sum_h g_w[n][h] * feats[h][n][f]  -> split bf16 global.
// One thread per (node, 4 features). MLP=8 independent LDG.128 per thread.
// ---------------------------------------------------------------------------
__global__ __launch_bounds__(256) void k3a_agg(const float* __restrict__ feats, int N)
{
    int idx = blockIdx.x * 256 + threadIdx.x;
    if (idx >= N * 32) return;
    const int n = idx >> 5, f = (idx & 31) << 2;

    float4 w0 = *(const float4*)(g_w + (size_t)n * HOPS);
    float4 w1 = *(const float4*)(g_w + (size_t)n * HOPS + 4);
    const float wv[8] = {w0.x, w0.y, w0.z, w0.w, w1.x, w1.y, w1.z, w1.w};

    float ax = 0.f, ay = 0.f, az = 0.f, aw = 0.f;
    #pragma unroll
    for (int hop = 0; hop < HOPS; ++hop) {
        const float4 v = *(const float4*)(feats + (size_t)hop * N * FDIM
                                                + (size_t)n * FDIM + f);
        ax += wv[hop] * v.x; ay += wv[hop] * v.y;
        az += wv[hop] * v.z; aw += wv[hop] * v.w;
    }
    Bf4 uh, ulo;
    float fv[4] = {ax, ay, az, aw};
    #pragma unroll
    for (int j = 0; j < 4; ++j) {
        __nv_bfloat16 h = __float2bfloat16(fv[j]);
        uh.e[j]  = h;
        ulo.e[j] = __float2bfloat16(fv[j] - __bfloat162float(h));
    }
    *(ull*)(g_agg_hi + (size_t)n * FDIM + f) = uh.u;
    *(ull*)(g_agg_lo + (size_t)n * FDIM + f) = ulo.u;
}

// ---------------------------------------------------------------------------
// k3b: out = prelu(agg@Wo1+bo1, a_out) @ Wo2 + bo2.  256 thr, BM=64.
// ---------------------------------------------------------------------------
#define AGH 0
#define AGL 17408
#define BB  34816
#define TH  108544
#define TL  142336
#define K3_SMEM 176128

__global__ __launch_bounds__(256, 1) void k3b_out(
    const float* __restrict__ bo1, const float* __restrict__ a_out_p,
    const float* __restrict__ bo2, float* __restrict__ out, int N)
{
    extern __shared__ char smraw[];
    const uint32_t sb = smem_u32(smraw);
    const int tid = threadIdx.x, wid = tid >> 5, lane = tid & 31;
    const int n0 = blockIdx.x * 64;
    const int g = lane >> 2, tg = lane & 3;

    // ---- load agg tile (already split bf16) via cp.async ----
    #pragma unroll
    for (int i = 0; i < 4; ++i) {
        int idx = i * 256 + tid;
        int r = idx >> 4, c8 = (idx & 15) << 3;
        int n = n0 + r; if (n > N - 1) n = N - 1;
        CP_ASYNC16(sb + AGH + r * 272 + c8 * 2, g_agg_hi + (size_t)n * FDIM + c8);
        CP_ASYNC16(sb + AGL + r * 272 + c8 * 2, g_agg_lo + (size_t)n * FDIM + c8);
    }
    CP_COMMIT();

    const int brow = (lane & 7) + ((lane >> 4) << 3);
    const int bko  = ((lane >> 3) & 1) * 8;

    // ---- FFN1: t = prelu(agg[64x128] @ Wo1 + bo1) -> split smem (pitch 528B) ----
    {
        const int wm = wid & 1, wn = wid >> 1;   // 2M x 4N, warp 32x64
        float acc1[2][8][4];
        #pragma unroll
        for (int a = 0; a < 2; ++a)
            #pragma unroll
            for (int b = 0; b < 8; ++b)
                #pragma unroll
                for (int c = 0; c < 4; ++c) acc1[a][b][c] = 0.f;

        const uint32_t aoffH = sb + AGH + (uint32_t)(wm * 32 + (lane & 15)) * 272
                             + (uint32_t)((lane >> 4) * 8) * 2;
        const uint32_t aoffL = aoffH + (AGL - AGH);
        const uint32_t boffH = sb + BB + (uint32_t)(wn * 64 + brow) * 144 + (uint32_t)bko * 2;
        const uint32_t boffL = boffH + 36864;

        for (int cb = 0; cb < 2; ++cb) {
            if (cb) __syncthreads();
            #pragma unroll
            for (int i = 0; i < 8; ++i) {
                int idx = i * 256 + tid;
                int r = idx >> 3, c8 = (idx & 7) << 3;
                CP_ASYNC16(sb + BB + r * 144 + c8 * 2,
                           g_Wo1T_hi + (size_t)r * 128 + cb * 64 + c8);
                CP_ASYNC16(sb + BB + 36864 + r * 144 + c8 * 2,
                           g_Wo1T_lo + (size_t)r * 128 + cb * 64 + c8);
            }
            CP_COMMIT();
            CP_WAIT0();
            __syncthreads();
            #pragma unroll
            for (int ks = 0; ks < 4; ++ks) {
                const int kglob = cb * 64 + ks * 16;
                uint32_t ah[2][4], al[2][4];
                ldsm4(ah[0], aoffH + kglob * 2);
                ldsm4(ah[1], aoffH + 16 * 272 + kglob * 2);
                ldsm4(al[0], aoffL + kglob * 2);
                ldsm4(al[1], aoffL + 16 * 272 + kglob * 2);
                #pragma unroll
                for (int ntp = 0; ntp < 4; ++ntp) {
                    uint32_t bh[4], bl[4];
                    ldsm4(bh, boffH + ntp * 16 * 144 + ks * 32);
                    ldsm4(bl, boffL + ntp * 16 * 144 + ks * 32);
                    #pragma unroll
                    for (int mt = 0; mt < 2; ++mt) {
                        mma16816(acc1[mt][ntp * 2],     ah[mt], bh);
                        mma16816(acc1[mt][ntp * 2],     ah[mt], bl);
                        mma16816(acc1[mt][ntp * 2],     al[mt], bh);
                        mma16816(acc1[mt][ntp * 2 + 1], ah[mt], bh + 2);
                        mma16816(acc1[mt][ntp * 2 + 1], ah[mt], bl + 2);
                        mma16816(acc1[mt][ntp * 2 + 1], al[mt], bh + 2);
                    }
                }
            }
        }
        __syncthreads();

        const float a_out = *a_out_p;
        __nv_bfloat16* th = (__nv_bfloat16*)(smraw + TH);
        __nv_bfloat16* tl = (__nv_bfloat16*)(smraw + TL);
        #pragma unroll
        for (int mt = 0; mt < 2; ++mt) {
            const int r = wm * 32 + mt * 16 + g;
            #pragma unroll
            for (int nt = 0; nt < 8; ++nt) {
                const int c = wn * 64 + nt * 8 + tg * 2;
                const float b0v = __ldg(&bo1[c]), b1v = __ldg(&bo1[c + 1]);
                float x0 = prelu_f(acc1[mt][nt][0] + b0v, a_out);
                float x1 = prelu_f(acc1[mt][nt][1] + b1v, a_out);
                float x2 = prelu_f(acc1[mt][nt][2] + b0v, a_out);
                float x3 = prelu_f(acc1[mt][nt][3] + b1v, a_out);
                store_split2(th, tl, (size_t)r * 264 + c, x0, x1);
                store_split2(th, tl, (size_t)(r + 8) * 264 + c, x2, x3);
            }
        }
        __syncthreads();
    }

    // ---- FFN2: out = t[64x256] @ Wo2 + bo2 ----
    {
        const int wm2 = wid & 1, wn2 = wid >> 1;  // 2M x 4N, warp 32x16
        float acc2[2][2][4];
        #pragma unroll
        for (int a = 0; a < 2; ++a)
            #pragma unroll
            for (int b = 0; b < 2; ++b)
                #pragma unroll
                for (int c = 0; c < 4; ++c) acc2[a][b][c] = 0.f;

        const uint32_t aoffH = sb + TH + (uint32_t)(wm2 * 32 + (lane & 15)) * 528
                             + (uint32_t)((lane >> 4) * 8) * 2;
        const uint32_t aoffL = aoffH + (TL - TH);
        const uint32_t boffH = sb + BB + (uint32_t)(wn2 * 16 + brow) * 144 + (uint32_t)bko * 2;
        const uint32_t boffL = boffH + 36864;

        for (int ch = 0; ch < 4; ++ch) {
            __syncthreads();
            #pragma unroll
            for (int i = 0; i < 2; ++i) {
                int idx = i * 256 + tid;
                int r = idx >> 3, c8 = (idx & 7) << 3;
                CP_ASYNC16(sb + BB + r * 144 + c8 * 2,
                           g_Wo2T_hi + (size_t)r * 256 + ch * 64 + c8);
                CP_ASYNC16(sb + BB + 36864 + r * 144 + c8 * 2,
                           g_Wo2T_lo + (size_t)r * 256 + ch * 64 + c8);
            }
            CP_COMMIT();
            CP_WAIT0();
            __syncthreads();
            #pragma unroll
            for (int ks = 0; ks < 4; ++ks) {
                const int kglob = ch * 64 + ks * 16;
                uint32_t ah[2][4], al[2][4], bh[4], bl[4];
                ldsm4(ah[0], aoffH + kglob * 2);
                ldsm4(ah[1], aoffH + 16 * 528 + kglob * 2);
                ldsm4(al[0], aoffL + kglob * 2);
                ldsm4(al[1], aoffL + 16 * 528 + kglob * 2);
                ldsm4(bh, boffH + ks * 32);
                ldsm4(bl, boffL + ks * 32);
                #pragma unroll
                for (int mt = 0; mt < 2; ++mt) {
                    mma16816(acc2[mt][0], ah[mt], bh);
                    mma16816(acc2[mt][0], ah[mt], bl);
                    mma16816(acc2[mt][0], al[mt], bh);
                    mma16816(acc2[mt][1], ah[mt], bh + 2);
                    mma16816(acc2[mt][1], ah[mt], bl + 2);
                    mma16816(acc2[mt][1], al[mt], bh + 2);
                }
            }
        }

        #pragma unroll
        for (int mt = 0; mt < 2; ++mt) {
            const int n = n0 + wm2 * 32 + mt * 16 + g;
            #pragma unroll
            for (int nt = 0; nt < 2; ++nt) {
                const int c = wn2 * 16 + nt * 8 + tg * 2;
                const float b0v = __ldg(&bo2[c]), b1v = __ldg(&bo2[c + 1]);
                if (n < N) {
                    float2 o = make_float2(acc2[mt][nt][0] + b0v, acc2[mt][nt][1] + b1v);
                    *(float2*)&out[(size_t)n * NCLS + c] = o;
                }
                if (n + 8 < N) {
                    float2 o = make_float2(acc2[mt][nt][2] + b0v, acc2[mt][nt][3] + b1v);
                    *(float2*)&out[(size_t)(n + 8) * NCLS + c] = o;
                }
            }
        }
    }
}

// ---------------------------------------------------------------------------
extern "C" void kernel_launch(void* const* d_in, const int* in_sizes, int n_in,
                              void* d_out, int out_size)
{
    const float* feats  = (const float*)d_in[0];
    const float* W_jk1  = (const float*)d_in[1];
    const float* b_jk1  = (const float*)d_in[2];
    const float* W_jk2  = (const float*)d_in[3];
    const float* b_jk2  = (const float*)d_in[4];
    const float* a_jk   = (const float*)d_in[5];
    const float* a_main = (const float*)d_in[6];
    const float* a_out  = (const float*)d_in[7];
    const float* w_ref  = (const float*)d_in[8];
    const float* w_x    = (const float*)d_in[9];
    const float* b_att  = (const float*)d_in[10];
    const float* W_o1   = (const float*)d_in[11];
    const float* b_o1   = (const float*)d_in[12];
    const float* W_o2   = (const float*)d_in[13];
    const float* b_o2   = (const float*)d_in[14];
    float* out = (float*)d_out;

    const int N = in_sizes[0] / (HOPS * FDIM);
    const int nb128 = (N + 127) / 128;
    const int nb64  = (N + 63) / 64;

    cudaFuncSetAttribute(k12,     cudaFuncAttributeMaxDynamicSharedMemorySize, K12_SMEM);
    cudaFuncSetAttribute(k3b_out, cudaFuncAttributeMaxDynamicSharedMemorySize, K3_SMEM);

    k0_convert<<<368, 1024>>>(W_jk1, W_jk2, W_o1, W_o2);
    k12<<<nb128, 512, K12_SMEM>>>(feats, w_x, b_jk1, a_jk, b_jk2, a_main,
                                  w_ref, b_att, N);
    k3a_agg<<<(N * 32 + 255) / 256, 256>>>(feats, N);
    k3b_out<<<nb64, 256, K3_SMEM>>>(b_o1, a_out, b_o2, out, N);
}

// round 7
// speedup vs baseline: 4.5821x; 1.7192x over previous
#include <cuda_runtime.h>
#include <cuda_bf16.h>
#include <cstdint>

#define HOPS 8
#define FDIM 128
#define HID  256
#define NCLS 64
#define NMAX 100096

typedef unsigned long long ull;

// ---------------- scratch (device globals; no runtime alloc) ----------------
__device__ float g_sx[(size_t)NMAX * HOPS];
__device__ float g_w [(size_t)NMAX * HOPS];
__device__ __nv_bfloat16 g_agg_hi[(size_t)NMAX * FDIM];
__device__ __nv_bfloat16 g_agg_lo[(size_t)NMAX * FDIM];
__device__ __nv_bfloat16 g_W1T_hi[(size_t)HID * 1024];   // [c][k]
__device__ __nv_bfloat16 g_W2T_hi[(size_t)HID * HID];
__device__ __nv_bfloat16 g_Wo1T_hi[(size_t)HID * FDIM];  // [c=256][k=128]
__device__ __nv_bfloat16 g_Wo1T_lo[(size_t)HID * FDIM];
__device__ __nv_bfloat16 g_Wo2T_hi[(size_t)NCLS * HID];  // [c=64][k=256]
__device__ __nv_bfloat16 g_Wo2T_lo[(size_t)NCLS * HID];

// ---------------- helpers ----------------
__device__ __forceinline__ uint32_t smem_u32(const void* p) {
    uint32_t a;
    asm("{ .reg .u64 t; cvta.to.shared.u64 t, %1; cvt.u32.u64 %0, t; }" : "=r"(a) : "l"(p));
    return a;
}
__device__ __forceinline__ void ldsm4(uint32_t* r, uint32_t addr) {
    asm volatile("ldmatrix.sync.aligned.m8n8.x4.shared.b16 {%0,%1,%2,%3}, [%4];"
        : "=r"(r[0]), "=r"(r[1]), "=r"(r[2]), "=r"(r[3]) : "r"(addr));
}
__device__ __forceinline__ void ldsm2(uint32_t* r, uint32_t addr) {
    asm volatile("ldmatrix.sync.aligned.m8n8.x2.shared.b16 {%0,%1}, [%2];"
        : "=r"(r[0]), "=r"(r[1]) : "r"(addr));
}
__device__ __forceinline__ void mma16816(float* c, const uint32_t* a, const uint32_t* b) {
    asm volatile("mma.sync.aligned.m16n8k16.row.col.f32.bf16.bf16.f32 "
        "{%0,%1,%2,%3}, {%4,%5,%6,%7}, {%8,%9}, {%0,%1,%2,%3};"
        : "+f"(c[0]), "+f"(c[1]), "+f"(c[2]), "+f"(c[3])
        : "r"(a[0]), "r"(a[1]), "r"(a[2]), "r"(a[3]), "r"(b[0]), "r"(b[1]));
}
#define CP_ASYNC16(dst, src) \
    asm volatile("cp.async.cg.shared.global [%0], [%1], 16;" :: "r"(dst), "l"(src))
#define CP_COMMIT() asm volatile("cp.async.commit_group;" ::: "memory")
#define CP_WAIT0()  asm volatile("cp.async.wait_group 0;" ::: "memory")

__device__ __forceinline__ float prelu_f(float v, float a) { return v >= 0.f ? v : a * v; }

union BfPair { uint32_t u; __nv_bfloat16 e[2]; };
union Bf8    { uint4 q;    __nv_bfloat16 e[8]; };

__device__ __forceinline__ uint32_t pack_bf16x2(float x0, float x1) {
    BfPair p;
    p.e[0] = __float2bfloat16(x0);
    p.e[1] = __float2bfloat16(x1);
    return p.u;
}
__device__ __forceinline__ void store_split2(__nv_bfloat16* hi, __nv_bfloat16* lo,
                                             size_t base, float x0, float x1) {
    BfPair ph, pl;
    ph.e[0] = __float2bfloat16(x0);
    ph.e[1] = __float2bfloat16(x1);
    pl.e[0] = __float2bfloat16(x0 - __bfloat162float(ph.e[0]));
    pl.e[1] = __float2bfloat16(x1 - __bfloat162float(ph.e[1]));
    *(uint32_t*)&hi[base] = ph.u;
    *(uint32_t*)&lo[base] = pl.u;
}

// ---------------------------------------------------------------------------
// k0: transpose weights. W1/W2 -> bf16 hi only (attention path).
//     Wo1/Wo2 -> split hi/lo (output path, 3-pass).
// ---------------------------------------------------------------------------
__global__ void k0_convert(const float* __restrict__ W1, const float* __restrict__ W2,
                           const float* __restrict__ Wo1, const float* __restrict__ Wo2)
{
    int idx = blockIdx.x * 1024 + threadIdx.x;
    if (idx < 262144) {                       // W1 [1024][256] hi only
        int k = idx >> 8, c = idx & 255;
        g_W1T_hi[(size_t)c * 1024 + k] = __float2bfloat16(W1[idx]);
        return;
    }
    if (idx < 327680) {                       // W2 [256][256] hi only
        int i = idx - 262144, k = i >> 8, c = i & 255;
        g_W2T_hi[(size_t)c * 256 + k] = __float2bfloat16(W2[i]);
        return;
    }
    float v; size_t dst; __nv_bfloat16* ph; __nv_bfloat16* pl;
    if (idx < 360448) {                       // Wo1 [128][256] split
        int i = idx - 327680, k = i >> 8, c = i & 255;
        v = Wo1[i]; dst = (size_t)c * 128 + k; ph = g_Wo1T_hi; pl = g_Wo1T_lo;
    } else if (idx < 376832) {                // Wo2 [256][64] split
        int i = idx - 360448, k = i >> 6, c = i & 63;
        v = Wo2[i]; dst = (size_t)c * 256 + k; ph = g_Wo2T_hi; pl = g_Wo2T_lo;
    } else return;
    __nv_bfloat16 h = __float2bfloat16(v);
    ph[dst] = h;
    pl[dst] = __float2bfloat16(v - __bfloat162float(h));
}

// ---------------------------------------------------------------------------
// k12 smem layout (1-pass bf16). Stage = A[128][64] (pitch 144) + B[256][64]:
// 18432 + 36864 = 55296, two stages. Phase 2: H[128][264] bf16 (pitch 528)
// at 0, W2 B-chunk at 67584. Extras at 110592.
// ---------------------------------------------------------------------------
#define STG    55296
#define S_AH   0
#define S_BH   18432
#define HREG   0
#define B2H    67584
#define EX_WX   110592
#define EX_B1   111104
#define EX_B2   112128
#define EX_WR   113152
#define EX_SRED 114176
#define K12_SMEM 116224

__global__ __launch_bounds__(512, 1) void k12(
    const float* __restrict__ feats, const float* __restrict__ wx,
    const float* __restrict__ b1, const float* __restrict__ a_jk_p,
    const float* __restrict__ b2, const float* __restrict__ a_main_p,
    const float* __restrict__ w_ref, const float* __restrict__ b_att_p, int N)
{
    extern __shared__ char smraw[];
    const uint32_t sb = smem_u32(smraw);
    const int tid = threadIdx.x, wid = tid >> 5, lane = tid & 31;
    const int n0 = blockIdx.x * 128;
    const int wm = wid & 3, wn = wid >> 2;          // 4M x 4N warps, tile 32x64
    const int g = lane >> 2, tg = lane & 3;

    float* wxs  = (float*)(smraw + EX_WX);
    float* sb1  = (float*)(smraw + EX_B1);
    float* sb2  = (float*)(smraw + EX_B2);
    float* swr  = (float*)(smraw + EX_WR);
    float* sred = (float*)(smraw + EX_SRED);
    if (tid < 128) wxs[tid] = wx[tid];
    else if (tid < 384) sb1[tid - 128] = b1[tid - 128];
    if (tid < 256) sb2[tid] = b2[tid];
    else swr[tid - 256] = w_ref[tid - 256];

    float acc[2][8][4];
    #pragma unroll
    for (int a = 0; a < 2; ++a)
        #pragma unroll
        for (int b = 0; b < 8; ++b)
            #pragma unroll
            for (int c = 0; c < 4; ++c) acc[a][b][c] = 0.f;

    const uint32_t aoff_c = (uint32_t)(wm * 32 + (lane & 15)) * 144
                          + (uint32_t)((lane >> 4) * 8) * 2;
    const int brow = (lane & 7) + ((lane >> 4) << 3);
    const int bko  = ((lane >> 3) & 1) * 8;
    const uint32_t boff_c = (uint32_t)(wn * 64 + brow) * 144 + (uint32_t)bko * 2;

    // ---------------- Phase 1: 16 K-chunks of 64, double-buffered ----------------
    float4 areg[4];
    {   // prologue: chunk 0
        #pragma unroll
        for (int i = 0; i < 4; ++i) {
            int idx = i * 512 + tid;
            int r = idx >> 4, cq = (idx & 15) << 2;
            int n = n0 + r; if (n > N - 1) n = N - 1;
            areg[i] = *(const float4*)(feats + (size_t)n * FDIM + cq);
        }
        #pragma unroll
        for (int i = 0; i < 4; ++i) {
            int idx = i * 512 + tid;
            int r = idx >> 3, c8 = (idx & 7) << 3;
            CP_ASYNC16(sb + S_BH + r * 144 + c8 * 2, g_W1T_hi + (size_t)r * 1024 + c8);
        }
        CP_COMMIT();
        #pragma unroll
        for (int i = 0; i < 4; ++i) {
            int idx = i * 512 + tid;
            int r = idx >> 4, cq = (idx & 15) << 2;
            ull u = (ull)pack_bf16x2(areg[i].x, areg[i].y)
                  | ((ull)pack_bf16x2(areg[i].z, areg[i].w) << 32);
            *(ull*)(smraw + S_AH + r * 144 + cq * 2) = u;
        }
    }

    float sx0 = 0.f, sx1 = 0.f, sx2 = 0.f, sx3 = 0.f;

    for (int chunk = 0; chunk < 16; ++chunk) {
        const uint32_t sbase = (uint32_t)(chunk & 1) * STG;
        const int hop = chunk >> 1, f0 = (chunk & 1) << 6;

        CP_WAIT0();
        __syncthreads();

        if (chunk < 15) {
            const int cn = chunk + 1;
            const uint32_t nbase = (uint32_t)(cn & 1) * STG;
            const int c0n = cn << 6;
            #pragma unroll
            for (int i = 0; i < 4; ++i) {
                int idx = i * 512 + tid;
                int r = idx >> 3, c8 = (idx & 7) << 3;
                CP_ASYNC16(sb + nbase + S_BH + r * 144 + c8 * 2,
                           g_W1T_hi + (size_t)r * 1024 + c0n + c8);
            }
            CP_COMMIT();
            const int hop_n = cn >> 1, f0_n = (cn & 1) << 6;
            const float* fbn = feats + (size_t)hop_n * N * FDIM + f0_n;
            #pragma unroll
            for (int i = 0; i < 4; ++i) {
                int idx = i * 512 + tid;
                int r = idx >> 4, cq = (idx & 15) << 2;
                int n = n0 + r; if (n > N - 1) n = N - 1;
                areg[i] = *(const float4*)(fbn + (size_t)n * FDIM + cq);
            }
        }

        if (tid < 128) {   // fused s_x for row tid (bf16 hi precision — safe)
            const char* bh = smraw + sbase + S_AH + tid * 144;
            #pragma unroll
            for (int i8 = 0; i8 < 8; ++i8) {
                Bf8 qh;
                qh.q = *(const uint4*)(bh + i8 * 16);
                const float* wp = wxs + f0 + i8 * 8;
                sx0 += __bfloat162float(qh.e[0]) * wp[0] + __bfloat162float(qh.e[4]) * wp[4];
                sx1 += __bfloat162float(qh.e[1]) * wp[1] + __bfloat162float(qh.e[5]) * wp[5];
                sx2 += __bfloat162float(qh.e[2]) * wp[2] + __bfloat162float(qh.e[6]) * wp[6];
                sx3 += __bfloat162float(qh.e[3]) * wp[3] + __bfloat162float(qh.e[7]) * wp[7];
            }
        }

        const uint32_t aH = sb + sbase + S_AH + aoff_c;
        const uint32_t bH = sb + sbase + S_BH + boff_c;
        #pragma unroll
        for (int ks = 0; ks < 4; ++ks) {
            uint32_t ah[2][4];
            ldsm4(ah[0], aH + ks * 32);
            ldsm4(ah[1], aH + 16 * 144 + ks * 32);
            #pragma unroll
            for (int ntp = 0; ntp < 4; ++ntp) {
                uint32_t bhf[4];
                ldsm4(bhf, bH + ntp * 16 * 144 + ks * 32);
                #pragma unroll
                for (int mt = 0; mt < 2; ++mt) {
                    mma16816(acc[mt][ntp * 2],     ah[mt], bhf);
                    mma16816(acc[mt][ntp * 2 + 1], ah[mt], bhf + 2);
                }
            }
        }

        if (chunk < 15) {   // convert + store A(next) into next stage
            const uint32_t nbase = (uint32_t)((chunk + 1) & 1) * STG;
            #pragma unroll
            for (int i = 0; i < 4; ++i) {
                int idx = i * 512 + tid;
                int r = idx >> 4, cq = (idx & 15) << 2;
                ull u = (ull)pack_bf16x2(areg[i].x, areg[i].y)
                      | ((ull)pack_bf16x2(areg[i].z, areg[i].w) << 32);
                *(ull*)(smraw + nbase + S_AH + r * 144 + cq * 2) = u;
            }
        }

        if ((chunk & 1) && tid < 128) {
            if (n0 + tid < N)
                g_sx[(size_t)(n0 + tid) * HOPS + hop] = (sx0 + sx1) + (sx2 + sx3);
            sx0 = sx1 = sx2 = sx3 = 0.f;
        }
    }
    __syncthreads();

    // ---------------- epilogue 1: bias + prelu -> H bf16 tile in smem ----------------
    {
        const float a_jk = *a_jk_p;
        __nv_bfloat16* hh = (__nv_bfloat16*)(smraw + HREG);
        #pragma unroll
        for (int mt = 0; mt < 2; ++mt) {
            const int r = wm * 32 + mt * 16 + g;
            #pragma unroll
            for (int nt = 0; nt < 8; ++nt) {
                const int c = wn * 64 + nt * 8 + tg * 2;
                const float b0v = sb1[c], b1v = sb1[c + 1];
                float x0 = prelu_f(acc[mt][nt][0] + b0v, a_jk);
                float x1 = prelu_f(acc[mt][nt][1] + b1v, a_jk);
                float x2 = prelu_f(acc[mt][nt][2] + b0v, a_jk);
                float x3 = prelu_f(acc[mt][nt][3] + b1v, a_jk);
                *(uint32_t*)&hh[(size_t)r * 264 + c]       = pack_bf16x2(x0, x1);
                *(uint32_t*)&hh[(size_t)(r + 8) * 264 + c] = pack_bf16x2(x2, x3);
            }
        }
    }

    #pragma unroll
    for (int a = 0; a < 2; ++a)
        #pragma unroll
        for (int b = 0; b < 8; ++b)
            #pragma unroll
            for (int c = 0; c < 4; ++c) acc[a][b][c] = 0.f;

    // ---------------- Phase 2: jk = H @ W2, K=256 in 4 chunks ----------------
    const uint32_t a2H = sb + HREG + (uint32_t)(wm * 32 + (lane & 15)) * 528
                       + (uint32_t)((lane >> 4) * 8) * 2;
    const uint32_t b2f = sb + B2H + boff_c;

    for (int c2 = 0; c2 < 4; ++c2) {
        __syncthreads();   // H visible (c2=0) / prior MMA reads done before overwrite
        const int c0 = c2 << 6;
        #pragma unroll
        for (int i = 0; i < 4; ++i) {
            int idx = i * 512 + tid;
            int r = idx >> 3, c8 = (idx & 7) << 3;
            CP_ASYNC16(sb + B2H + r * 144 + c8 * 2,
                       g_W2T_hi + (size_t)r * 256 + c0 + c8);
        }
        CP_COMMIT();
        CP_WAIT0();
        __syncthreads();

        #pragma unroll
        for (int ks = 0; ks < 4; ++ks) {
            const uint32_t ko = (uint32_t)(c0 + ks * 16) * 2;
            uint32_t ah[2][4];
            ldsm4(ah[0], a2H + ko);
            ldsm4(ah[1], a2H + 16 * 528 + ko);
            #pragma unroll
            for (int ntp = 0; ntp < 4; ++ntp) {
                uint32_t bhf[4];
                ldsm4(bhf, b2f + ntp * 16 * 144 + ks * 32);
                #pragma unroll
                for (int mt = 0; mt < 2; ++mt) {
                    mma16816(acc[mt][ntp * 2],     ah[mt], bhf);
                    mma16816(acc[mt][ntp * 2 + 1], ah[mt], bhf + 2);
                }
            }
        }
    }

    // ---------------- epilogue 2: prelu -> dot(w_ref) -> softmax(sigmoid) ----------------
    const float a_main = *a_main_p;
    float part[2][2] = {{0.f, 0.f}, {0.f, 0.f}};
    #pragma unroll
    for (int mt = 0; mt < 2; ++mt) {
        #pragma unroll
        for (int nt = 0; nt < 8; ++nt) {
            const int c = wn * 64 + nt * 8 + tg * 2;
            const float w0 = swr[c], w1 = swr[c + 1];
            const float bb0 = sb2[c], bb1 = sb2[c + 1];
            part[mt][0] += prelu_f(acc[mt][nt][0] + bb0, a_main) * w0
                         + prelu_f(acc[mt][nt][1] + bb1, a_main) * w1;
            part[mt][1] += prelu_f(acc[mt][nt][2] + bb0, a_main) * w0
                         + prelu_f(acc[mt][nt][3] + bb1, a_main) * w1;
        }
    }
    #pragma unroll
    for (int mt = 0; mt < 2; ++mt)
        #pragma unroll
        for (int h = 0; h < 2; ++h) {
            part[mt][h] += __shfl_xor_sync(0xffffffffu, part[mt][h], 1);
            part[mt][h] += __shfl_xor_sync(0xffffffffu, part[mt][h], 2);
        }
    __syncthreads();
    if (tg == 0) {
        #pragma unroll
        for (int mt = 0; mt < 2; ++mt) {
            const int r = wm * 32 + mt * 16 + g;
            sred[r * 4 + wn]       = part[mt][0];
            sred[(r + 8) * 4 + wn] = part[mt][1];
        }
    }
    __syncthreads();

    if (tid < 128) {
        const int n = n0 + tid;
        if (n < N) {
            const float sref = sred[tid * 4] + sred[tid * 4 + 1]
                             + sred[tid * 4 + 2] + sred[tid * 4 + 3] + *b_att_p;
            const float* sxp = g_sx + (size_t)n * HOPS;
            float s[HOPS];
            float m = -1e30f;
            #pragma unroll
            for (int h = 0; h < HOPS; ++h) {
                float z = sxp[h] + sref;
                s[h] = 1.f / (1.f + expf(-z));
                m = fmaxf(m, s[h]);
            }
            float sum = 0.f;
            #pragma unroll
            for (int h = 0; h < HOPS; ++h) { s[h] = expf(s[h] - m); sum += s[h]; }
            const float inv = 1.f / sum;
            float* d = g_w + (size_t)n * HOPS;
            *(float4*)(d + 0) = make_float4(s[0] * inv, s[1] * inv, s[2] * inv, s[3] * inv);
            *(float4*)(d + 4) = make_float4(s[4] * inv, s[5] * inv, s[6] * inv, s[7] * inv);
        }
    }
}

// ---------------------------------------------------------------------------
// k3a: agg[n][f] = sum_h g_w[n][h] * feats[h][n][f]  -> split bf16 global.
// ---------------------------------------------------------------------------
__global__ __launch_bounds__(256) void k3a_agg(const float* __restrict__ feats, int N)
{
    int idx = blockIdx.x * 256 + threadIdx.x;
    if (idx >= N * 32) return;
    const int n = idx >> 5, f = (idx & 31) << 2;

    float4 w0 = *(const float4*)(g_w + (size_t)n * HOPS);
    float4 w1 = *(const float4*)(g_w + (size_t)n * HOPS + 4);
    const float wv[8] = {w0.x, w0.y, w0.z, w0.w, w1.x, w1.y, w1.z, w1.w};

    float ax = 0.f, ay = 0.f, az = 0.f, aw = 0.f;
    #pragma unroll
    for (int hop = 0; hop < HOPS; ++hop) {
        const float4 v = *(const float4*)(feats + (size_t)hop * N * FDIM
                                                + (size_t)n * FDIM + f);
        ax += wv[hop] * v.x; ay += wv[hop] * v.y;
        az += wv[hop] * v.z; aw += wv[hop] * v.w;
    }
    store_split2(g_agg_hi, g_agg_lo, (size_t)n * FDIM + f,     ax, ay);
    store_split2(g_agg_hi, g_agg_lo, (size_t)n * FDIM + f + 2, az, aw);
}

// ---------------------------------------------------------------------------
// k3b: out = prelu(agg@Wo1+bo1, a_out) @ Wo2 + bo2.  512 thr (16 warps), BM=64.
// FFN1 warps 2M x 8N (32x32); FFN2 warps 2M x 8N (32x8, ldmatrix.x2 B).
// ---------------------------------------------------------------------------
#define AGH 0
#define AGL 17408
#define BB  34816
#define BBL (BB + 36864)
#define TH  108544
#define TL  142336
#define K3_SMEM 176128

__global__ __launch_bounds__(512, 1) void k3b_out(
    const float* __restrict__ bo1, const float* __restrict__ a_out_p,
    const float* __restrict__ bo2, float* __restrict__ out, int N)
{
    extern __shared__ char smraw[];
    const uint32_t sb = smem_u32(smraw);
    const int tid = threadIdx.x, wid = tid >> 5, lane = tid & 31;
    const int n0 = blockIdx.x * 64;
    const int g = lane >> 2, tg = lane & 3;

    // ---- load agg tile (split bf16) via cp.async ----
    #pragma unroll
    for (int i = 0; i < 2; ++i) {
        int idx = i * 512 + tid;
        int r = idx >> 4, c8 = (idx & 15) << 3;
        int n = n0 + r; if (n > N - 1) n = N - 1;
        CP_ASYNC16(sb + AGH + r * 272 + c8 * 2, g_agg_hi + (size_t)n * FDIM + c8);
        CP_ASYNC16(sb + AGL + r * 272 + c8 * 2, g_agg_lo + (size_t)n * FDIM + c8);
    }
    CP_COMMIT();

    const int brow = (lane & 7) + ((lane >> 4) << 3);
    const int bko  = ((lane >> 3) & 1) * 8;
    const int wm = wid & 1, wn = wid >> 1;   // 2M x 8N

    // ---- FFN1: t = prelu(agg[64x128] @ Wo1 + bo1) -> split smem (pitch 528B) ----
    {
        float acc1[2][4][4];
        #pragma unroll
        for (int a = 0; a < 2; ++a)
            #pragma unroll
            for (int b = 0; b < 4; ++b)
                #pragma unroll
                for (int c = 0; c < 4; ++c) acc1[a][b][c] = 0.f;

        const uint32_t aoffH = sb + AGH + (uint32_t)(wm * 32 + (lane & 15)) * 272
                             + (uint32_t)((lane >> 4) * 8) * 2;
        const uint32_t aoffL = aoffH + (AGL - AGH);
        const uint32_t boffH = sb + BB + (uint32_t)(wn * 32 + brow) * 144 + (uint32_t)bko * 2;
        const uint32_t boffL = boffH + 36864;

        for (int cb = 0; cb < 2; ++cb) {
            if (cb) __syncthreads();
            #pragma unroll
            for (int i = 0; i < 4; ++i) {
                int idx = i * 512 + tid;
                int r = idx >> 3, c8 = (idx & 7) << 3;
                CP_ASYNC16(sb + BB + r * 144 + c8 * 2,
                           g_Wo1T_hi + (size_t)r * 128 + cb * 64 + c8);
                CP_ASYNC16(sb + BBL + r * 144 + c8 * 2,
                           g_Wo1T_lo + (size_t)r * 128 + cb * 64 + c8);
            }
            CP_COMMIT();
            CP_WAIT0();
            __syncthreads();
            #pragma unroll
            for (int ks = 0; ks < 4; ++ks) {
                const int kglob = cb * 64 + ks * 16;
                uint32_t ah[2][4], al[2][4];
                ldsm4(ah[0], aoffH + kglob * 2);
                ldsm4(ah[1], aoffH + 16 * 272 + kglob * 2);
                ldsm4(al[0], aoffL + kglob * 2);
                ldsm4(al[1], aoffL + 16 * 272 + kglob * 2);
                #pragma unroll
                for (int ntp = 0; ntp < 2; ++ntp) {
                    uint32_t bh[4], bl[4];
                    ldsm4(bh, boffH + ntp * 16 * 144 + ks * 32);
                    ldsm4(bl, boffL + ntp * 16 * 144 + ks * 32);
                    #pragma unroll
                    for (int mt = 0; mt < 2; ++mt) {
                        mma16816(acc1[mt][ntp * 2],     ah[mt], bh);
                        mma16816(acc1[mt][ntp * 2],     ah[mt], bl);
                        mma16816(acc1[mt][ntp * 2],     al[mt], bh);
                        mma16816(acc1[mt][ntp * 2 + 1], ah[mt], bh + 2);
                        mma16816(acc1[mt][ntp * 2 + 1], ah[mt], bl + 2);
                        mma16816(acc1[mt][ntp * 2 + 1], al[mt], bh + 2);
                    }
                }
            }
        }
        __syncthreads();

        const float a_out = *a_out_p;
        __nv_bfloat16* th = (__nv_bfloat16*)(smraw + TH);
        __nv_bfloat16* tl = (__nv_bfloat16*)(smraw + TL);
        #pragma unroll
        for (int mt = 0; mt < 2; ++mt) {
            const int r = wm * 32 + mt * 16 + g;
            #pragma unroll
            for (int nt = 0; nt < 4; ++nt) {
                const int c = wn * 32 + nt * 8 + tg * 2;
                const float b0v = __ldg(&bo1[c]), b1v = __ldg(&bo1[c + 1]);
                float x0 = prelu_f(acc1[mt][nt][0] + b0v, a_out);
                float x1 = prelu_f(acc1[mt][nt][1] + b1v, a_out);
                float x2 = prelu_f(acc1[mt][nt][2] + b0v, a_out);
                float x3 = prelu_f(acc1[mt][nt][3] + b1v, a_out);
                store_split2(th, tl, (size_t)r * 264 + c, x0, x1);
                store_split2(th, tl, (size_t)(r + 8) * 264 + c, x2, x3);
            }
        }
        __syncthreads();
    }

    // ---- FFN2: out = t[64x256] @ Wo2 + bo2 ----
    {
        float acc2[2][4];
        #pragma unroll
        for (int a = 0; a < 2; ++a)
            #pragma unroll
            for (int c = 0; c < 4; ++c) acc2[a][c] = 0.f;

        const uint32_t aoffH = sb + TH + (uint32_t)(wm * 32 + (lane & 15)) * 528
                             + (uint32_t)((lane >> 4) * 8) * 2;
        const uint32_t aoffL = aoffH + (TL - TH);
        const int l16 = lane & 15;
        const uint32_t boff2H = sb + BB + (uint32_t)(wn * 8 + (l16 & 7)) * 144
                              + (uint32_t)((l16 >> 3) * 16);
        const uint32_t boff2L = boff2H + 36864;

        for (int ch = 0; ch < 4; ++ch) {
            __syncthreads();
            {   // 64 rows x 8 uint4 = 512 items, one per thread (hi + lo)
                int r = tid >> 3, c8 = (tid & 7) << 3;
                CP_ASYNC16(sb + BB + r * 144 + c8 * 2,
                           g_Wo2T_hi + (size_t)r * 256 + ch * 64 + c8);
                CP_ASYNC16(sb + BBL + r * 144 + c8 * 2,
                           g_Wo2T_lo + (size_t)r * 256 + ch * 64 + c8);
            }
            CP_COMMIT();
            CP_WAIT0();
            __syncthreads();
            #pragma unroll
            for (int ks = 0; ks < 4; ++ks) {
                const int kglob = ch * 64 + ks * 16;
                uint32_t ah[2][4], al[2][4], bh[2], bl[2];
                ldsm4(ah[0], aoffH + kglob * 2);
                ldsm4(ah[1], aoffH + 16 * 528 + kglob * 2);
                ldsm4(al[0], aoffL + kglob * 2);
                ldsm4(al[1], aoffL + 16 * 528 + kglob * 2);
                ldsm2(bh, boff2H + ks * 32);
                ldsm2(bl, boff2L + ks * 32);
                #pragma unroll
                for (int mt = 0; mt < 2; ++mt) {
                    mma16816(acc2[mt], ah[mt], bh);
                    mma16816(acc2[mt], ah[mt], bl);
                    mma16816(acc2[mt], al[mt], bh);
                }
            }
        }

        const int c = wn * 8 + tg * 2;
        const float b0v = __ldg(&bo2[c]), b1v = __ldg(&bo2[c + 1]);
        #pragma unroll
        for (int mt = 0; mt < 2; ++mt) {
            const int n = n0 + wm * 32 + mt * 16 + g;
            if (n < N) {
                float2 o = make_float2(acc2[mt][0] + b0v, acc2[mt][1] + b1v);
                *(float2*)&out[(size_t)n * NCLS + c] = o;
            }
            if (n + 8 < N) {
                float2 o = make_float2(acc2[mt][2] + b0v, acc2[mt][3] + b1v);
                *(float2*)&out[(size_t)(n + 8) * NCLS + c] = o;
            }
        }
    }
}

// ---------------------------------------------------------------------------
extern "C" void kernel_launch(void* const* d_in, const int* in_sizes, int n_in,
                              void* d_out, int out_size)
{
    const float* feats  = (const float*)d_in[0];
    const float* W_jk1  = (const float*)d_in[1];
    const float* b_jk1  = (const float*)d_in[2];
    const float* W_jk2  = (const float*)d_in[3];
    const float* b_jk2  = (const float*)d_in[4];
    const float* a_jk   = (const float*)d_in[5];
    const float* a_main = (const float*)d_in[6];
    const float* a_out  = (const float*)d_in[7];
    const float* w_ref  = (const float*)d_in[8];
    const float* w_x    = (const float*)d_in[9];
    const float* b_att  = (const float*)d_in[10];
    const float* W_o1   = (const float*)d_in[11];
    const float* b_o1   = (const float*)d_in[12];
    const float* W_o2   = (const float*)d_in[13];
    const float* b_o2   = (const float*)d_in[14];
    float* out = (float*)d_out;

    const int N = in_sizes[0] / (HOPS * FDIM);
    const int nb128 = (N + 127) / 128;
    const int nb64  = (N + 63) / 64;

    cudaFuncSetAttribute(k12,     cudaFuncAttributeMaxDynamicSharedMemorySize, K12_SMEM);
    cudaFuncSetAttribute(k3b_out, cudaFuncAttributeMaxDynamicSharedMemorySize, K3_SMEM);

    k0_convert<<<368, 1024>>>(W_jk1, W_jk2, W_o1, W_o2);
    k12<<<nb128, 512, K12_SMEM>>>(feats, w_x, b_jk1, a_jk, b_jk2, a_main,
                                  w_ref, b_att, N);
    k3a_agg<<<(N * 32 + 255) / 256, 256>>>(feats, N);
    k3b_out<<<nb64, 512, K3_SMEM>>>(b_o1, a_out, b_o2, out, N);
}

// round 8
// speedup vs baseline: 4.6867x; 1.0228x over previous
#include <cuda_runtime.h>
#include <cuda_bf16.h>
#include <cstdint>

#define HOPS 8
#define FDIM 128
#define HID  256
#define NCLS 64
#define NMAX 100096

typedef unsigned long long ull;

// ---------------- scratch (device globals; no runtime alloc) ----------------
__device__ float g_sx[(size_t)NMAX * HOPS];
__device__ float g_w [(size_t)NMAX * HOPS];
__device__ __nv_bfloat16 g_W1T_hi[(size_t)HID * 1024];   // [c][k]
__device__ __nv_bfloat16 g_W2T_hi[(size_t)HID * HID];
__device__ __nv_bfloat16 g_Wo1T_hi[(size_t)HID * FDIM];  // [c=256][k=128]
__device__ __nv_bfloat16 g_Wo1T_lo[(size_t)HID * FDIM];
__device__ __nv_bfloat16 g_Wo2T_hi[(size_t)NCLS * HID];  // [c=64][k=256]
__device__ __nv_bfloat16 g_Wo2T_lo[(size_t)NCLS * HID];

// ---------------- helpers ----------------
__device__ __forceinline__ uint32_t smem_u32(const void* p) {
    uint32_t a;
    asm("{ .reg .u64 t; cvta.to.shared.u64 t, %1; cvt.u32.u64 %0, t; }" : "=r"(a) : "l"(p));
    return a;
}
__device__ __forceinline__ void ldsm4(uint32_t* r, uint32_t addr) {
    asm volatile("ldmatrix.sync.aligned.m8n8.x4.shared.b16 {%0,%1,%2,%3}, [%4];"
        : "=r"(r[0]), "=r"(r[1]), "=r"(r[2]), "=r"(r[3]) : "r"(addr));
}
__device__ __forceinline__ void ldsm2(uint32_t* r, uint32_t addr) {
    asm volatile("ldmatrix.sync.aligned.m8n8.x2.shared.b16 {%0,%1}, [%2];"
        : "=r"(r[0]), "=r"(r[1]) : "r"(addr));
}
__device__ __forceinline__ void mma16816(float* c, const uint32_t* a, const uint32_t* b) {
    asm volatile("mma.sync.aligned.m16n8k16.row.col.f32.bf16.bf16.f32 "
        "{%0,%1,%2,%3}, {%4,%5,%6,%7}, {%8,%9}, {%0,%1,%2,%3};"
        : "+f"(c[0]), "+f"(c[1]), "+f"(c[2]), "+f"(c[3])
        : "r"(a[0]), "r"(a[1]), "r"(a[2]), "r"(a[3]), "r"(b[0]), "r"(b[1]));
}
#define CP_ASYNC16(dst, src) \
    asm volatile("cp.async.cg.shared.global [%0], [%1], 16;" :: "r"(dst), "l"(src))
#define CP_COMMIT() asm volatile("cp.async.commit_group;" ::: "memory")
#define CP_WAIT0()  asm volatile("cp.async.wait_group 0;" ::: "memory")

__device__ __forceinline__ float prelu_f(float v, float a) { return v >= 0.f ? v : a * v; }

union BfPair { uint32_t u; __nv_bfloat16 e[2]; };
union Bf8    { uint4 q;    __nv_bfloat16 e[8]; };

__device__ __forceinline__ uint32_t pack_bf16x2(float x0, float x1) {
    BfPair p;
    p.e[0] = __float2bfloat16(x0);
    p.e[1] = __float2bfloat16(x1);
    return p.u;
}
__device__ __forceinline__ void store_split2(__nv_bfloat16* hi, __nv_bfloat16* lo,
                                             size_t base, float x0, float x1) {
    BfPair ph, pl;
    ph.e[0] = __float2bfloat16(x0);
    ph.e[1] = __float2bfloat16(x1);
    pl.e[0] = __float2bfloat16(x0 - __bfloat162float(ph.e[0]));
    pl.e[1] = __float2bfloat16(x1 - __bfloat162float(ph.e[1]));
    *(uint32_t*)&hi[base] = ph.u;
    *(uint32_t*)&lo[base] = pl.u;
}

// ---------------------------------------------------------------------------
// k0: transpose weights. W1/W2 -> bf16 hi only; Wo1/Wo2 -> split hi/lo.
// ---------------------------------------------------------------------------
__global__ void k0_convert(const float* __restrict__ W1, const float* __restrict__ W2,
                           const float* __restrict__ Wo1, const float* __restrict__ Wo2)
{
    int idx = blockIdx.x * 1024 + threadIdx.x;
    if (idx < 262144) {                       // W1 [1024][256] hi only
        int k = idx >> 8, c = idx & 255;
        g_W1T_hi[(size_t)c * 1024 + k] = __float2bfloat16(W1[idx]);
        return;
    }
    if (idx < 327680) {                       // W2 [256][256] hi only
        int i = idx - 262144, k = i >> 8, c = i & 255;
        g_W2T_hi[(size_t)c * 256 + k] = __float2bfloat16(W2[i]);
        return;
    }
    float v; size_t dst; __nv_bfloat16* ph; __nv_bfloat16* pl;
    if (idx < 360448) {                       // Wo1 [128][256] split
        int i = idx - 327680, k = i >> 8, c = i & 255;
        v = Wo1[i]; dst = (size_t)c * 128 + k; ph = g_Wo1T_hi; pl = g_Wo1T_lo;
    } else if (idx < 376832) {                // Wo2 [256][64] split
        int i = idx - 360448, k = i >> 6, c = i & 63;
        v = Wo2[i]; dst = (size_t)c * 256 + k; ph = g_Wo2T_hi; pl = g_Wo2T_lo;
    } else return;
    __nv_bfloat16 h = __float2bfloat16(v);
    ph[dst] = h;
    pl[dst] = __float2bfloat16(v - __bfloat162float(h));
}

// ---------------------------------------------------------------------------
// k12 smem layout (1-pass bf16).
// ---------------------------------------------------------------------------
#define STG    55296
#define S_AH   0
#define S_BH   18432
#define HREG   0
#define B2H    67584
#define EX_WX   110592
#define EX_B1   111104
#define EX_B2   112128
#define EX_WR   113152
#define EX_SRED 114176
#define K12_SMEM 116224

__global__ __launch_bounds__(512, 1) void k12(
    const float* __restrict__ feats, const float* __restrict__ wx,
    const float* __restrict__ b1, const float* __restrict__ a_jk_p,
    const float* __restrict__ b2, const float* __restrict__ a_main_p,
    const float* __restrict__ w_ref, const float* __restrict__ b_att_p, int N)
{
    extern __shared__ char smraw[];
    const uint32_t sb = smem_u32(smraw);
    const int tid = threadIdx.x, wid = tid >> 5, lane = tid & 31;
    const int n0 = blockIdx.x * 128;
    const int wm = wid & 3, wn = wid >> 2;          // 4M x 4N warps, tile 32x64
    const int g = lane >> 2, tg = lane & 3;
    const int sxrow = wid * 8 + (lane >> 2);        // s_x: 4 threads per row

    float* wxs  = (float*)(smraw + EX_WX);
    float* sb1  = (float*)(smraw + EX_B1);
    float* sb2  = (float*)(smraw + EX_B2);
    float* swr  = (float*)(smraw + EX_WR);
    float* sred = (float*)(smraw + EX_SRED);
    if (tid < 128) wxs[tid] = wx[tid];
    else if (tid < 384) sb1[tid - 128] = b1[tid - 128];
    if (tid < 256) sb2[tid] = b2[tid];
    else swr[tid - 256] = w_ref[tid - 256];

    float acc[2][8][4];
    #pragma unroll
    for (int a = 0; a < 2; ++a)
        #pragma unroll
        for (int b = 0; b < 8; ++b)
            #pragma unroll
            for (int c = 0; c < 4; ++c) acc[a][b][c] = 0.f;

    const uint32_t aoff_c = (uint32_t)(wm * 32 + (lane & 15)) * 144
                          + (uint32_t)((lane >> 4) * 8) * 2;
    const int brow = (lane & 7) + ((lane >> 4) << 3);
    const int bko  = ((lane >> 3) & 1) * 8;
    const uint32_t boff_c = (uint32_t)(wn * 64 + brow) * 144 + (uint32_t)bko * 2;

    // ---------------- Phase 1: 16 K-chunks of 64, double-buffered ----------------
    float4 areg[4];
    {   // prologue: chunk 0
        #pragma unroll
        for (int i = 0; i < 4; ++i) {
            int idx = i * 512 + tid;
            int r = idx >> 4, cq = (idx & 15) << 2;
            int n = n0 + r; if (n > N - 1) n = N - 1;
            areg[i] = *(const float4*)(feats + (size_t)n * FDIM + cq);
        }
        #pragma unroll
        for (int i = 0; i < 4; ++i) {
            int idx = i * 512 + tid;
            int r = idx >> 3, c8 = (idx & 7) << 3;
            CP_ASYNC16(sb + S_BH + r * 144 + c8 * 2, g_W1T_hi + (size_t)r * 1024 + c8);
        }
        CP_COMMIT();
        #pragma unroll
        for (int i = 0; i < 4; ++i) {
            int idx = i * 512 + tid;
            int r = idx >> 4, cq = (idx & 15) << 2;
            ull u = (ull)pack_bf16x2(areg[i].x, areg[i].y)
                  | ((ull)pack_bf16x2(areg[i].z, areg[i].w) << 32);
            *(ull*)(smraw + S_AH + r * 144 + cq * 2) = u;
        }
    }

    float sx0 = 0.f, sx1 = 0.f;

    for (int chunk = 0; chunk < 16; ++chunk) {
        const uint32_t sbase = (uint32_t)(chunk & 1) * STG;
        const int hop = chunk >> 1, f0 = (chunk & 1) << 6;

        CP_WAIT0();
        __syncthreads();

        if (chunk < 15) {
            const int cn = chunk + 1;
            const uint32_t nbase = (uint32_t)(cn & 1) * STG;
            const int c0n = cn << 6;
            #pragma unroll
            for (int i = 0; i < 4; ++i) {
                int idx = i * 512 + tid;
                int r = idx >> 3, c8 = (idx & 7) << 3;
                CP_ASYNC16(sb + nbase + S_BH + r * 144 + c8 * 2,
                           g_W1T_hi + (size_t)r * 1024 + c0n + c8);
            }
            CP_COMMIT();
            const int hop_n = cn >> 1, f0_n = (cn & 1) << 6;
            const float* fbn = feats + (size_t)hop_n * N * FDIM + f0_n;
            #pragma unroll
            for (int i = 0; i < 4; ++i) {
                int idx = i * 512 + tid;
                int r = idx >> 4, cq = (idx & 15) << 2;
                int n = n0 + r; if (n > N - 1) n = N - 1;
                areg[i] = *(const float4*)(fbn + (size_t)n * FDIM + cq);
            }
        }

        {   // fused s_x, spread over all warps: 4 threads/row, 16 cols each
            const char* bh = smraw + sbase + S_AH + sxrow * 144 + tg * 32;
            #pragma unroll
            for (int q = 0; q < 2; ++q) {
                Bf8 qh;
                qh.q = *(const uint4*)(bh + q * 16);
                const float* wp = wxs + f0 + tg * 16 + q * 8;
                sx0 += __bfloat162float(qh.e[0]) * wp[0] + __bfloat162float(qh.e[2]) * wp[2]
                     + __bfloat162float(qh.e[4]) * wp[4] + __bfloat162float(qh.e[6]) * wp[6];
                sx1 += __bfloat162float(qh.e[1]) * wp[1] + __bfloat162float(qh.e[3]) * wp[3]
                     + __bfloat162float(qh.e[5]) * wp[5] + __bfloat162float(qh.e[7]) * wp[7];
            }
        }

        const uint32_t aH = sb + sbase + S_AH + aoff_c;
        const uint32_t bH = sb + sbase + S_BH + boff_c;
        #pragma unroll
        for (int ks = 0; ks < 4; ++ks) {
            uint32_t ah[2][4];
            ldsm4(ah[0], aH + ks * 32);
            ldsm4(ah[1], aH + 16 * 144 + ks * 32);
            #pragma unroll
            for (int ntp = 0; ntp < 4; ++ntp) {
                uint32_t bhf[4];
                ldsm4(bhf, bH + ntp * 16 * 144 + ks * 32);
                #pragma unroll
                for (int mt = 0; mt < 2; ++mt) {
                    mma16816(acc[mt][ntp * 2],     ah[mt], bhf);
                    mma16816(acc[mt][ntp * 2 + 1], ah[mt], bhf + 2);
                }
            }
        }

        if (chunk < 15) {   // convert + store A(next) into next stage
            const uint32_t nbase = (uint32_t)((chunk + 1) & 1) * STG;
            #pragma unroll
            for (int i = 0; i < 4; ++i) {
                int idx = i * 512 + tid;
                int r = idx >> 4, cq = (idx & 15) << 2;
                ull u = (ull)pack_bf16x2(areg[i].x, areg[i].y)
                      | ((ull)pack_bf16x2(areg[i].z, areg[i].w) << 32);
                *(ull*)(smraw + nbase + S_AH + r * 144 + cq * 2) = u;
            }
        }

        if (chunk & 1) {
            float s = sx0 + sx1;
            s += __shfl_xor_sync(0xffffffffu, s, 1);
            s += __shfl_xor_sync(0xffffffffu, s, 2);
            if (tg == 0 && n0 + sxrow < N)
                g_sx[(size_t)(n0 + sxrow) * HOPS + hop] = s;
            sx0 = sx1 = 0.f;
        }
    }
    __syncthreads();

    // ---------------- epilogue 1: bias + prelu -> H bf16 tile in smem ----------------
    {
        const float a_jk = *a_jk_p;
        __nv_bfloat16* hh = (__nv_bfloat16*)(smraw + HREG);
        #pragma unroll
        for (int mt = 0; mt < 2; ++mt) {
            const int r = wm * 32 + mt * 16 + g;
            #pragma unroll
            for (int nt = 0; nt < 8; ++nt) {
                const int c = wn * 64 + nt * 8 + tg * 2;
                const float b0v = sb1[c], b1v = sb1[c + 1];
                float x0 = prelu_f(acc[mt][nt][0] + b0v, a_jk);
                float x1 = prelu_f(acc[mt][nt][1] + b1v, a_jk);
                float x2 = prelu_f(acc[mt][nt][2] + b0v, a_jk);
                float x3 = prelu_f(acc[mt][nt][3] + b1v, a_jk);
                *(uint32_t*)&hh[(size_t)r * 264 + c]       = pack_bf16x2(x0, x1);
                *(uint32_t*)&hh[(size_t)(r + 8) * 264 + c] = pack_bf16x2(x2, x3);
            }
        }
    }

    #pragma unroll
    for (int a = 0; a < 2; ++a)
        #pragma unroll
        for (int b = 0; b < 8; ++b)
            #pragma unroll
            for (int c = 0; c < 4; ++c) acc[a][b][c] = 0.f;

    // ---------------- Phase 2: jk = H @ W2, K=256 in 4 chunks ----------------
    const uint32_t a2H = sb + HREG + (uint32_t)(wm * 32 + (lane & 15)) * 528
                       + (uint32_t)((lane >> 4) * 8) * 2;
    const uint32_t b2f = sb + B2H + boff_c;

    for (int c2 = 0; c2 < 4; ++c2) {
        __syncthreads();
        const int c0 = c2 << 6;
        #pragma unroll
        for (int i = 0; i < 4; ++i) {
            int idx = i * 512 + tid;
            int r = idx >> 3, c8 = (idx & 7) << 3;
            CP_ASYNC16(sb + B2H + r * 144 + c8 * 2,
                       g_W2T_hi + (size_t)r * 256 + c0 + c8);
        }
        CP_COMMIT();
        CP_WAIT0();
        __syncthreads();

        #pragma unroll
        for (int ks = 0; ks < 4; ++ks) {
            const uint32_t ko = (uint32_t)(c0 + ks * 16) * 2;
            uint32_t ah[2][4];
            ldsm4(ah[0], a2H + ko);
            ldsm4(ah[1], a2H + 16 * 528 + ko);
            #pragma unroll
            for (int ntp = 0; ntp < 4; ++ntp) {
                uint32_t bhf[4];
                ldsm4(bhf, b2f + ntp * 16 * 144 + ks * 32);
                #pragma unroll
                for (int mt = 0; mt < 2; ++mt) {
                    mma16816(acc[mt][ntp * 2],     ah[mt], bhf);
                    mma16816(acc[mt][ntp * 2 + 1], ah[mt], bhf + 2);
                }
            }
        }
    }

    // ---------------- epilogue 2: prelu -> dot(w_ref) -> softmax(sigmoid) ----------------
    const float a_main = *a_main_p;
    float part[2][2] = {{0.f, 0.f}, {0.f, 0.f}};
    #pragma unroll
    for (int mt = 0; mt < 2; ++mt) {
        #pragma unroll
        for (int nt = 0; nt < 8; ++nt) {
            const int c = wn * 64 + nt * 8 + tg * 2;
            const float w0 = swr[c], w1 = swr[c + 1];
            const float bb0 = sb2[c], bb1 = sb2[c + 1];
            part[mt][0] += prelu_f(acc[mt][nt][0] + bb0, a_main) * w0
                         + prelu_f(acc[mt][nt][1] + bb1, a_main) * w1;
            part[mt][1] += prelu_f(acc[mt][nt][2] + bb0, a_main) * w0
                         + prelu_f(acc[mt][nt][3] + bb1, a_main) * w1;
        }
    }
    #pragma unroll
    for (int mt = 0; mt < 2; ++mt)
        #pragma unroll
        for (int h = 0; h < 2; ++h) {
            part[mt][h] += __shfl_xor_sync(0xffffffffu, part[mt][h], 1);
            part[mt][h] += __shfl_xor_sync(0xffffffffu, part[mt][h], 2);
        }
    __syncthreads();
    if (tg == 0) {
        #pragma unroll
        for (int mt = 0; mt < 2; ++mt) {
            const int r = wm * 32 + mt * 16 + g;
            sred[r * 4 + wn]       = part[mt][0];
            sred[(r + 8) * 4 + wn] = part[mt][1];
        }
    }
    __syncthreads();

    if (tid < 128) {
        const int n = n0 + tid;
        if (n < N) {
            const float sref = sred[tid * 4] + sred[tid * 4 + 1]
                             + sred[tid * 4 + 2] + sred[tid * 4 + 3] + *b_att_p;
            const float* sxp = g_sx + (size_t)n * HOPS;
            float s[HOPS];
            float m = -1e30f;
            #pragma unroll
            for (int h = 0; h < HOPS; ++h) {
                float z = sxp[h] + sref;
                s[h] = 1.f / (1.f + expf(-z));
                m = fmaxf(m, s[h]);
            }
            float sum = 0.f;
            #pragma unroll
            for (int h = 0; h < HOPS; ++h) { s[h] = expf(s[h] - m); sum += s[h]; }
            const float inv = 1.f / sum;
            float* d = g_w + (size_t)n * HOPS;
            *(float4*)(d + 0) = make_float4(s[0] * inv, s[1] * inv, s[2] * inv, s[3] * inv);
            *(float4*)(d + 4) = make_float4(s[4] * inv, s[5] * inv, s[6] * inv, s[7] * inv);
        }
    }
}

// ---------------------------------------------------------------------------
// k3: FUSED  agg (smem) -> FFN1 -> FFN2 -> out.  512 thr, BM=64.
// FFN1: 4 double-buffered K-chunks of 32 (pitch 80).
// FFN2: 4 double-buffered K-chunks of 64 (pitch 144).
// ---------------------------------------------------------------------------
#define K3_SWV 0
#define K3_AGH 2048
#define K3_AGL 19456
#define K3_TH  36864
#define K3_TL  70656
#define K3_BB  104448
#define K3_SMEM 186368

__global__ __launch_bounds__(512, 1) void k3_fused(
    const float* __restrict__ feats, const float* __restrict__ bo1,
    const float* __restrict__ a_out_p, const float* __restrict__ bo2,
    float* __restrict__ out, int N)
{
    extern __shared__ char smraw[];
    const uint32_t sb = smem_u32(smraw);
    const int tid = threadIdx.x, wid = tid >> 5, lane = tid & 31;
    const int n0 = blockIdx.x * 64;
    const int g = lane >> 2, tg = lane & 3;
    const int wm = wid & 1, wn = wid >> 1;   // 2M x 8N

    // ---- prologue: FFN1 chunk0 (k 0..31) cp.async — hides under aggregation ----
    #pragma unroll
    for (int i = 0; i < 2; ++i) {
        int idx = i * 512 + tid;
        int r = idx >> 2, c8 = (idx & 3) << 3;
        CP_ASYNC16(sb + K3_BB + r * 80 + c8 * 2,
                   g_Wo1T_hi + (size_t)r * 128 + c8);
        CP_ASYNC16(sb + K3_BB + 20480 + r * 80 + c8 * 2,
                   g_Wo1T_lo + (size_t)r * 128 + c8);
    }
    CP_COMMIT();

    // ---- load hop-weight tile ----
    {
        int r = tid >> 3, h = tid & 7;
        int n = n0 + r; if (n > N - 1) n = N - 1;
        ((float*)(smraw + K3_SWV))[tid] = g_w[(size_t)n * HOPS + h];
    }
    __syncthreads();

    // ---- Phase A: aggregation into split-bf16 smem (pitch 272B) ----
    {
        const float* swv = (const float*)(smraw + K3_SWV);
        __nv_bfloat16* agh = (__nv_bfloat16*)(smraw + K3_AGH);
        __nv_bfloat16* agl = (__nv_bfloat16*)(smraw + K3_AGL);
        #pragma unroll
        for (int i = 0; i < 4; ++i) {
            int idx = i * 512 + tid;
            int r = idx >> 5, f = (idx & 31) << 2;
            int n = n0 + r; if (n > N - 1) n = N - 1;
            const float* wp = swv + r * 8;
            float ax = 0.f, ay = 0.f, az = 0.f, aw = 0.f;
            #pragma unroll
            for (int hop = 0; hop < HOPS; ++hop) {
                const float4 v = *(const float4*)(feats + (size_t)hop * N * FDIM
                                                        + (size_t)n * FDIM + f);
                const float w = wp[hop];
                ax += w * v.x; ay += w * v.y; az += w * v.z; aw += w * v.w;
            }
            store_split2(agh, agl, (size_t)r * 136 + f,     ax, ay);
            store_split2(agh, agl, (size_t)r * 136 + f + 2, az, aw);
        }
    }

    const int brow = (lane & 7) + ((lane >> 4) << 3);
    const int bko  = ((lane >> 3) & 1) * 8;

    // ---- FFN1: t = prelu(agg[64x128] @ Wo1 + bo1); 4 chunks of k=32, dbl-buf ----
    {
        float acc1[2][4][4];
        #pragma unroll
        for (int a = 0; a < 2; ++a)
            #pragma unroll
            for (int b = 0; b < 4; ++b)
                #pragma unroll
                for (int c = 0; c < 4; ++c) acc1[a][b][c] = 0.f;

        const uint32_t aoffH = sb + K3_AGH + (uint32_t)(wm * 32 + (lane & 15)) * 272
                             + (uint32_t)((lane >> 4) * 8) * 2;
        const uint32_t aoffL = aoffH + (K3_AGL - K3_AGH);
        const uint32_t bfrag = (uint32_t)(wn * 32 + brow) * 80 + (uint32_t)bko * 2;

        for (int c = 0; c < 4; ++c) {
            CP_WAIT0();
            __syncthreads();
            if (c < 3) {
                const int cn = c + 1;
                const uint32_t nb = sb + K3_BB + (uint32_t)(cn & 1) * 40960;
                #pragma unroll
                for (int i = 0; i < 2; ++i) {
                    int idx = i * 512 + tid;
                    int r = idx >> 2, c8 = (idx & 3) << 3;
                    CP_ASYNC16(nb + r * 80 + c8 * 2,
                               g_Wo1T_hi + (size_t)r * 128 + cn * 32 + c8);
                    CP_ASYNC16(nb + 20480 + r * 80 + c8 * 2,
                               g_Wo1T_lo + (size_t)r * 128 + cn * 32 + c8);
                }
                CP_COMMIT();
            }
            const uint32_t bH = sb + K3_BB + (uint32_t)(c & 1) * 40960 + bfrag;
            const uint32_t bL = bH + 20480;
            #pragma unroll
            for (int ks = 0; ks < 2; ++ks) {
                const int kglob = c * 32 + ks * 16;
                uint32_t ah[2][4], al[2][4];
                ldsm4(ah[0], aoffH + kglob * 2);
                ldsm4(ah[1], aoffH + 16 * 272 + kglob * 2);
                ldsm4(al[0], aoffL + kglob * 2);
                ldsm4(al[1], aoffL + 16 * 272 + kglob * 2);
                #pragma unroll
                for (int ntp = 0; ntp < 2; ++ntp) {
                    uint32_t bh[4], bl[4];
                    ldsm4(bh, bH + ntp * 16 * 80 + ks * 32);
                    ldsm4(bl, bL + ntp * 16 * 80 + ks * 32);
                    #pragma unroll
                    for (int mt = 0; mt < 2; ++mt) {
                        mma16816(acc1[mt][ntp * 2],     ah[mt], bh);
                        mma16816(acc1[mt][ntp * 2],     ah[mt], bl);
                        mma16816(acc1[mt][ntp * 2],     al[mt], bh);
                        mma16816(acc1[mt][ntp * 2 + 1], ah[mt], bh + 2);
                        mma16816(acc1[mt][ntp * 2 + 1], ah[mt], bl + 2);
                        mma16816(acc1[mt][ntp * 2 + 1], al[mt], bh + 2);
                    }
                }
            }
        }
        __syncthreads();   // all FFN1 MMAs done -> BB reusable

        // kick FFN2 chunk0 load (overlaps t epilogue)
        {
            int r = tid >> 3, c8 = (tid & 7) << 3;
            CP_ASYNC16(sb + K3_BB + r * 144 + c8 * 2,
                       g_Wo2T_hi + (size_t)r * 256 + c8);
            CP_ASYNC16(sb + K3_BB + 9216 + r * 144 + c8 * 2,
                       g_Wo2T_lo + (size_t)r * 256 + c8);
        }
        CP_COMMIT();

        const float a_out = *a_out_p;
        __nv_bfloat16* th = (__nv_bfloat16*)(smraw + K3_TH);
        __nv_bfloat16* tl = (__nv_bfloat16*)(smraw + K3_TL);
        #pragma unroll
        for (int mt = 0; mt < 2; ++mt) {
            const int r = wm * 32 + mt * 16 + g;
            #pragma unroll
            for (int nt = 0; nt < 4; ++nt) {
                const int c = wn * 32 + nt * 8 + tg * 2;
                const float b0v = __ldg(&bo1[c]), b1v = __ldg(&bo1[c + 1]);
                float x0 = prelu_f(acc1[mt][nt][0] + b0v, a_out);
                float x1 = prelu_f(acc1[mt][nt][1] + b1v, a_out);
                float x2 = prelu_f(acc1[mt][nt][2] + b0v, a_out);
                float x3 = prelu_f(acc1[mt][nt][3] + b1v, a_out);
                store_split2(th, tl, (size_t)r * 264 + c, x0, x1);
                store_split2(th, tl, (size_t)(r + 8) * 264 + c, x2, x3);
            }
        }
    }

    // ---- FFN2: out = t[64x256] @ Wo2 + bo2; 4 chunks of k=64, dbl-buf ----
    {
        float acc2[2][4];
        #pragma unroll
        for (int a = 0; a < 2; ++a)
            #pragma unroll
            for (int c = 0; c < 4; ++c) acc2[a][c] = 0.f;

        const uint32_t aoffH = sb + K3_TH + (uint32_t)(wm * 32 + (lane & 15)) * 528
                             + (uint32_t)((lane >> 4) * 8) * 2;
        const uint32_t aoffL = aoffH + (K3_TL - K3_TH);
        const int l16 = lane & 15;
        const uint32_t bfrag2 = (uint32_t)(wn * 8 + (l16 & 7)) * 144
                              + (uint32_t)((l16 >> 3) * 16);

        for (int ch = 0; ch < 4; ++ch) {
            CP_WAIT0();
            __syncthreads();
            if (ch < 3) {
                const int cn = ch + 1;
                const uint32_t nb = sb + K3_BB + (uint32_t)(cn & 1) * 18432;
                int r = tid >> 3, c8 = (tid & 7) << 3;
                CP_ASYNC16(nb + r * 144 + c8 * 2,
                           g_Wo2T_hi + (size_t)r * 256 + cn * 64 + c8);
                CP_ASYNC16(nb + 9216 + r * 144 + c8 * 2,
                           g_Wo2T_lo + (size_t)r * 256 + cn * 64 + c8);
                CP_COMMIT();
            }
            const uint32_t bH = sb + K3_BB + (uint32_t)(ch & 1) * 18432 + bfrag2;
            const uint32_t bL = bH + 9216;
            #pragma unroll
            for (int ks = 0; ks < 4; ++ks) {
                const int kglob = ch * 64 + ks * 16;
                uint32_t ah[2][4], al[2][4], bh[2], bl[2];
                ldsm4(ah[0], aoffH + kglob * 2);
                ldsm4(ah[1], aoffH + 16 * 528 + kglob * 2);
                ldsm4(al[0], aoffL + kglob * 2);
                ldsm4(al[1], aoffL + 16 * 528 + kglob * 2);
                ldsm2(bh, bH + ks * 32);
                ldsm2(bl, bL + ks * 32);
                #pragma unroll
                for (int mt = 0; mt < 2; ++mt) {
                    mma16816(acc2[mt], ah[mt], bh);
                    mma16816(acc2[mt], ah[mt], bl);
                    mma16816(acc2[mt], al[mt], bh);
                }
            }
        }

        const int c = wn * 8 + tg * 2;
        const float b0v = __ldg(&bo2[c]), b1v = __ldg(&bo2[c + 1]);
        #pragma unroll
        for (int mt = 0; mt < 2; ++mt) {
            const int n = n0 + wm * 32 + mt * 16 + g;
            if (n < N) {
                float2 o = make_float2(acc2[mt][0] + b0v, acc2[mt][1] + b1v);
                *(float2*)&out[(size_t)n * NCLS + c] = o;
            }
            if (n + 8 < N) {
                float2 o = make_float2(acc2[mt][2] + b0v, acc2[mt][3] + b1v);
                *(float2*)&out[(size_t)(n + 8) * NCLS + c] = o;
            }
        }
    }
}

// ---------------------------------------------------------------------------
extern "C" void kernel_launch(void* const* d_in, const int* in_sizes, int n_in,
                              void* d_out, int out_size)
{
    const float* feats  = (const float*)d_in[0];
    const float* W_jk1  = (const float*)d_in[1];
    const float* b_jk1  = (const float*)d_in[2];
    const float* W_jk2  = (const float*)d_in[3];
    const float* b_jk2  = (const float*)d_in[4];
    const float* a_jk   = (const float*)d_in[5];
    const float* a_main = (const float*)d_in[6];
    const float* a_out  = (const float*)d_in[7];
    const float* w_ref  = (const float*)d_in[8];
    const float* w_x    = (const float*)d_in[9];
    const float* b_att  = (const float*)d_in[10];
    const float* W_o1   = (const float*)d_in[11];
    const float* b_o1   = (const float*)d_in[12];
    const float* W_o2   = (const float*)d_in[13];
    const float* b_o2   = (const float*)d_in[14];
    float* out = (float*)d_out;

    const int N = in_sizes[0] / (HOPS * FDIM);
    const int nb128 = (N + 127) / 128;
    const int nb64  = (N + 63) / 64;

    cudaFuncSetAttribute(k12,      cudaFuncAttributeMaxDynamicSharedMemorySize, K12_SMEM);
    cudaFuncSetAttribute(k3_fused, cudaFuncAttributeMaxDynamicSharedMemorySize, K3_SMEM);

    k0_convert<<<368, 1024>>>(W_jk1, W_jk2, W_o1, W_o2);
    k12<<<nb128, 512, K12_SMEM>>>(feats, w_x, b_jk1, a_jk, b_jk2, a_main,
                                  w_ref, b_att, N);
    k3_fused<<<nb64, 512, K3_SMEM>>>(feats, b_o1, a_out, b_o2, out, N);
}

// round 9
// speedup vs baseline: 4.7537x; 1.0143x over previous
#include <cuda_runtime.h>
#include <cuda_bf16.h>
#include <cstdint>

#define HOPS 8
#define FDIM 128
#define HID  256
#define NCLS 64
#define NMAX 100096

typedef unsigned long long ull;

// ---------------- scratch (device globals; no runtime alloc) ----------------
__device__ float g_sx[(size_t)NMAX * HOPS];
__device__ float g_w [(size_t)NMAX * HOPS];
__device__ __nv_bfloat16 g_agg_hi[(size_t)NMAX * FDIM];
__device__ __nv_bfloat16 g_agg_lo[(size_t)NMAX * FDIM];
__device__ __nv_bfloat16 g_W1T_hi[(size_t)HID * 1024];   // [c][k]
__device__ __nv_bfloat16 g_W2T_hi[(size_t)HID * HID];
__device__ __nv_bfloat16 g_Wo1T_hi[(size_t)HID * FDIM];  // [c=256][k=128]
__device__ __nv_bfloat16 g_Wo1T_lo[(size_t)HID * FDIM];
__device__ __nv_bfloat16 g_Wo2T_hi[(size_t)NCLS * HID];  // [c=64][k=256]
__device__ __nv_bfloat16 g_Wo2T_lo[(size_t)NCLS * HID];

// ---------------- helpers ----------------
__device__ __forceinline__ uint32_t smem_u32(const void* p) {
    uint32_t a;
    asm("{ .reg .u64 t; cvta.to.shared.u64 t, %1; cvt.u32.u64 %0, t; }" : "=r"(a) : "l"(p));
    return a;
}
__device__ __forceinline__ void ldsm4(uint32_t* r, uint32_t addr) {
    asm volatile("ldmatrix.sync.aligned.m8n8.x4.shared.b16 {%0,%1,%2,%3}, [%4];"
        : "=r"(r[0]), "=r"(r[1]), "=r"(r[2]), "=r"(r[3]) : "r"(addr));
}
__device__ __forceinline__ void ldsm2(uint32_t* r, uint32_t addr) {
    asm volatile("ldmatrix.sync.aligned.m8n8.x2.shared.b16 {%0,%1}, [%2];"
        : "=r"(r[0]), "=r"(r[1]) : "r"(addr));
}
__device__ __forceinline__ void mma16816(float* c, const uint32_t* a, const uint32_t* b) {
    asm volatile("mma.sync.aligned.m16n8k16.row.col.f32.bf16.bf16.f32 "
        "{%0,%1,%2,%3}, {%4,%5,%6,%7}, {%8,%9}, {%0,%1,%2,%3};"
        : "+f"(c[0]), "+f"(c[1]), "+f"(c[2]), "+f"(c[3])
        : "r"(a[0]), "r"(a[1]), "r"(a[2]), "r"(a[3]), "r"(b[0]), "r"(b[1]));
}
#define CP_ASYNC16(dst, src) \
    asm volatile("cp.async.cg.shared.global [%0], [%1], 16;" :: "r"(dst), "l"(src))
#define CP_COMMIT() asm volatile("cp.async.commit_group;" ::: "memory")
#define CP_WAIT0()  asm volatile("cp.async.wait_group 0;" ::: "memory")

__device__ __forceinline__ float prelu_f(float v, float a) { return v >= 0.f ? v : a * v; }

union BfPair { uint32_t u; __nv_bfloat16 e[2]; };
union Bf8    { uint4 q;    __nv_bfloat16 e[8]; };

__device__ __forceinline__ uint32_t pack_bf16x2(float x0, float x1) {
    BfPair p;
    p.e[0] = __float2bfloat16(x0);
    p.e[1] = __float2bfloat16(x1);
    return p.u;
}
__device__ __forceinline__ void store_split2(__nv_bfloat16* hi, __nv_bfloat16* lo,
                                             size_t base, float x0, float x1) {
    BfPair ph, pl;
    ph.e[0] = __float2bfloat16(x0);
    ph.e[1] = __float2bfloat16(x1);
    pl.e[0] = __float2bfloat16(x0 - __bfloat162float(ph.e[0]));
    pl.e[1] = __float2bfloat16(x1 - __bfloat162float(ph.e[1]));
    *(uint32_t*)&hi[base] = ph.u;
    *(uint32_t*)&lo[base] = pl.u;
}

// ---------------------------------------------------------------------------
// k0: transpose weights. W1/W2 -> bf16 hi only; Wo1/Wo2 -> split hi/lo.
// ---------------------------------------------------------------------------
__global__ void k0_convert(const float* __restrict__ W1, const float* __restrict__ W2,
                           const float* __restrict__ Wo1, const float* __restrict__ Wo2)
{
    int idx = blockIdx.x * 1024 + threadIdx.x;
    if (idx < 262144) {                       // W1 [1024][256] hi only
        int k = idx >> 8, c = idx & 255;
        g_W1T_hi[(size_t)c * 1024 + k] = __float2bfloat16(W1[idx]);
        return;
    }
    if (idx < 327680) {                       // W2 [256][256] hi only
        int i = idx - 262144, k = i >> 8, c = i & 255;
        g_W2T_hi[(size_t)c * 256 + k] = __float2bfloat16(W2[i]);
        return;
    }
    float v; size_t dst; __nv_bfloat16* ph; __nv_bfloat16* pl;
    if (idx < 360448) {                       // Wo1 [128][256] split
        int i = idx - 327680, k = i >> 8, c = i & 255;
        v = Wo1[i]; dst = (size_t)c * 128 + k; ph = g_Wo1T_hi; pl = g_Wo1T_lo;
    } else if (idx < 376832) {                // Wo2 [256][64] split
        int i = idx - 360448, k = i >> 6, c = i & 63;
        v = Wo2[i]; dst = (size_t)c * 256 + k; ph = g_Wo2T_hi; pl = g_Wo2T_lo;
    } else return;
    __nv_bfloat16 h = __float2bfloat16(v);
    ph[dst] = h;
    pl[dst] = __float2bfloat16(v - __bfloat162float(h));
}

// ---------------------------------------------------------------------------
// k12: BM=64, 256 threads, 2 CTAs/SM (decoupled barrier domains).
// Stage = A 64x64 (pitch 144, 9216B) + B 256x64 (36864B) = 46080, x2.
// Phase 2: H 64x264 (pitch 528, 33792B) at 0, W2 chunk at 34816.
// ---------------------------------------------------------------------------
#define STG    46080
#define S_AH   0
#define S_BH   9216
#define HREG   0
#define B2H    34816
#define EX_WX   92160
#define EX_B1   92672
#define EX_B2   93696
#define EX_WR   94720
#define EX_SRED 95744
#define K12_SMEM 96768

__global__ __launch_bounds__(256, 2) void k12(
    const float* __restrict__ feats, const float* __restrict__ wx,
    const float* __restrict__ b1, const float* __restrict__ a_jk_p,
    const float* __restrict__ b2, const float* __restrict__ a_main_p,
    const float* __restrict__ w_ref, const float* __restrict__ b_att_p, int N)
{
    extern __shared__ char smraw[];
    const uint32_t sb = smem_u32(smraw);
    const int tid = threadIdx.x, wid = tid >> 5, lane = tid & 31;
    const int n0 = blockIdx.x * 64;
    const int wm = wid & 1, wn = wid >> 1;          // 2M x 4N warps, tile 32x64
    const int g = lane >> 2, tg = lane & 3;
    const int sxrow = tid >> 2;                     // s_x: 4 threads per row (64 rows)

    float* wxs  = (float*)(smraw + EX_WX);
    float* sb1  = (float*)(smraw + EX_B1);
    float* sb2  = (float*)(smraw + EX_B2);
    float* swr  = (float*)(smraw + EX_WR);
    float* sred = (float*)(smraw + EX_SRED);
    if (tid < 128) wxs[tid] = wx[tid];
    sb1[tid] = b1[tid];
    sb2[tid] = b2[tid];
    swr[tid] = w_ref[tid];

    float acc[2][8][4];
    #pragma unroll
    for (int a = 0; a < 2; ++a)
        #pragma unroll
        for (int b = 0; b < 8; ++b)
            #pragma unroll
            for (int c = 0; c < 4; ++c) acc[a][b][c] = 0.f;

    const uint32_t aoff_c = (uint32_t)(wm * 32 + (lane & 15)) * 144
                          + (uint32_t)((lane >> 4) * 8) * 2;
    const int brow = (lane & 7) + ((lane >> 4) << 3);
    const int bko  = ((lane >> 3) & 1) * 8;
    const uint32_t boff_c = (uint32_t)(wn * 64 + brow) * 144 + (uint32_t)bko * 2;

    // ---------------- Phase 1: 16 K-chunks of 64, double-buffered ----------------
    float4 areg[4];
    {   // prologue: chunk 0
        #pragma unroll
        for (int i = 0; i < 4; ++i) {
            int idx = i * 256 + tid;
            int r = idx >> 4, cq = (idx & 15) << 2;
            int n = n0 + r; if (n > N - 1) n = N - 1;
            areg[i] = *(const float4*)(feats + (size_t)n * FDIM + cq);
        }
        #pragma unroll
        for (int i = 0; i < 8; ++i) {
            int idx = i * 256 + tid;
            int r = idx >> 3, c8 = (idx & 7) << 3;
            CP_ASYNC16(sb + S_BH + r * 144 + c8 * 2, g_W1T_hi + (size_t)r * 1024 + c8);
        }
        CP_COMMIT();
        #pragma unroll
        for (int i = 0; i < 4; ++i) {
            int idx = i * 256 + tid;
            int r = idx >> 4, cq = (idx & 15) << 2;
            ull u = (ull)pack_bf16x2(areg[i].x, areg[i].y)
                  | ((ull)pack_bf16x2(areg[i].z, areg[i].w) << 32);
            *(ull*)(smraw + S_AH + r * 144 + cq * 2) = u;
        }
    }

    float sx0 = 0.f, sx1 = 0.f;

    for (int chunk = 0; chunk < 16; ++chunk) {
        const uint32_t sbase = (uint32_t)(chunk & 1) * STG;
        const int hop = chunk >> 1, f0 = (chunk & 1) << 6;

        CP_WAIT0();
        __syncthreads();

        if (chunk < 15) {
            const int cn = chunk + 1;
            const uint32_t nbase = (uint32_t)(cn & 1) * STG;
            const int c0n = cn << 6;
            #pragma unroll
            for (int i = 0; i < 8; ++i) {
                int idx = i * 256 + tid;
                int r = idx >> 3, c8 = (idx & 7) << 3;
                CP_ASYNC16(sb + nbase + S_BH + r * 144 + c8 * 2,
                           g_W1T_hi + (size_t)r * 1024 + c0n + c8);
            }
            CP_COMMIT();
            const int hop_n = cn >> 1, f0_n = (cn & 1) << 6;
            const float* fbn = feats + (size_t)hop_n * N * FDIM + f0_n;
            #pragma unroll
            for (int i = 0; i < 4; ++i) {
                int idx = i * 256 + tid;
                int r = idx >> 4, cq = (idx & 15) << 2;
                int n = n0 + r; if (n > N - 1) n = N - 1;
                areg[i] = *(const float4*)(fbn + (size_t)n * FDIM + cq);
            }
        }

        {   // fused s_x: 4 threads/row, 16 cols each
            const char* bh = smraw + sbase + S_AH + sxrow * 144 + tg * 32;
            #pragma unroll
            for (int q = 0; q < 2; ++q) {
                Bf8 qh;
                qh.q = *(const uint4*)(bh + q * 16);
                const float* wp = wxs + f0 + tg * 16 + q * 8;
                sx0 += __bfloat162float(qh.e[0]) * wp[0] + __bfloat162float(qh.e[2]) * wp[2]
                     + __bfloat162float(qh.e[4]) * wp[4] + __bfloat162float(qh.e[6]) * wp[6];
                sx1 += __bfloat162float(qh.e[1]) * wp[1] + __bfloat162float(qh.e[3]) * wp[3]
                     + __bfloat162float(qh.e[5]) * wp[5] + __bfloat162float(qh.e[7]) * wp[7];
            }
        }

        const uint32_t aH = sb + sbase + S_AH + aoff_c;
        const uint32_t bH = sb + sbase + S_BH + boff_c;
        #pragma unroll
        for (int ks = 0; ks < 4; ++ks) {
            uint32_t ah[2][4];
            ldsm4(ah[0], aH + ks * 32);
            ldsm4(ah[1], aH + 16 * 144 + ks * 32);
            #pragma unroll
            for (int ntp = 0; ntp < 4; ++ntp) {
                uint32_t bhf[4];
                ldsm4(bhf, bH + ntp * 16 * 144 + ks * 32);
                #pragma unroll
                for (int mt = 0; mt < 2; ++mt) {
                    mma16816(acc[mt][ntp * 2],     ah[mt], bhf);
                    mma16816(acc[mt][ntp * 2 + 1], ah[mt], bhf + 2);
                }
            }
        }

        if (chunk < 15) {   // convert + store A(next) into next stage
            const uint32_t nbase = (uint32_t)((chunk + 1) & 1) * STG;
            #pragma unroll
            for (int i = 0; i < 4; ++i) {
                int idx = i * 256 + tid;
                int r = idx >> 4, cq = (idx & 15) << 2;
                ull u = (ull)pack_bf16x2(areg[i].x, areg[i].y)
                      | ((ull)pack_bf16x2(areg[i].z, areg[i].w) << 32);
                *(ull*)(smraw + nbase + S_AH + r * 144 + cq * 2) = u;
            }
        }

        if (chunk & 1) {
            float s = sx0 + sx1;
            s += __shfl_xor_sync(0xffffffffu, s, 1);
            s += __shfl_xor_sync(0xffffffffu, s, 2);
            if (tg == 0 && n0 + sxrow < N)
                g_sx[(size_t)(n0 + sxrow) * HOPS + hop] = s;
            sx0 = sx1 = 0.f;
        }
    }
    __syncthreads();

    // ---------------- epilogue 1: bias + prelu -> H bf16 tile in smem ----------------
    {
        const float a_jk = *a_jk_p;
        __nv_bfloat16* hh = (__nv_bfloat16*)(smraw + HREG);
        #pragma unroll
        for (int mt = 0; mt < 2; ++mt) {
            const int r = wm * 32 + mt * 16 + g;
            #pragma unroll
            for (int nt = 0; nt < 8; ++nt) {
                const int c = wn * 64 + nt * 8 + tg * 2;
                const float b0v = sb1[c], b1v = sb1[c + 1];
                float x0 = prelu_f(acc[mt][nt][0] + b0v, a_jk);
                float x1 = prelu_f(acc[mt][nt][1] + b1v, a_jk);
                float x2 = prelu_f(acc[mt][nt][2] + b0v, a_jk);
                float x3 = prelu_f(acc[mt][nt][3] + b1v, a_jk);
                *(uint32_t*)&hh[(size_t)r * 264 + c]       = pack_bf16x2(x0, x1);
                *(uint32_t*)&hh[(size_t)(r + 8) * 264 + c] = pack_bf16x2(x2, x3);
            }
        }
    }

    #pragma unroll
    for (int a = 0; a < 2; ++a)
        #pragma unroll
        for (int b = 0; b < 8; ++b)
            #pragma unroll
            for (int c = 0; c < 4; ++c) acc[a][b][c] = 0.f;

    // ---------------- Phase 2: jk = H @ W2, K=256 in 4 chunks ----------------
    const uint32_t a2H = sb + HREG + (uint32_t)(wm * 32 + (lane & 15)) * 528
                       + (uint32_t)((lane >> 4) * 8) * 2;
    const uint32_t b2f = sb + B2H + boff_c;

    for (int c2 = 0; c2 < 4; ++c2) {
        __syncthreads();
        const int c0 = c2 << 6;
        #pragma unroll
        for (int i = 0; i < 8; ++i) {
            int idx = i * 256 + tid;
            int r = idx >> 3, c8 = (idx & 7) << 3;
            CP_ASYNC16(sb + B2H + r * 144 + c8 * 2,
                       g_W2T_hi + (size_t)r * 256 + c0 + c8);
        }
        CP_COMMIT();
        CP_WAIT0();
        __syncthreads();

        #pragma unroll
        for (int ks = 0; ks < 4; ++ks) {
            const uint32_t ko = (uint32_t)(c0 + ks * 16) * 2;
            uint32_t ah[2][4];
            ldsm4(ah[0], a2H + ko);
            ldsm4(ah[1], a2H + 16 * 528 + ko);
            #pragma unroll
            for (int ntp = 0; ntp < 4; ++ntp) {
                uint32_t bhf[4];
                ldsm4(bhf, b2f + ntp * 16 * 144 + ks * 32);
                #pragma unroll
                for (int mt = 0; mt < 2; ++mt) {
                    mma16816(acc[mt][ntp * 2],     ah[mt], bhf);
                    mma16816(acc[mt][ntp * 2 + 1], ah[mt], bhf + 2);
                }
            }
        }
    }

    // ---------------- epilogue 2: prelu -> dot(w_ref) -> softmax(sigmoid) ----------------
    const float a_main = *a_main_p;
    float part[2][2] = {{0.f, 0.f}, {0.f, 0.f}};
    #pragma unroll
    for (int mt = 0; mt < 2; ++mt) {
        #pragma unroll
        for (int nt = 0; nt < 8; ++nt) {
            const int c = wn * 64 + nt * 8 + tg * 2;
            const float w0 = swr[c], w1 = swr[c + 1];
            const float bb0 = sb2[c], bb1 = sb2[c + 1];
            part[mt][0] += prelu_f(acc[mt][nt][0] + bb0, a_main) * w0
                         + prelu_f(acc[mt][nt][1] + bb1, a_main) * w1;
            part[mt][1] += prelu_f(acc[mt][nt][2] + bb0, a_main) * w0
                         + prelu_f(acc[mt][nt][3] + bb1, a_main) * w1;
        }
    }
    #pragma unroll
    for (int mt = 0; mt < 2; ++mt)
        #pragma unroll
        for (int h = 0; h < 2; ++h) {
            part[mt][h] += __shfl_xor_sync(0xffffffffu, part[mt][h], 1);
            part[mt][h] += __shfl_xor_sync(0xffffffffu, part[mt][h], 2);
        }
    __syncthreads();
    if (tg == 0) {
        #pragma unroll
        for (int mt = 0; mt < 2; ++mt) {
            const int r = wm * 32 + mt * 16 + g;
            sred[r * 4 + wn]       = part[mt][0];
            sred[(r + 8) * 4 + wn] = part[mt][1];
        }
    }
    __syncthreads();

    if (tid < 64) {
        const int n = n0 + tid;
        if (n < N) {
            const float sref = sred[tid * 4] + sred[tid * 4 + 1]
                             + sred[tid * 4 + 2] + sred[tid * 4 + 3] + *b_att_p;
            const float* sxp = g_sx + (size_t)n * HOPS;
            float s[HOPS];
            float m = -1e30f;
            #pragma unroll
            for (int h = 0; h < HOPS; ++h) {
                float z = sxp[h] + sref;
                s[h] = 1.f / (1.f + expf(-z));
                m = fmaxf(m, s[h]);
            }
            float sum = 0.f;
            #pragma unroll
            for (int h = 0; h < HOPS; ++h) { s[h] = expf(s[h] - m); sum += s[h]; }
            const float inv = 1.f / sum;
            float* d = g_w + (size_t)n * HOPS;
            *(float4*)(d + 0) = make_float4(s[0] * inv, s[1] * inv, s[2] * inv, s[3] * inv);
            *(float4*)(d + 4) = make_float4(s[4] * inv, s[5] * inv, s[6] * inv, s[7] * inv);
        }
    }
}

// ---------------------------------------------------------------------------
// k3a: agg[n][f] = sum_h g_w[n][h] * feats[h][n][f]  -> split bf16 global.
// High-occupancy standalone (aggregation needs MLP, not fusion).
// ---------------------------------------------------------------------------
__global__ __launch_bounds__(256) void k3a_agg(const float* __restrict__ feats, int N)
{
    int idx = blockIdx.x * 256 + threadIdx.x;
    if (idx >= N * 32) return;
    const int n = idx >> 5, f = (idx & 31) << 2;

    float4 w0 = *(const float4*)(g_w + (size_t)n * HOPS);
    float4 w1 = *(const float4*)(g_w + (size_t)n * HOPS + 4);
    const float wv[8] = {w0.x, w0.y, w0.z, w0.w, w1.x, w1.y, w1.z, w1.w};

    float ax = 0.f, ay = 0.f, az = 0.f, aw = 0.f;
    #pragma unroll
    for (int hop = 0; hop < HOPS; ++hop) {
        const float4 v = *(const float4*)(feats + (size_t)hop * N * FDIM
                                                + (size_t)n * FDIM + f);
        ax += wv[hop] * v.x; ay += wv[hop] * v.y;
        az += wv[hop] * v.z; aw += wv[hop] * v.w;
    }
    store_split2(g_agg_hi, g_agg_lo, (size_t)n * FDIM + f,     ax, ay);
    store_split2(g_agg_hi, g_agg_lo, (size_t)n * FDIM + f + 2, az, aw);
}

// ---------------------------------------------------------------------------
// k3b: out = prelu(agg@Wo1+bo1, a_out) @ Wo2 + bo2.  512 thr, BM=64.
// Pipelined: FFN1 4 dbl-buf K-chunks of 32 (pitch 80); FFN2 4 dbl-buf of 64.
// ---------------------------------------------------------------------------
#define K3_AGH 0
#define K3_AGL 17408
#define K3_TH  34816
#define K3_TL  68608
#define K3_BB  102400
#define K3_SMEM 184320

__global__ __launch_bounds__(512, 1) void k3b_out(
    const float* __restrict__ bo1, const float* __restrict__ a_out_p,
    const float* __restrict__ bo2, float* __restrict__ out, int N)
{
    extern __shared__ char smraw[];
    const uint32_t sb = smem_u32(smraw);
    const int tid = threadIdx.x, wid = tid >> 5, lane = tid & 31;
    const int n0 = blockIdx.x * 64;
    const int g = lane >> 2, tg = lane & 3;
    const int wm = wid & 1, wn = wid >> 1;   // 2M x 8N

    // ---- prologue: agg tile + FFN1 chunk0 cp.async, single group ----
    #pragma unroll
    for (int i = 0; i < 2; ++i) {
        int idx = i * 512 + tid;
        int r = idx >> 4, c8 = (idx & 15) << 3;
        int n = n0 + r; if (n > N - 1) n = N - 1;
        CP_ASYNC16(sb + K3_AGH + r * 272 + c8 * 2, g_agg_hi + (size_t)n * FDIM + c8);
        CP_ASYNC16(sb + K3_AGL + r * 272 + c8 * 2, g_agg_lo + (size_t)n * FDIM + c8);
    }
    #pragma unroll
    for (int i = 0; i < 2; ++i) {
        int idx = i * 512 + tid;
        int r = idx >> 2, c8 = (idx & 3) << 3;
        CP_ASYNC16(sb + K3_BB + r * 80 + c8 * 2,
                   g_Wo1T_hi + (size_t)r * 128 + c8);
        CP_ASYNC16(sb + K3_BB + 20480 + r * 80 + c8 * 2,
                   g_Wo1T_lo + (size_t)r * 128 + c8);
    }
    CP_COMMIT();

    const int brow = (lane & 7) + ((lane >> 4) << 3);
    const int bko  = ((lane >> 3) & 1) * 8;

    // ---- FFN1: t = prelu(agg[64x128] @ Wo1 + bo1); 4 chunks of k=32, dbl-buf ----
    {
        float acc1[2][4][4];
        #pragma unroll
        for (int a = 0; a < 2; ++a)
            #pragma unroll
            for (int b = 0; b < 4; ++b)
                #pragma unroll
                for (int c = 0; c < 4; ++c) acc1[a][b][c] = 0.f;

        const uint32_t aoffH = sb + K3_AGH + (uint32_t)(wm * 32 + (lane & 15)) * 272
                             + (uint32_t)((lane >> 4) * 8) * 2;
        const uint32_t aoffL = aoffH + (K3_AGL - K3_AGH);
        const uint32_t bfrag = (uint32_t)(wn * 32 + brow) * 80 + (uint32_t)bko * 2;

        for (int c = 0; c < 4; ++c) {
            CP_WAIT0();
            __syncthreads();
            if (c < 3) {
                const int cn = c + 1;
                const uint32_t nb = sb + K3_BB + (uint32_t)(cn & 1) * 40960;
                #pragma unroll
                for (int i = 0; i < 2; ++i) {
                    int idx = i * 512 + tid;
                    int r = idx >> 2, c8 = (idx & 3) << 3;
                    CP_ASYNC16(nb + r * 80 + c8 * 2,
                               g_Wo1T_hi + (size_t)r * 128 + cn * 32 + c8);
                    CP_ASYNC16(nb + 20480 + r * 80 + c8 * 2,
                               g_Wo1T_lo + (size_t)r * 128 + cn * 32 + c8);
                }
                CP_COMMIT();
            }
            const uint32_t bH = sb + K3_BB + (uint32_t)(c & 1) * 40960 + bfrag;
            const uint32_t bL = bH + 20480;
            #pragma unroll
            for (int ks = 0; ks < 2; ++ks) {
                const int kglob = c * 32 + ks * 16;
                uint32_t ah[2][4], al[2][4];
                ldsm4(ah[0], aoffH + kglob * 2);
                ldsm4(ah[1], aoffH + 16 * 272 + kglob * 2);
                ldsm4(al[0], aoffL + kglob * 2);
                ldsm4(al[1], aoffL + 16 * 272 + kglob * 2);
                #pragma unroll
                for (int ntp = 0; ntp < 2; ++ntp) {
                    uint32_t bh[4], bl[4];
                    ldsm4(bh, bH + ntp * 16 * 80 + ks * 32);
                    ldsm4(bl, bL + ntp * 16 * 80 + ks * 32);
                    #pragma unroll
                    for (int mt = 0; mt < 2; ++mt) {
                        mma16816(acc1[mt][ntp * 2],     ah[mt], bh);
                        mma16816(acc1[mt][ntp * 2],     ah[mt], bl);
                        mma16816(acc1[mt][ntp * 2],     al[mt], bh);
                        mma16816(acc1[mt][ntp * 2 + 1], ah[mt], bh + 2);
                        mma16816(acc1[mt][ntp * 2 + 1], ah[mt], bl + 2);
                        mma16816(acc1[mt][ntp * 2 + 1], al[mt], bh + 2);
                    }
                }
            }
        }
        __syncthreads();   // all FFN1 MMAs done -> BB reusable

        // kick FFN2 chunk0 load (overlaps t epilogue)
        {
            int r = tid >> 3, c8 = (tid & 7) << 3;
            CP_ASYNC16(sb + K3_BB + r * 144 + c8 * 2,
                       g_Wo2T_hi + (size_t)r * 256 + c8);
            CP_ASYNC16(sb + K3_BB + 9216 + r * 144 + c8 * 2,
                       g_Wo2T_lo + (size_t)r * 256 + c8);
        }
        CP_COMMIT();

        const float a_out = *a_out_p;
        __nv_bfloat16* th = (__nv_bfloat16*)(smraw + K3_TH);
        __nv_bfloat16* tl = (__nv_bfloat16*)(smraw + K3_TL);
        #pragma unroll
        for (int mt = 0; mt < 2; ++mt) {
            const int r = wm * 32 + mt * 16 + g;
            #pragma unroll
            for (int nt = 0; nt < 4; ++nt) {
                const int c = wn * 32 + nt * 8 + tg * 2;
                const float b0v = __ldg(&bo1[c]), b1v = __ldg(&bo1[c + 1]);
                float x0 = prelu_f(acc1[mt][nt][0] + b0v, a_out);
                float x1 = prelu_f(acc1[mt][nt][1] + b1v, a_out);
                float x2 = prelu_f(acc1[mt][nt][2] + b0v, a_out);
                float x3 = prelu_f(acc1[mt][nt][3] + b1v, a_out);
                store_split2(th, tl, (size_t)r * 264 + c, x0, x1);
                store_split2(th, tl, (size_t)(r + 8) * 264 + c, x2, x3);
            }
        }
    }

    // ---- FFN2: out = t[64x256] @ Wo2 + bo2; 4 chunks of k=64, dbl-buf ----
    {
        float acc2[2][4];
        #pragma unroll
        for (int a = 0; a < 2; ++a)
            #pragma unroll
            for (int c = 0; c < 4; ++c) acc2[a][c] = 0.f;

        const uint32_t aoffH = sb + K3_TH + (uint32_t)(wm * 32 + (lane & 15)) * 528
                             + (uint32_t)((lane >> 4) * 8) * 2;
        const uint32_t aoffL = aoffH + (K3_TL - K3_TH);
        const int l16 = lane & 15;
        const uint32_t bfrag2 = (uint32_t)(wn * 8 + (l16 & 7)) * 144
                              + (uint32_t)((l16 >> 3) * 16);

        for (int ch = 0; ch < 4; ++ch) {
            CP_WAIT0();
            __syncthreads();
            if (ch < 3) {
                const int cn = ch + 1;
                const uint32_t nb = sb + K3_BB + (uint32_t)(cn & 1) * 18432;
                int r = tid >> 3, c8 = (tid & 7) << 3;
                CP_ASYNC16(nb + r * 144 + c8 * 2,
                           g_Wo2T_hi + (size_t)r * 256 + cn * 64 + c8);
                CP_ASYNC16(nb + 9216 + r * 144 + c8 * 2,
                           g_Wo2T_lo + (size_t)r * 256 + cn * 64 + c8);
                CP_COMMIT();
            }
            const uint32_t bH = sb + K3_BB + (uint32_t)(ch & 1) * 18432 + bfrag2;
            const uint32_t bL = bH + 9216;
            #pragma unroll
            for (int ks = 0; ks < 4; ++ks) {
                const int kglob = ch * 64 + ks * 16;
                uint32_t ah[2][4], al[2][4], bh[2], bl[2];
                ldsm4(ah[0], aoffH + kglob * 2);
                ldsm4(ah[1], aoffH + 16 * 528 + kglob * 2);
                ldsm4(al[0], aoffL + kglob * 2);
                ldsm4(al[1], aoffL + 16 * 528 + kglob * 2);
                ldsm2(bh, bH + ks * 32);
                ldsm2(bl, bL + ks * 32);
                #pragma unroll
                for (int mt = 0; mt < 2; ++mt) {
                    mma16816(acc2[mt], ah[mt], bh);
                    mma16816(acc2[mt], ah[mt], bl);
                    mma16816(acc2[mt], al[mt], bh);
                }
            }
        }

        const int c = wn * 8 + tg * 2;
        const float b0v = __ldg(&bo2[c]), b1v = __ldg(&bo2[c + 1]);
        #pragma unroll
        for (int mt = 0; mt < 2; ++mt) {
            const int n = n0 + wm * 32 + mt * 16 + g;
            if (n < N) {
                float2 o = make_float2(acc2[mt][0] + b0v, acc2[mt][1] + b1v);
                *(float2*)&out[(size_t)n * NCLS + c] = o;
            }
            if (n + 8 < N) {
                float2 o = make_float2(acc2[mt][2] + b0v, acc2[mt][3] + b1v);
                *(float2*)&out[(size_t)(n + 8) * NCLS + c] = o;
            }
        }
    }
}

// ---------------------------------------------------------------------------
extern "C" void kernel_launch(void* const* d_in, const int* in_sizes, int n_in,
                              void* d_out, int out_size)
{
    const float* feats  = (const float*)d_in[0];
    const float* W_jk1  = (const float*)d_in[1];
    const float* b_jk1  = (const float*)d_in[2];
    const float* W_jk2  = (const float*)d_in[3];
    const float* b_jk2  = (const float*)d_in[4];
    const float* a_jk   = (const float*)d_in[5];
    const float* a_main = (const float*)d_in[6];
    const float* a_out  = (const float*)d_in[7];
    const float* w_ref  = (const float*)d_in[8];
    const float* w_x    = (const float*)d_in[9];
    const float* b_att  = (const float*)d_in[10];
    const float* W_o1   = (const float*)d_in[11];
    const float* b_o1   = (const float*)d_in[12];
    const float* W_o2   = (const float*)d_in[13];
    const float* b_o2   = (const float*)d_in[14];
    float* out = (float*)d_out;

    const int N = in_sizes[0] / (HOPS * FDIM);
    const int nb64 = (N + 63) / 64;

    cudaFuncSetAttribute(k12,     cudaFuncAttributeMaxDynamicSharedMemorySize, K12_SMEM);
    cudaFuncSetAttribute(k3b_out, cudaFuncAttributeMaxDynamicSharedMemorySize, K3_SMEM);

    k0_convert<<<368, 1024>>>(W_jk1, W_jk2, W_o1, W_o2);
    k12<<<nb64, 256, K12_SMEM>>>(feats, w_x, b_jk1, a_jk, b_jk2, a_main,
                                 w_ref, b_att, N);
    k3a_agg<<<(N * 32 + 255) / 256, 256>>>(feats, N);
    k3b_out<<<nb64, 512, K3_SMEM>>>(b_o1, a_out, b_o2, out, N);
}

// round 10
// speedup vs baseline: 4.9849x; 1.0486x over previous
#include <cuda_runtime.h>
#include <cuda_bf16.h>
#include <cuda_fp16.h>
#include <cstdint>

#define HOPS 8
#define FDIM 128
#define HID  256
#define NCLS 64
#define NMAX 100096

typedef unsigned long long ull;

// ---------------- scratch (device globals; no runtime alloc) ----------------
__device__ float g_sx[(size_t)NMAX * HOPS];
__device__ float g_w [(size_t)NMAX * HOPS];
__device__ __half g_agg[(size_t)NMAX * FDIM];
__device__ __nv_bfloat16 g_W1T_hi[(size_t)HID * 1024];   // [c][k]
__device__ __nv_bfloat16 g_W2T_hi[(size_t)HID * HID];
__device__ __half g_Wo1T_h[(size_t)HID * FDIM];          // [c=256][k=128]
__device__ __half g_Wo2T_h[(size_t)NCLS * HID];          // [c=64][k=256]

// ---------------- helpers ----------------
__device__ __forceinline__ uint32_t smem_u32(const void* p) {
    uint32_t a;
    asm("{ .reg .u64 t; cvta.to.shared.u64 t, %1; cvt.u32.u64 %0, t; }" : "=r"(a) : "l"(p));
    return a;
}
__device__ __forceinline__ void ldsm4(uint32_t* r, uint32_t addr) {
    asm volatile("ldmatrix.sync.aligned.m8n8.x4.shared.b16 {%0,%1,%2,%3}, [%4];"
        : "=r"(r[0]), "=r"(r[1]), "=r"(r[2]), "=r"(r[3]) : "r"(addr));
}
__device__ __forceinline__ void mma16816(float* c, const uint32_t* a, const uint32_t* b) {
    asm volatile("mma.sync.aligned.m16n8k16.row.col.f32.bf16.bf16.f32 "
        "{%0,%1,%2,%3}, {%4,%5,%6,%7}, {%8,%9}, {%0,%1,%2,%3};"
        : "+f"(c[0]), "+f"(c[1]), "+f"(c[2]), "+f"(c[3])
        : "r"(a[0]), "r"(a[1]), "r"(a[2]), "r"(a[3]), "r"(b[0]), "r"(b[1]));
}
__device__ __forceinline__ void mma16816h(float* c, const uint32_t* a, const uint32_t* b) {
    asm volatile("mma.sync.aligned.m16n8k16.row.col.f32.f16.f16.f32 "
        "{%0,%1,%2,%3}, {%4,%5,%6,%7}, {%8,%9}, {%0,%1,%2,%3};"
        : "+f"(c[0]), "+f"(c[1]), "+f"(c[2]), "+f"(c[3])
        : "r"(a[0]), "r"(a[1]), "r"(a[2]), "r"(a[3]), "r"(b[0]), "r"(b[1]));
}
#define CP_ASYNC16(dst, src) \
    asm volatile("cp.async.cg.shared.global [%0], [%1], 16;" :: "r"(dst), "l"(src))
#define CP_COMMIT() asm volatile("cp.async.commit_group;" ::: "memory")
#define CP_WAIT0()  asm volatile("cp.async.wait_group 0;" ::: "memory")

__device__ __forceinline__ float prelu_f(float v, float a) { return v >= 0.f ? v : a * v; }

union BfPair { uint32_t u; __nv_bfloat16 e[2]; };
union Bf8    { uint4 q;    __nv_bfloat16 e[8]; };

__device__ __forceinline__ uint32_t pack_bf16x2(float x0, float x1) {
    BfPair p;
    p.e[0] = __float2bfloat16(x0);
    p.e[1] = __float2bfloat16(x1);
    return p.u;
}
__device__ __forceinline__ uint32_t pack_half2(float x0, float x1) {
    __half2 h = __floats2half2_rn(x0, x1);
    return *(uint32_t*)&h;
}

// ---------------------------------------------------------------------------
// k0: transpose weights. W1/W2 -> bf16; Wo1/Wo2 -> fp16 (1-pass output path).
// ---------------------------------------------------------------------------
__global__ void k0_convert(const float* __restrict__ W1, const float* __restrict__ W2,
                           const float* __restrict__ Wo1, const float* __restrict__ Wo2)
{
    int idx = blockIdx.x * 1024 + threadIdx.x;
    if (idx < 262144) {                       // W1 [1024][256]
        int k = idx >> 8, c = idx & 255;
        g_W1T_hi[(size_t)c * 1024 + k] = __float2bfloat16(W1[idx]);
        return;
    }
    if (idx < 327680) {                       // W2 [256][256]
        int i = idx - 262144, k = i >> 8, c = i & 255;
        g_W2T_hi[(size_t)c * 256 + k] = __float2bfloat16(W2[i]);
        return;
    }
    if (idx < 360448) {                       // Wo1 [128][256] -> fp16
        int i = idx - 327680, k = i >> 8, c = i & 255;
        g_Wo1T_h[(size_t)c * 128 + k] = __float2half_rn(Wo1[i]);
        return;
    }
    if (idx < 376832) {                       // Wo2 [256][64] -> fp16
        int i = idx - 360448, k = i >> 6, c = i & 63;
        g_Wo2T_h[(size_t)c * 256 + k] = __float2half_rn(Wo2[i]);
    }
}

// ---------------------------------------------------------------------------
// k12: BM=64, 256 threads, 2 CTAs/SM.  Phase-2 W2 chunks double-buffered.
// ---------------------------------------------------------------------------
#define STG    46080
#define S_AH   0
#define S_BH   9216
#define HREG   0
#define B2H    34816
#define EX_WX   108544
#define EX_B1   109056
#define EX_B2   110080
#define EX_WR   111104
#define EX_SRED 112128
#define K12_SMEM 113152

__global__ __launch_bounds__(256, 2) void k12(
    const float* __restrict__ feats, const float* __restrict__ wx,
    const float* __restrict__ b1, const float* __restrict__ a_jk_p,
    const float* __restrict__ b2, const float* __restrict__ a_main_p,
    const float* __restrict__ w_ref, const float* __restrict__ b_att_p, int N)
{
    extern __shared__ char smraw[];
    const uint32_t sb = smem_u32(smraw);
    const int tid = threadIdx.x, wid = tid >> 5, lane = tid & 31;
    const int n0 = blockIdx.x * 64;
    const int wm = wid & 1, wn = wid >> 1;          // 2M x 4N warps, tile 32x64
    const int g = lane >> 2, tg = lane & 3;
    const int sxrow = tid >> 2;

    float* wxs  = (float*)(smraw + EX_WX);
    float* sb1  = (float*)(smraw + EX_B1);
    float* sb2  = (float*)(smraw + EX_B2);
    float* swr  = (float*)(smraw + EX_WR);
    float* sred = (float*)(smraw + EX_SRED);
    if (tid < 128) wxs[tid] = wx[tid];
    sb1[tid] = b1[tid];
    sb2[tid] = b2[tid];
    swr[tid] = w_ref[tid];

    float acc[2][8][4];
    #pragma unroll
    for (int a = 0; a < 2; ++a)
        #pragma unroll
        for (int b = 0; b < 8; ++b)
            #pragma unroll
            for (int c = 0; c < 4; ++c) acc[a][b][c] = 0.f;

    const uint32_t aoff_c = (uint32_t)(wm * 32 + (lane & 15)) * 144
                          + (uint32_t)((lane >> 4) * 8) * 2;
    const int brow = (lane & 7) + ((lane >> 4) << 3);
    const int bko  = ((lane >> 3) & 1) * 8;
    const uint32_t boff_c = (uint32_t)(wn * 64 + brow) * 144 + (uint32_t)bko * 2;

    // ---------------- Phase 1: 16 K-chunks of 64, double-buffered ----------------
    float4 areg[4];
    {
        #pragma unroll
        for (int i = 0; i < 4; ++i) {
            int idx = i * 256 + tid;
            int r = idx >> 4, cq = (idx & 15) << 2;
            int n = n0 + r; if (n > N - 1) n = N - 1;
            areg[i] = *(const float4*)(feats + (size_t)n * FDIM + cq);
        }
        #pragma unroll
        for (int i = 0; i < 8; ++i) {
            int idx = i * 256 + tid;
            int r = idx >> 3, c8 = (idx & 7) << 3;
            CP_ASYNC16(sb + S_BH + r * 144 + c8 * 2, g_W1T_hi + (size_t)r * 1024 + c8);
        }
        CP_COMMIT();
        #pragma unroll
        for (int i = 0; i < 4; ++i) {
            int idx = i * 256 + tid;
            int r = idx >> 4, cq = (idx & 15) << 2;
            ull u = (ull)pack_bf16x2(areg[i].x, areg[i].y)
                  | ((ull)pack_bf16x2(areg[i].z, areg[i].w) << 32);
            *(ull*)(smraw + S_AH + r * 144 + cq * 2) = u;
        }
    }

    float sx0 = 0.f, sx1 = 0.f;

    for (int chunk = 0; chunk < 16; ++chunk) {
        const uint32_t sbase = (uint32_t)(chunk & 1) * STG;
        const int hop = chunk >> 1, f0 = (chunk & 1) << 6;

        CP_WAIT0();
        __syncthreads();

        if (chunk < 15) {
            const int cn = chunk + 1;
            const uint32_t nbase = (uint32_t)(cn & 1) * STG;
            const int c0n = cn << 6;
            #pragma unroll
            for (int i = 0; i < 8; ++i) {
                int idx = i * 256 + tid;
                int r = idx >> 3, c8 = (idx & 7) << 3;
                CP_ASYNC16(sb + nbase + S_BH + r * 144 + c8 * 2,
                           g_W1T_hi + (size_t)r * 1024 + c0n + c8);
            }
            CP_COMMIT();
            const int hop_n = cn >> 1, f0_n = (cn & 1) << 6;
            const float* fbn = feats + (size_t)hop_n * N * FDIM + f0_n;
            #pragma unroll
            for (int i = 0; i < 4; ++i) {
                int idx = i * 256 + tid;
                int r = idx >> 4, cq = (idx & 15) << 2;
                int n = n0 + r; if (n > N - 1) n = N - 1;
                areg[i] = *(const float4*)(fbn + (size_t)n * FDIM + cq);
            }
        }

        {   // fused s_x: 4 threads/row, 16 cols each
            const char* bh = smraw + sbase + S_AH + sxrow * 144 + tg * 32;
            #pragma unroll
            for (int q = 0; q < 2; ++q) {
                Bf8 qh;
                qh.q = *(const uint4*)(bh + q * 16);
                const float* wp = wxs + f0 + tg * 16 + q * 8;
                sx0 += __bfloat162float(qh.e[0]) * wp[0] + __bfloat162float(qh.e[2]) * wp[2]
                     + __bfloat162float(qh.e[4]) * wp[4] + __bfloat162float(qh.e[6]) * wp[6];
                sx1 += __bfloat162float(qh.e[1]) * wp[1] + __bfloat162float(qh.e[3]) * wp[3]
                     + __bfloat162float(qh.e[5]) * wp[5] + __bfloat162float(qh.e[7]) * wp[7];
            }
        }

        const uint32_t aH = sb + sbase + S_AH + aoff_c;
        const uint32_t bH = sb + sbase + S_BH + boff_c;
        #pragma unroll
        for (int ks = 0; ks < 4; ++ks) {
            uint32_t ah[2][4];
            ldsm4(ah[0], aH + ks * 32);
            ldsm4(ah[1], aH + 16 * 144 + ks * 32);
            #pragma unroll
            for (int ntp = 0; ntp < 4; ++ntp) {
                uint32_t bhf[4];
                ldsm4(bhf, bH + ntp * 16 * 144 + ks * 32);
                #pragma unroll
                for (int mt = 0; mt < 2; ++mt) {
                    mma16816(acc[mt][ntp * 2],     ah[mt], bhf);
                    mma16816(acc[mt][ntp * 2 + 1], ah[mt], bhf + 2);
                }
            }
        }

        if (chunk < 15) {
            const uint32_t nbase = (uint32_t)((chunk + 1) & 1) * STG;
            #pragma unroll
            for (int i = 0; i < 4; ++i) {
                int idx = i * 256 + tid;
                int r = idx >> 4, cq = (idx & 15) << 2;
                ull u = (ull)pack_bf16x2(areg[i].x, areg[i].y)
                      | ((ull)pack_bf16x2(areg[i].z, areg[i].w) << 32);
                *(ull*)(smraw + nbase + S_AH + r * 144 + cq * 2) = u;
            }
        }

        if (chunk & 1) {
            float s = sx0 + sx1;
            s += __shfl_xor_sync(0xffffffffu, s, 1);
            s += __shfl_xor_sync(0xffffffffu, s, 2);
            if (tg == 0 && n0 + sxrow < N)
                g_sx[(size_t)(n0 + sxrow) * HOPS + hop] = s;
            sx0 = sx1 = 0.f;
        }
    }
    __syncthreads();

    // kick phase-2 W2 chunk0 (into B2 buf0; overlaps epilogue 1)
    #pragma unroll
    for (int i = 0; i < 8; ++i) {
        int idx = i * 256 + tid;
        int r = idx >> 3, c8 = (idx & 7) << 3;
        CP_ASYNC16(sb + B2H + r * 144 + c8 * 2, g_W2T_hi + (size_t)r * 256 + c8);
    }
    CP_COMMIT();

    // ---------------- epilogue 1: bias + prelu -> H bf16 tile in smem ----------------
    {
        const float a_jk = *a_jk_p;
        __nv_bfloat16* hh = (__nv_bfloat16*)(smraw + HREG);
        #pragma unroll
        for (int mt = 0; mt < 2; ++mt) {
            const int r = wm * 32 + mt * 16 + g;
            #pragma unroll
            for (int nt = 0; nt < 8; ++nt) {
                const int c = wn * 64 + nt * 8 + tg * 2;
                const float b0v = sb1[c], b1v = sb1[c + 1];
                float x0 = prelu_f(acc[mt][nt][0] + b0v, a_jk);
                float x1 = prelu_f(acc[mt][nt][1] + b1v, a_jk);
                float x2 = prelu_f(acc[mt][nt][2] + b0v, a_jk);
                float x3 = prelu_f(acc[mt][nt][3] + b1v, a_jk);
                *(uint32_t*)&hh[(size_t)r * 264 + c]       = pack_bf16x2(x0, x1);
                *(uint32_t*)&hh[(size_t)(r + 8) * 264 + c] = pack_bf16x2(x2, x3);
            }
        }
    }

    #pragma unroll
    for (int a = 0; a < 2; ++a)
        #pragma unroll
        for (int b = 0; b < 8; ++b)
            #pragma unroll
            for (int c = 0; c < 4; ++c) acc[a][b][c] = 0.f;

    // ---------------- Phase 2: jk = H @ W2, 4 chunks of 64, double-buffered ----------------
    const uint32_t a2H = sb + HREG + (uint32_t)(wm * 32 + (lane & 15)) * 528
                       + (uint32_t)((lane >> 4) * 8) * 2;

    for (int c2 = 0; c2 < 4; ++c2) {
        CP_WAIT0();
        __syncthreads();
        if (c2 < 3) {
            const int cn = c2 + 1;
            const uint32_t nb = sb + B2H + (uint32_t)(cn & 1) * 36864;
            #pragma unroll
            for (int i = 0; i < 8; ++i) {
                int idx = i * 256 + tid;
                int r = idx >> 3, c8 = (idx & 7) << 3;
                CP_ASYNC16(nb + r * 144 + c8 * 2,
                           g_W2T_hi + (size_t)r * 256 + cn * 64 + c8);
            }
            CP_COMMIT();
        }
        const uint32_t b2f = sb + B2H + (uint32_t)(c2 & 1) * 36864 + boff_c;

        #pragma unroll
        for (int ks = 0; ks < 4; ++ks) {
            const uint32_t ko = (uint32_t)(c2 * 64 + ks * 16) * 2;
            uint32_t ah[2][4];
            ldsm4(ah[0], a2H + ko);
            ldsm4(ah[1], a2H + 16 * 528 + ko);
            #pragma unroll
            for (int ntp = 0; ntp < 4; ++ntp) {
                uint32_t bhf[4];
                ldsm4(bhf, b2f + ntp * 16 * 144 + ks * 32);
                #pragma unroll
                for (int mt = 0; mt < 2; ++mt) {
                    mma16816(acc[mt][ntp * 2],     ah[mt], bhf);
                    mma16816(acc[mt][ntp * 2 + 1], ah[mt], bhf + 2);
                }
            }
        }
    }

    // ---------------- epilogue 2: prelu -> dot(w_ref) -> softmax(sigmoid) ----------------
    const float a_main = *a_main_p;
    float part[2][2] = {{0.f, 0.f}, {0.f, 0.f}};
    #pragma unroll
    for (int mt = 0; mt < 2; ++mt) {
        #pragma unroll
        for (int nt = 0; nt < 8; ++nt) {
            const int c = wn * 64 + nt * 8 + tg * 2;
            const float w0 = swr[c], w1 = swr[c + 1];
            const float bb0 = sb2[c], bb1 = sb2[c + 1];
            part[mt][0] += prelu_f(acc[mt][nt][0] + bb0, a_main) * w0
                         + prelu_f(acc[mt][nt][1] + bb1, a_main) * w1;
            part[mt][1] += prelu_f(acc[mt][nt][2] + bb0, a_main) * w0
                         + prelu_f(acc[mt][nt][3] + bb1, a_main) * w1;
        }
    }
    #pragma unroll
    for (int mt = 0; mt < 2; ++mt)
        #pragma unroll
        for (int h = 0; h < 2; ++h) {
            part[mt][h] += __shfl_xor_sync(0xffffffffu, part[mt][h], 1);
            part[mt][h] += __shfl_xor_sync(0xffffffffu, part[mt][h], 2);
        }
    __syncthreads();
    if (tg == 0) {
        #pragma unroll
        for (int mt = 0; mt < 2; ++mt) {
            const int r = wm * 32 + mt * 16 + g;
            sred[r * 4 + wn]       = part[mt][0];
            sred[(r + 8) * 4 + wn] = part[mt][1];
        }
    }
    __syncthreads();

    if (tid < 64) {
        const int n = n0 + tid;
        if (n < N) {
            const float sref = sred[tid * 4] + sred[tid * 4 + 1]
                             + sred[tid * 4 + 2] + sred[tid * 4 + 3] + *b_att_p;
            const float* sxp = g_sx + (size_t)n * HOPS;
            float s[HOPS];
            float m = -1e30f;
            #pragma unroll
            for (int h = 0; h < HOPS; ++h) {
                float z = sxp[h] + sref;
                s[h] = 1.f / (1.f + expf(-z));
                m = fmaxf(m, s[h]);
            }
            float sum = 0.f;
            #pragma unroll
            for (int h = 0; h < HOPS; ++h) { s[h] = expf(s[h] - m); sum += s[h]; }
            const float inv = 1.f / sum;
            float* d = g_w + (size_t)n * HOPS;
            *(float4*)(d + 0) = make_float4(s[0] * inv, s[1] * inv, s[2] * inv, s[3] * inv);
            *(float4*)(d + 4) = make_float4(s[4] * inv, s[5] * inv, s[6] * inv, s[7] * inv);
        }
    }
}

// ---------------------------------------------------------------------------
// k3a: agg[n][f] = sum_h g_w[n][h] * feats[h][n][f]  -> fp16 global (1-pass).
// ---------------------------------------------------------------------------
__global__ __launch_bounds__(256) void k3a_agg(const float* __restrict__ feats, int N)
{
    int idx = blockIdx.x * 256 + threadIdx.x;
    if (idx >= N * 32) return;
    const int n = idx >> 5, f = (idx & 31) << 2;

    float4 w0 = *(const float4*)(g_w + (size_t)n * HOPS);
    float4 w1 = *(const float4*)(g_w + (size_t)n * HOPS + 4);
    const float wv[8] = {w0.x, w0.y, w0.z, w0.w, w1.x, w1.y, w1.z, w1.w};

    float ax = 0.f, ay = 0.f, az = 0.f, aw = 0.f;
    #pragma unroll
    for (int hop = 0; hop < HOPS; ++hop) {
        const float4 v = *(const float4*)(feats + (size_t)hop * N * FDIM
                                                + (size_t)n * FDIM + f);
        ax += wv[hop] * v.x; ay += wv[hop] * v.y;
        az += wv[hop] * v.z; aw += wv[hop] * v.w;
    }
    ull u = (ull)pack_half2(ax, ay) | ((ull)pack_half2(az, aw) << 32);
    *(ull*)(g_agg + (size_t)n * FDIM + f) = u;
}

// ---------------------------------------------------------------------------
// k3b: out = prelu(agg@Wo1+bo1, a_out) @ Wo2 + bo2.  fp16 1-pass.
// 256 thr, BM=64, 2 CTAs/SM.  FFN1: 4 dbl-buf chunks k=32; FFN2: 4 of k=64.
// ---------------------------------------------------------------------------
#define K3_AG 0
#define K3_T  17408
#define K3_BB 51200
#define K3_SMEM 92160

__global__ __launch_bounds__(256, 2) void k3b_out(
    const float* __restrict__ bo1, const float* __restrict__ a_out_p,
    const float* __restrict__ bo2, float* __restrict__ out, int N)
{
    extern __shared__ char smraw[];
    const uint32_t sb = smem_u32(smraw);
    const int tid = threadIdx.x, wid = tid >> 5, lane = tid & 31;
    const int n0 = blockIdx.x * 64;
    const int g = lane >> 2, tg = lane & 3;
    const int wm = wid & 1, wn = wid >> 1;   // 2M x 4N

    // ---- prologue: agg tile + FFN1 chunk0 cp.async ----
    #pragma unroll
    for (int i = 0; i < 4; ++i) {
        int idx = i * 256 + tid;
        int r = idx >> 4, c8 = (idx & 15) << 3;
        int n = n0 + r; if (n > N - 1) n = N - 1;
        CP_ASYNC16(sb + K3_AG + r * 272 + c8 * 2, g_agg + (size_t)n * FDIM + c8);
    }
    #pragma unroll
    for (int i = 0; i < 4; ++i) {
        int idx = i * 256 + tid;
        int r = idx >> 2, c8 = (idx & 3) << 3;
        CP_ASYNC16(sb + K3_BB + r * 80 + c8 * 2, g_Wo1T_h + (size_t)r * 128 + c8);
    }
    CP_COMMIT();

    const int brow = (lane & 7) + ((lane >> 4) << 3);
    const int bko  = ((lane >> 3) & 1) * 8;

    // ---- FFN1: t = prelu(agg[64x128] @ Wo1 + bo1), 4 chunks of k=32 ----
    float acc1[2][8][4];
    #pragma unroll
    for (int a = 0; a < 2; ++a)
        #pragma unroll
        for (int b = 0; b < 8; ++b)
            #pragma unroll
            for (int c = 0; c < 4; ++c) acc1[a][b][c] = 0.f;

    {
        const uint32_t aoff = sb + K3_AG + (uint32_t)(wm * 32 + (lane & 15)) * 272
                            + (uint32_t)((lane >> 4) * 8) * 2;
        const uint32_t bfrag = (uint32_t)(wn * 64 + brow) * 80 + (uint32_t)bko * 2;

        for (int c = 0; c < 4; ++c) {
            CP_WAIT0();
            __syncthreads();
            if (c < 3) {
                const int cn = c + 1;
                const uint32_t nb = sb + K3_BB + (uint32_t)(cn & 1) * 20480;
                #pragma unroll
                for (int i = 0; i < 4; ++i) {
                    int idx = i * 256 + tid;
                    int r = idx >> 2, c8 = (idx & 3) << 3;
                    CP_ASYNC16(nb + r * 80 + c8 * 2,
                               g_Wo1T_h + (size_t)r * 128 + cn * 32 + c8);
                }
                CP_COMMIT();
            }
            const uint32_t bH = sb + K3_BB + (uint32_t)(c & 1) * 20480 + bfrag;
            #pragma unroll
            for (int ks = 0; ks < 2; ++ks) {
                const int kglob = c * 32 + ks * 16;
                uint32_t ah[2][4];
                ldsm4(ah[0], aoff + kglob * 2);
                ldsm4(ah[1], aoff + 16 * 272 + kglob * 2);
                #pragma unroll
                for (int ntp = 0; ntp < 4; ++ntp) {
                    uint32_t bh[4];
                    ldsm4(bh, bH + ntp * 16 * 80 + ks * 32);
                    #pragma unroll
                    for (int mt = 0; mt < 2; ++mt) {
                        mma16816h(acc1[mt][ntp * 2],     ah[mt], bh);
                        mma16816h(acc1[mt][ntp * 2 + 1], ah[mt], bh + 2);
                    }
                }
            }
        }
    }
    __syncthreads();   // all FFN1 MMAs done -> BB reusable

    // kick FFN2 chunk0 load (overlaps t epilogue)
    #pragma unroll
    for (int i = 0; i < 2; ++i) {
        int idx = i * 256 + tid;
        int r = idx >> 3, c8 = (idx & 7) << 3;
        CP_ASYNC16(sb + K3_BB + r * 144 + c8 * 2, g_Wo2T_h + (size_t)r * 256 + c8);
    }
    CP_COMMIT();

    // ---- t epilogue -> fp16 smem tile (pitch 528B) ----
    {
        const float a_out = *a_out_p;
        __half* th = (__half*)(smraw + K3_T);
        #pragma unroll
        for (int mt = 0; mt < 2; ++mt) {
            const int r = wm * 32 + mt * 16 + g;
            #pragma unroll
            for (int nt = 0; nt < 8; ++nt) {
                const int c = wn * 64 + nt * 8 + tg * 2;
                const float b0v = __ldg(&bo1[c]), b1v = __ldg(&bo1[c + 1]);
                float x0 = prelu_f(acc1[mt][nt][0] + b0v, a_out);
                float x1 = prelu_f(acc1[mt][nt][1] + b1v, a_out);
                float x2 = prelu_f(acc1[mt][nt][2] + b0v, a_out);
                float x3 = prelu_f(acc1[mt][nt][3] + b1v, a_out);
                *(uint32_t*)&th[(size_t)r * 264 + c]       = pack_half2(x0, x1);
                *(uint32_t*)&th[(size_t)(r + 8) * 264 + c] = pack_half2(x2, x3);
            }
        }
    }

    // ---- FFN2: out = t[64x256] @ Wo2 + bo2, 4 chunks of k=64 ----
    {
        float acc2[2][2][4];
        #pragma unroll
        for (int a = 0; a < 2; ++a)
            #pragma unroll
            for (int b = 0; b < 2; ++b)
                #pragma unroll
                for (int c = 0; c < 4; ++c) acc2[a][b][c] = 0.f;

        const uint32_t aoff = sb + K3_T + (uint32_t)(wm * 32 + (lane & 15)) * 528
                            + (uint32_t)((lane >> 4) * 8) * 2;
        const uint32_t bfrag = (uint32_t)(wn * 16 + brow) * 144 + (uint32_t)bko * 2;

        for (int ch = 0; ch < 4; ++ch) {
            CP_WAIT0();
            __syncthreads();
            if (ch < 3) {
                const int cn = ch + 1;
                const uint32_t nb = sb + K3_BB + (uint32_t)(cn & 1) * 9216;
                #pragma unroll
                for (int i = 0; i < 2; ++i) {
                    int idx = i * 256 + tid;
                    int r = idx >> 3, c8 = (idx & 7) << 3;
                    CP_ASYNC16(nb + r * 144 + c8 * 2,
                               g_Wo2T_h + (size_t)r * 256 + cn * 64 + c8);
                }
                CP_COMMIT();
            }
            const uint32_t bH = sb + K3_BB + (uint32_t)(ch & 1) * 9216 + bfrag;
            #pragma unroll
            for (int ks = 0; ks < 4; ++ks) {
                const int kglob = ch * 64 + ks * 16;
                uint32_t ah[2][4], bh[4];
                ldsm4(ah[0], aoff + kglob * 2);
                ldsm4(ah[1], aoff + 16 * 528 + kglob * 2);
                ldsm4(bh, bH + ks * 32);
                #pragma unroll
                for (int mt = 0; mt < 2; ++mt) {
                    mma16816h(acc2[mt][0], ah[mt], bh);
                    mma16816h(acc2[mt][1], ah[mt], bh + 2);
                }
            }
        }

        #pragma unroll
        for (int mt = 0; mt < 2; ++mt) {
            const int n = n0 + wm * 32 + mt * 16 + g;
            #pragma unroll
            for (int ncl = 0; ncl < 2; ++ncl) {
                const int c = wn * 16 + ncl * 8 + tg * 2;
                const float b0v = __ldg(&bo2[c]), b1v = __ldg(&bo2[c + 1]);
                if (n < N) {
                    float2 o = make_float2(acc2[mt][ncl][0] + b0v, acc2[mt][ncl][1] + b1v);
                    *(float2*)&out[(size_t)n * NCLS + c] = o;
                }
                if (n + 8 < N) {
                    float2 o = make_float2(acc2[mt][ncl][2] + b0v, acc2[mt][ncl][3] + b1v);
                    *(float2*)&out[(size_t)(n + 8) * NCLS + c] = o;
                }
            }
        }
    }
}

// ---------------------------------------------------------------------------
extern "C" void kernel_launch(void* const* d_in, const int* in_sizes, int n_in,
                              void* d_out, int out_size)
{
    const float* feats  = (const float*)d_in[0];
    const float* W_jk1  = (const float*)d_in[1];
    const float* b_jk1  = (const float*)d_in[2];
    const float* W_jk2  = (const float*)d_in[3];
    const float* b_jk2  = (const float*)d_in[4];
    const float* a_jk   = (const float*)d_in[5];
    const float* a_main = (const float*)d_in[6];
    const float* a_out  = (const float*)d_in[7];
    const float* w_ref  = (const float*)d_in[8];
    const float* w_x    = (const float*)d_in[9];
    const float* b_att  = (const float*)d_in[10];
    const float* W_o1   = (const float*)d_in[11];
    const float* b_o1   = (const float*)d_in[12];
    const float* W_o2   = (const float*)d_in[13];
    const float* b_o2   = (const float*)d_in[14];
    float* out = (float*)d_out;

    const int N = in_sizes[0] / (HOPS * FDIM);
    const int nb64 = (N + 63) / 64;

    cudaFuncSetAttribute(k12,     cudaFuncAttributeMaxDynamicSharedMemorySize, K12_SMEM);
    cudaFuncSetAttribute(k3b_out, cudaFuncAttributeMaxDynamicSharedMemorySize, K3_SMEM);

    k0_convert<<<368, 1024>>>(W_jk1, W_jk2, W_o1, W_o2);
    k12<<<nb64, 256, K12_SMEM>>>(feats, w_x, b_jk1, a_jk, b_jk2, a_main,
                                 w_ref, b_att, N);
    k3a_agg<<<(N * 32 + 255) / 256, 256>>>(feats, N);
    k3b_out<<<nb64, 256, K3_SMEM>>>(b_o1, a_out, b_o2, out, N);
}